// round 1
// baseline (speedup 1.0000x reference)
#include <cuda_runtime.h>
#include <math.h>

// ---------------- problem constants ----------------
#define NN   384
#define CIN  128
#define NH   4
#define CH   32
#define M_TOT (NN*NN)                   // 147456 pair positions
#define QK_SCALE 0.17677669529663687f   // 1/sqrt(32)

// ---------------- scratch (static device globals; no allocs allowed) ----------------
__device__ float g_Q  [(size_t)M_TOT*CIN];
__device__ float g_Kp [(size_t)M_TOT*CIN];
__device__ float g_Vp [(size_t)M_TOT*CIN];
__device__ float g_Gp [(size_t)M_TOT*CIN];
__device__ float g_TRI[(size_t)NH*M_TOT];
__device__ float g_O  [(size_t)M_TOT*CIN];

// ---------------- GEMM tile config ----------------
#define BM 64
#define BN 64
#define SA_STRIDE 68   // padded (mod-32 = 4) to keep transposed stores ~conflict-light, 16B-aligned reads

// =====================================================================
// Kernel 1: fused LayerNorm + projections
//   A[M,128] = LN(z) computed on the fly; B = one of {wq,wk,wv,wg,wtri}
//   nt 0-1 -> Q (scaled), 2-3 -> K, 4-5 -> V, 6-7 -> G (sigmoid), 8 -> TRI (4 cols)
// =====================================================================
__global__ void __launch_bounds__(256)
proj_kernel(const float* __restrict__ z,
            const float* __restrict__ lnw, const float* __restrict__ lnb,
            const float* __restrict__ wq,  const float* __restrict__ wk,
            const float* __restrict__ wv,  const float* __restrict__ wg,
            const float* __restrict__ wtri)
{
    extern __shared__ float sh[];
    float* sA = sh;                      // [128][SA_STRIDE]  (k-major, transposed)
    float* sB = sh + 128*SA_STRIDE;      // [128][64]

    const int tid = threadIdx.x;
    const int nt  = blockIdx.x;          // 0..8   (N tiles adjacent -> z rows reused in L2)
    const int mt  = blockIdx.y;          // 0..2303
    const int m0  = mt * BM;

    // ---- A tile: load 64 z-rows, LayerNorm, store transposed ----
    {
        const int row  = tid >> 2;       // 0..63
        const int part = tid & 3;        // 0..3 (32 channels each)
        const float* zr = z + (size_t)(m0 + row)*CIN + part*32;
        float vals[32];
        float s1 = 0.f, s2 = 0.f;
        #pragma unroll
        for (int j = 0; j < 32; j += 4) {
            float4 t = *(const float4*)(zr + j);
            vals[j]=t.x; vals[j+1]=t.y; vals[j+2]=t.z; vals[j+3]=t.w;
            s1 += t.x + t.y + t.z + t.w;
            s2 += t.x*t.x + t.y*t.y + t.z*t.z + t.w*t.w;
        }
        s1 += __shfl_xor_sync(0xffffffffu, s1, 1);
        s2 += __shfl_xor_sync(0xffffffffu, s2, 1);
        s1 += __shfl_xor_sync(0xffffffffu, s1, 2);
        s2 += __shfl_xor_sync(0xffffffffu, s2, 2);
        const float mu  = s1 * (1.f/128.f);
        const float var = s2 * (1.f/128.f) - mu*mu;
        const float inv = rsqrtf(var + 1e-5f);
        #pragma unroll
        for (int j = 0; j < 32; j++) {
            const int k = part*32 + j;
            sA[k*SA_STRIDE + row] = (vals[j]-mu)*inv*__ldg(lnw+k) + __ldg(lnb+k);
        }
    }

    // ---- B tile ----
    if (nt < 8) {
        const float* W = (nt < 2) ? wq : (nt < 4) ? wk : (nt < 6) ? wv : wg;
        const int cb = (nt & 1) * 64;
        for (int idx = tid; idx < 128*64; idx += 256) {
            const int kk = idx >> 6, nl = idx & 63;
            sB[kk*64 + nl] = W[kk*128 + cb + nl];
        }
    } else {
        for (int idx = tid; idx < 128*64; idx += 256) {
            const int kk = idx >> 6, nl = idx & 63;
            sB[kk*64 + nl] = (nl < 4) ? wtri[kk*4 + nl] : 0.f;
        }
    }
    __syncthreads();

    // ---- compute: 4x4 microtile per thread ----
    const int ty = tid >> 4, tx = tid & 15;
    float acc[4][4];
    #pragma unroll
    for (int r = 0; r < 4; r++)
        #pragma unroll
        for (int c = 0; c < 4; c++) acc[r][c] = 0.f;

    const float* pA = sA + ty*4;
    const float* pB = sB + tx*4;
    #pragma unroll 16
    for (int kk = 0; kk < 128; kk++) {
        const float4 a = *(const float4*)(pA + kk*SA_STRIDE);
        const float4 b = *(const float4*)(pB + kk*64);
        acc[0][0] += a.x*b.x; acc[0][1] += a.x*b.y; acc[0][2] += a.x*b.z; acc[0][3] += a.x*b.w;
        acc[1][0] += a.y*b.x; acc[1][1] += a.y*b.y; acc[1][2] += a.y*b.z; acc[1][3] += a.y*b.w;
        acc[2][0] += a.z*b.x; acc[2][1] += a.z*b.y; acc[2][2] += a.z*b.z; acc[2][3] += a.z*b.w;
        acc[3][0] += a.w*b.x; acc[3][1] += a.w*b.y; acc[3][2] += a.w*b.z; acc[3][3] += a.w*b.w;
    }

    // ---- epilogue ----
    const int mg = m0 + ty*4;
    if (nt < 8) {
        float* dst = (nt < 2) ? g_Q : (nt < 4) ? g_Kp : (nt < 6) ? g_Vp : g_Gp;
        const int col = (nt & 1)*64 + tx*4;
        #pragma unroll
        for (int r = 0; r < 4; r++) {
            float4 o;
            if (nt < 2) {
                o = make_float4(acc[r][0]*QK_SCALE, acc[r][1]*QK_SCALE,
                                acc[r][2]*QK_SCALE, acc[r][3]*QK_SCALE);
            } else if (nt >= 6) {
                o = make_float4(1.f/(1.f+__expf(-acc[r][0])), 1.f/(1.f+__expf(-acc[r][1])),
                                1.f/(1.f+__expf(-acc[r][2])), 1.f/(1.f+__expf(-acc[r][3])));
            } else {
                o = make_float4(acc[r][0], acc[r][1], acc[r][2], acc[r][3]);
            }
            *(float4*)(dst + (size_t)(mg + r)*CIN + col) = o;
        }
    } else if (tx == 0) {
        #pragma unroll
        for (int r = 0; r < 4; r++)
            #pragma unroll
            for (int c = 0; c < 4; c++)
                g_TRI[(size_t)c*M_TOT + mg + r] = acc[r][c];   // head = c
    }
}

// =====================================================================
// Kernel 2: flash attention per (i, h). 384 threads = 1 thread per query.
//   scores[q,k] = q·k + 1e9*(mask[i,k]-1) + tri[h,q,k]; softmax over k; @V
// =====================================================================
__global__ void __launch_bounds__(384)
attn_kernel(const float* __restrict__ mask)
{
    __shared__ float sK[128][32];
    __shared__ float sV[128][32];
    __shared__ float sMb[128];

    const int i = blockIdx.x;
    const int h = blockIdx.y;
    const int q = threadIdx.x;          // 0..383
    const size_t rowbase = (size_t)i * NN;

    // query vector in registers
    float qv[32];
    {
        const float* qp = g_Q + (rowbase + q)*CIN + h*CH;
        #pragma unroll
        for (int c = 0; c < 32; c += 4) {
            float4 t = *(const float4*)(qp + c);
            qv[c]=t.x; qv[c+1]=t.y; qv[c+2]=t.z; qv[c+3]=t.w;
        }
    }
    // tri bias row: depends on pair position (q, k) and head h — NOT on i
    const float* trip = g_TRI + (size_t)h*M_TOT + (size_t)q*NN;

    float mrun = -3.0e38f, l = 0.f;
    float acc[32];
    #pragma unroll
    for (int c = 0; c < 32; c++) acc[c] = 0.f;

    for (int kt = 0; kt < NN; kt += 128) {
        for (int idx = threadIdx.x; idx < 128*32; idx += 384) {
            const int key = idx >> 5, c = idx & 31;
            const size_t g = (rowbase + kt + key)*CIN + h*CH + c;
            sK[key][c] = g_Kp[g];
            sV[key][c] = g_Vp[g];
        }
        if (threadIdx.x < 128)
            sMb[threadIdx.x] = 1e9f * (mask[rowbase + kt + threadIdx.x] - 1.f);
        __syncthreads();

        #pragma unroll 1
        for (int j0 = 0; j0 < 128; j0 += 8) {
            float tb[8];
            #pragma unroll
            for (int j = 0; j < 8; j += 4) {
                float4 t = *(const float4*)(trip + kt + j0 + j);
                tb[j]=t.x; tb[j+1]=t.y; tb[j+2]=t.z; tb[j+3]=t.w;
            }
            float s[8];
            #pragma unroll
            for (int j = 0; j < 8; j++) {
                float d = 0.f;
                #pragma unroll
                for (int c = 0; c < 32; c++) d += qv[c] * sK[j0+j][c];
                s[j] = d + sMb[j0+j] + tb[j];
            }
            float cm = s[0];
            #pragma unroll
            for (int j = 1; j < 8; j++) cm = fmaxf(cm, s[j]);
            const float mn = fmaxf(mrun, cm);
            const float scale = __expf(mrun - mn);
            mrun = mn;
            l *= scale;
            #pragma unroll
            for (int c = 0; c < 32; c++) acc[c] *= scale;
            #pragma unroll
            for (int j = 0; j < 8; j++) {
                const float p = __expf(s[j] - mrun);
                l += p;
                #pragma unroll
                for (int c = 0; c < 32; c++) acc[c] += p * sV[j0+j][c];
            }
        }
        __syncthreads();
    }

    const float invl = 1.f / l;
    float* op = g_O + (rowbase + q)*CIN + h*CH;
    #pragma unroll
    for (int c = 0; c < 32; c += 4) {
        float4 o = make_float4(acc[c]*invl, acc[c+1]*invl, acc[c+2]*invl, acc[c+3]*invl);
        *(float4*)(op + c) = o;
    }
}

// =====================================================================
// Kernel 3: out = (O * G) @ wo    [M,128]@[128,128]
// =====================================================================
__global__ void __launch_bounds__(256)
outproj_kernel(const float* __restrict__ wo, float* __restrict__ out)
{
    extern __shared__ float sh[];
    float* sA = sh;
    float* sB = sh + 128*SA_STRIDE;

    const int tid = threadIdx.x;
    const int nt  = blockIdx.x;          // 0..1
    const int m0  = blockIdx.y * BM;

    for (int idx = tid; idx < 64*128; idx += 256) {
        const int ml = idx >> 7, k = idx & 127;
        const size_t g = (size_t)(m0 + ml)*CIN + k;
        sA[k*SA_STRIDE + ml] = g_O[g] * g_Gp[g];
    }
    for (int idx = tid; idx < 128*64; idx += 256) {
        const int kk = idx >> 6, nl = idx & 63;
        sB[kk*64 + nl] = wo[kk*128 + nt*64 + nl];
    }
    __syncthreads();

    const int ty = tid >> 4, tx = tid & 15;
    float acc[4][4];
    #pragma unroll
    for (int r = 0; r < 4; r++)
        #pragma unroll
        for (int c = 0; c < 4; c++) acc[r][c] = 0.f;

    const float* pA = sA + ty*4;
    const float* pB = sB + tx*4;
    #pragma unroll 16
    for (int kk = 0; kk < 128; kk++) {
        const float4 a = *(const float4*)(pA + kk*SA_STRIDE);
        const float4 b = *(const float4*)(pB + kk*64);
        acc[0][0] += a.x*b.x; acc[0][1] += a.x*b.y; acc[0][2] += a.x*b.z; acc[0][3] += a.x*b.w;
        acc[1][0] += a.y*b.x; acc[1][1] += a.y*b.y; acc[1][2] += a.y*b.z; acc[1][3] += a.y*b.w;
        acc[2][0] += a.z*b.x; acc[2][1] += a.z*b.y; acc[2][2] += a.z*b.z; acc[2][3] += a.z*b.w;
        acc[3][0] += a.w*b.x; acc[3][1] += a.w*b.y; acc[3][2] += a.w*b.z; acc[3][3] += a.w*b.w;
    }

    const int mg  = m0 + ty*4;
    const int col = nt*64 + tx*4;
    #pragma unroll
    for (int r = 0; r < 4; r++) {
        float4 o = make_float4(acc[r][0], acc[r][1], acc[r][2], acc[r][3]);
        *(float4*)(out + (size_t)(mg + r)*CIN + col) = o;
    }
}

// =====================================================================
// launch
// =====================================================================
extern "C" void kernel_launch(void* const* d_in, const int* in_sizes, int n_in,
                              void* d_out, int out_size)
{
    (void)in_sizes; (void)n_in; (void)out_size;
    const float* z    = (const float*)d_in[0];
    const float* mask = (const float*)d_in[1];
    const float* lnw  = (const float*)d_in[2];
    const float* lnb  = (const float*)d_in[3];
    const float* wtri = (const float*)d_in[4];
    const float* wq   = (const float*)d_in[5];
    const float* wk   = (const float*)d_in[6];
    const float* wv   = (const float*)d_in[7];
    const float* wg   = (const float*)d_in[8];
    const float* wo   = (const float*)d_in[9];

    const size_t shmem = (size_t)(128*SA_STRIDE + 128*64) * sizeof(float);  // 67584 B
    cudaFuncSetAttribute(proj_kernel,    cudaFuncAttributeMaxDynamicSharedMemorySize, (int)shmem);
    cudaFuncSetAttribute(outproj_kernel, cudaFuncAttributeMaxDynamicSharedMemorySize, (int)shmem);

    // N-tiles fastest so z rows for one M-tile stay hot in L2 across all 9 B-tiles
    proj_kernel<<<dim3(9, M_TOT/BM), 256, shmem>>>(z, lnw, lnb, wq, wk, wv, wg, wtri);
    attn_kernel<<<dim3(NN, NH), 384>>>(mask);
    outproj_kernel<<<dim3(2, M_TOT/BM), 256, shmem>>>(wo, (float*)d_out);
}

// round 2
// speedup vs baseline: 1.0421x; 1.0421x over previous
#include <cuda_runtime.h>
#include <math.h>

// ---------------- problem constants ----------------
#define NN   384
#define CIN  128
#define NH   4
#define CH   32
#define M_TOT (NN*NN)                   // 147456
#define QK_SCALE 0.17677669529663687f   // 1/sqrt(32)
#define WCOLS 576                        // 512 proj cols + 4 tri + pad

// ---------------- scratch (device globals; no allocs allowed) ----------------
__device__ float g_LAh[(size_t)M_TOT*CIN];   // LN(z) tf32-hi
__device__ float g_LAl[(size_t)M_TOT*CIN];   // LN(z) tf32-lo
__device__ float g_Wh [(size_t)CIN*WCOLS];   // packed weights hi (wq|wk|wv|wg|wtri|0)
__device__ float g_Wl [(size_t)CIN*WCOLS];
__device__ float g_WOh[(size_t)CIN*CIN];     // wo hi
__device__ float g_WOl[(size_t)CIN*CIN];
__device__ float g_Q  [(size_t)M_TOT*CIN];
__device__ float g_Kp [(size_t)M_TOT*CIN];
__device__ float g_Vp [(size_t)M_TOT*CIN];
__device__ float g_Gp [(size_t)M_TOT*CIN];
__device__ float g_TRI[(size_t)NH*M_TOT];
__device__ float g_O  [(size_t)M_TOT*CIN];

// ---------------- helpers ----------------
__device__ __forceinline__ unsigned f2tf(float x) {
    unsigned u; asm("cvt.rna.tf32.f32 %0, %1;" : "=r"(u) : "f"(x)); return u;
}
__device__ __forceinline__ void split2(float x, float& hi, float& lo) {
    hi = __uint_as_float(f2tf(x));
    lo = __uint_as_float(f2tf(x - hi));
}
__device__ __forceinline__ unsigned fu(float x) { return __float_as_uint(x); }

// D += A*B   (m16n8k8 tf32, A row-major frag, B col-major frag)
__device__ __forceinline__ void mma8(float* d, const unsigned* a, const unsigned* b) {
    asm volatile(
        "mma.sync.aligned.m16n8k8.row.col.f32.tf32.tf32.f32 "
        "{%0,%1,%2,%3},{%4,%5,%6,%7},{%8,%9},{%0,%1,%2,%3};\n"
        : "+f"(d[0]), "+f"(d[1]), "+f"(d[2]), "+f"(d[3])
        : "r"(a[0]), "r"(a[1]), "r"(a[2]), "r"(a[3]), "r"(b[0]), "r"(b[1]));
}

// =====================================================================
// prep 1: LayerNorm + tf32 split  (1 warp per row)
// =====================================================================
__global__ void __launch_bounds__(256)
ln_split_kernel(const float* __restrict__ z,
                const float* __restrict__ lnw, const float* __restrict__ lnb)
{
    const int row  = blockIdx.x*8 + (threadIdx.x >> 5);
    const int lane = threadIdx.x & 31;
    const float4 v = *(const float4*)(z + (size_t)row*CIN + lane*4);
    float s1 = v.x+v.y+v.z+v.w;
    float s2 = v.x*v.x + v.y*v.y + v.z*v.z + v.w*v.w;
    #pragma unroll
    for (int o = 16; o; o >>= 1) {
        s1 += __shfl_xor_sync(0xffffffffu, s1, o);
        s2 += __shfl_xor_sync(0xffffffffu, s2, o);
    }
    const float mu  = s1 * (1.f/128.f);
    const float var = s2 * (1.f/128.f) - mu*mu;
    const float inv = rsqrtf(var + 1e-5f);
    const float4 w = *(const float4*)(lnw + lane*4);
    const float4 b = *(const float4*)(lnb + lane*4);
    float y[4] = { (v.x-mu)*inv*w.x + b.x, (v.y-mu)*inv*w.y + b.y,
                   (v.z-mu)*inv*w.z + b.z, (v.w-mu)*inv*w.w + b.w };
    float4 hi4, lo4;
    split2(y[0], hi4.x, lo4.x); split2(y[1], hi4.y, lo4.y);
    split2(y[2], hi4.z, lo4.z); split2(y[3], hi4.w, lo4.w);
    *(float4*)&g_LAh[(size_t)row*CIN + lane*4] = hi4;
    *(float4*)&g_LAl[(size_t)row*CIN + lane*4] = lo4;
}

// =====================================================================
// prep 2: split weights into hi/lo planes
// =====================================================================
__global__ void __launch_bounds__(256)
wsplit_kernel(const float* __restrict__ wq, const float* __restrict__ wk,
              const float* __restrict__ wv, const float* __restrict__ wg,
              const float* __restrict__ wtri, const float* __restrict__ wo)
{
    const int idx = blockIdx.x*256 + threadIdx.x;
    if (idx < CIN*WCOLS) {
        const int k = idx / WCOLS, n = idx % WCOLS;
        float v;
        if      (n < 128) v = wq[k*128 + n];
        else if (n < 256) v = wk[k*128 + n-128];
        else if (n < 384) v = wv[k*128 + n-256];
        else if (n < 512) v = wg[k*128 + n-384];
        else if (n < 516) v = wtri[k*4 + n-512];
        else              v = 0.f;
        float hi, lo; split2(v, hi, lo);
        g_Wh[idx] = hi; g_Wl[idx] = lo;
    } else if (idx < CIN*WCOLS + CIN*CIN) {
        const int j = idx - CIN*WCOLS;
        float hi, lo; split2(wo[j], hi, lo);
        g_WOh[j] = hi; g_WOl[j] = lo;
    }
}

// =====================================================================
// GEMM 1: C[M,576] = LN(z) @ W, 3xTF32.  BM=64 BN=64, 128 thr (4 warps 2x2),
// warp tile 32x32.  Epilogues: Q scale / K / V / sigmoid G / TRI transpose.
// =====================================================================
__global__ void __launch_bounds__(128)
proj_mma_kernel()
{
    extern __shared__ float sh[];
    float* sAh = sh;                 // [64][68]
    float* sAl = sAh + 64*68;
    float* sBh = sAl + 64*68;        // [64][72]
    float* sBl = sBh + 64*72;

    const int tid  = threadIdx.x;
    const int warp = tid >> 5, lane = tid & 31;
    const int g = lane >> 2, tg = lane & 3;
    const int wm = warp >> 1, wn = warp & 1;
    const int ntb = blockIdx.x;            // 0..8
    const int m0  = blockIdx.y * 64;
    const int n0  = ntb * 64;

    float acc[2][4][4];
    #pragma unroll
    for (int a = 0; a < 2; a++)
        #pragma unroll
        for (int b = 0; b < 4; b++)
            #pragma unroll
            for (int c = 0; c < 4; c++) acc[a][b][c] = 0.f;

    for (int kc = 0; kc < 128; kc += 64) {
        __syncthreads();
        for (int idx = tid; idx < 1024; idx += 128) {
            const int r = idx >> 4, c4 = (idx & 15) << 2;
            *(float4*)&sAh[r*68 + c4] = *(const float4*)&g_LAh[(size_t)(m0+r)*CIN + kc + c4];
            *(float4*)&sAl[r*68 + c4] = *(const float4*)&g_LAl[(size_t)(m0+r)*CIN + kc + c4];
            *(float4*)&sBh[r*72 + c4] = *(const float4*)&g_Wh[(size_t)(kc+r)*WCOLS + n0 + c4];
            *(float4*)&sBl[r*72 + c4] = *(const float4*)&g_Wl[(size_t)(kc+r)*WCOLS + n0 + c4];
        }
        __syncthreads();
        #pragma unroll
        for (int ks = 0; ks < 8; ks++) {
            const int k0 = ks*8;
            unsigned ah[2][4], al[2][4];
            #pragma unroll
            for (int mt = 0; mt < 2; mt++) {
                const int mr = wm*32 + mt*16;
                ah[mt][0] = fu(sAh[(mr+g  )*68 + k0+tg  ]);
                ah[mt][1] = fu(sAh[(mr+g+8)*68 + k0+tg  ]);
                ah[mt][2] = fu(sAh[(mr+g  )*68 + k0+tg+4]);
                ah[mt][3] = fu(sAh[(mr+g+8)*68 + k0+tg+4]);
                al[mt][0] = fu(sAl[(mr+g  )*68 + k0+tg  ]);
                al[mt][1] = fu(sAl[(mr+g+8)*68 + k0+tg  ]);
                al[mt][2] = fu(sAl[(mr+g  )*68 + k0+tg+4]);
                al[mt][3] = fu(sAl[(mr+g+8)*68 + k0+tg+4]);
            }
            #pragma unroll
            for (int nt = 0; nt < 4; nt++) {
                const int nc = wn*32 + nt*8;
                unsigned bh[2], bl[2];
                bh[0] = fu(sBh[(k0+tg  )*72 + nc + g]);
                bh[1] = fu(sBh[(k0+tg+4)*72 + nc + g]);
                bl[0] = fu(sBl[(k0+tg  )*72 + nc + g]);
                bl[1] = fu(sBl[(k0+tg+4)*72 + nc + g]);
                #pragma unroll
                for (int mt = 0; mt < 2; mt++) {
                    mma8(acc[mt][nt], ah[mt], bh);
                    mma8(acc[mt][nt], ah[mt], bl);
                    mma8(acc[mt][nt], al[mt], bh);
                }
            }
        }
    }

    if (ntb < 8) {
        float* dst = (ntb < 2) ? g_Q : (ntb < 4) ? g_Kp : (ntb < 6) ? g_Vp : g_Gp;
        const int cbase = (ntb & 1)*64;
        #pragma unroll
        for (int mt = 0; mt < 2; mt++) {
            const int r0 = m0 + wm*32 + mt*16 + g;
            #pragma unroll
            for (int nt = 0; nt < 4; nt++) {
                const int col = cbase + wn*32 + nt*8 + 2*tg;
                float v0 = acc[mt][nt][0], v1 = acc[mt][nt][1];
                float v2 = acc[mt][nt][2], v3 = acc[mt][nt][3];
                if (ntb < 2) { v0*=QK_SCALE; v1*=QK_SCALE; v2*=QK_SCALE; v3*=QK_SCALE; }
                else if (ntb >= 6) {
                    v0 = 1.f/(1.f+__expf(-v0)); v1 = 1.f/(1.f+__expf(-v1));
                    v2 = 1.f/(1.f+__expf(-v2)); v3 = 1.f/(1.f+__expf(-v3));
                }
                *(float2*)&dst[(size_t)r0*CIN + col]     = make_float2(v0, v1);
                *(float2*)&dst[(size_t)(r0+8)*CIN + col] = make_float2(v2, v3);
            }
        }
    } else if (wn == 0 && tg < 2) {
        // cols 512..515 -> g_TRI[head][m]
        #pragma unroll
        for (int mt = 0; mt < 2; mt++) {
            const int r0 = m0 + wm*32 + mt*16 + g;
            const int c0 = 2*tg;
            g_TRI[(size_t)c0*M_TOT     + r0]   = acc[mt][0][0];
            g_TRI[(size_t)(c0+1)*M_TOT + r0]   = acc[mt][0][1];
            g_TRI[(size_t)c0*M_TOT     + r0+8] = acc[mt][0][2];
            g_TRI[(size_t)(c0+1)*M_TOT + r0+8] = acc[mt][0][3];
        }
    }
}

// =====================================================================
// Kernel: flash attention, tensorized (3xTF32).  Block = (q-tile 64, i, h),
// 128 thr = 4 warps; warp owns 16 query rows; 6 key chunks of 64.
// =====================================================================
__global__ void __launch_bounds__(128)
attn_mma_kernel(const float* __restrict__ mask)
{
    extern __shared__ float sh[];
    float* sQh = sh;             // [64][36]
    float* sQl = sQh + 2304;
    float* sKh = sQl + 2304;     // [64][36]
    float* sKl = sKh + 2304;
    float* sVh = sKl + 2304;     // [64][40]
    float* sVl = sVh + 2560;
    float* sPh = sVl + 2560;     // [64][68]
    float* sPl = sPh + 4352;
    float* sMb = sPl + 4352;     // [64]

    const int tid  = threadIdx.x;
    const int warp = tid >> 5, lane = tid & 31;
    const int g = lane >> 2, tg = lane & 3;
    const int q0 = blockIdx.x * 64;
    const int i  = blockIdx.y;
    const int h  = blockIdx.z;
    const size_t rowbase = (size_t)i * NN;

    // Q tile -> split smem
    for (int idx = tid; idx < 2048; idx += 128) {
        const int r = idx >> 5, c = idx & 31;
        float hi, lo;
        split2(g_Q[(rowbase + q0 + r)*CIN + h*CH + c], hi, lo);
        sQh[r*36 + c] = hi; sQl[r*36 + c] = lo;
    }

    const int qrow = q0 + warp*16 + g;           // global query index (row0)
    const float* triP0 = g_TRI + (size_t)h*M_TOT + (size_t)qrow*NN;
    const float* triP1 = triP0 + (size_t)8*NN;

    float m0v = -1e30f, m1v = -1e30f, l0 = 0.f, l1 = 0.f;
    float oacc[4][4];
    #pragma unroll
    for (int a = 0; a < 4; a++)
        #pragma unroll
        for (int b = 0; b < 4; b++) oacc[a][b] = 0.f;

    for (int kb = 0; kb < NN; kb += 64) {
        __syncthreads();
        for (int idx = tid; idx < 2048; idx += 128) {
            const int r = idx >> 5, c = idx & 31;
            const size_t gidx = (rowbase + kb + r)*CIN + h*CH + c;
            float hi, lo;
            split2(g_Kp[gidx], hi, lo); sKh[r*36+c] = hi; sKl[r*36+c] = lo;
            split2(g_Vp[gidx], hi, lo); sVh[r*40+c] = hi; sVl[r*40+c] = lo;
        }
        if (tid < 64) sMb[tid] = 1e9f * (mask[rowbase + kb + tid] - 1.f);
        __syncthreads();

        // ---- S = Q K^T ----
        float s[8][4];
        #pragma unroll
        for (int a = 0; a < 8; a++)
            #pragma unroll
            for (int b = 0; b < 4; b++) s[a][b] = 0.f;

        #pragma unroll
        for (int ks = 0; ks < 4; ks++) {
            const int k0 = ks*8;
            const int mr = warp*16;
            unsigned ah[4], al[4];
            ah[0] = fu(sQh[(mr+g  )*36 + k0+tg  ]);
            ah[1] = fu(sQh[(mr+g+8)*36 + k0+tg  ]);
            ah[2] = fu(sQh[(mr+g  )*36 + k0+tg+4]);
            ah[3] = fu(sQh[(mr+g+8)*36 + k0+tg+4]);
            al[0] = fu(sQl[(mr+g  )*36 + k0+tg  ]);
            al[1] = fu(sQl[(mr+g+8)*36 + k0+tg  ]);
            al[2] = fu(sQl[(mr+g  )*36 + k0+tg+4]);
            al[3] = fu(sQl[(mr+g+8)*36 + k0+tg+4]);
            #pragma unroll
            for (int nt = 0; nt < 8; nt++) {
                unsigned bh[2], bl[2];
                bh[0] = fu(sKh[(nt*8+g)*36 + k0+tg  ]);
                bh[1] = fu(sKh[(nt*8+g)*36 + k0+tg+4]);
                bl[0] = fu(sKl[(nt*8+g)*36 + k0+tg  ]);
                bl[1] = fu(sKl[(nt*8+g)*36 + k0+tg+4]);
                mma8(s[nt], ah, bh);
                mma8(s[nt], ah, bl);
                mma8(s[nt], al, bh);
            }
        }

        // ---- bias + online softmax ----
        float cm0 = -1e30f, cm1 = -1e30f;
        #pragma unroll
        for (int nt = 0; nt < 8; nt++) {
            const int col = nt*8 + 2*tg;
            const float2 t0 = *(const float2*)&triP0[kb + col];
            const float2 t1 = *(const float2*)&triP1[kb + col];
            const float mb0 = sMb[col], mb1 = sMb[col+1];
            s[nt][0] += t0.x + mb0; s[nt][1] += t0.y + mb1;
            s[nt][2] += t1.x + mb0; s[nt][3] += t1.y + mb1;
            cm0 = fmaxf(cm0, fmaxf(s[nt][0], s[nt][1]));
            cm1 = fmaxf(cm1, fmaxf(s[nt][2], s[nt][3]));
        }
        cm0 = fmaxf(cm0, __shfl_xor_sync(0xffffffffu, cm0, 1));
        cm0 = fmaxf(cm0, __shfl_xor_sync(0xffffffffu, cm0, 2));
        cm1 = fmaxf(cm1, __shfl_xor_sync(0xffffffffu, cm1, 1));
        cm1 = fmaxf(cm1, __shfl_xor_sync(0xffffffffu, cm1, 2));
        const float nm0 = fmaxf(m0v, cm0), nm1 = fmaxf(m1v, cm1);
        const float sc0 = __expf(m0v - nm0), sc1 = __expf(m1v - nm1);
        m0v = nm0; m1v = nm1;

        float sum0 = 0.f, sum1 = 0.f;
        const int prow0 = (warp*16+g)*68, prow1 = prow0 + 8*68;
        #pragma unroll
        for (int nt = 0; nt < 8; nt++) {
            const int col = nt*8 + 2*tg;
            const float p0 = __expf(s[nt][0]-nm0), p1 = __expf(s[nt][1]-nm0);
            const float p2 = __expf(s[nt][2]-nm1), p3 = __expf(s[nt][3]-nm1);
            sum0 += p0 + p1; sum1 += p2 + p3;
            float hi, lo;
            split2(p0,hi,lo); sPh[prow0+col]   = hi; sPl[prow0+col]   = lo;
            split2(p1,hi,lo); sPh[prow0+col+1] = hi; sPl[prow0+col+1] = lo;
            split2(p2,hi,lo); sPh[prow1+col]   = hi; sPl[prow1+col]   = lo;
            split2(p3,hi,lo); sPh[prow1+col+1] = hi; sPl[prow1+col+1] = lo;
        }
        sum0 += __shfl_xor_sync(0xffffffffu, sum0, 1);
        sum0 += __shfl_xor_sync(0xffffffffu, sum0, 2);
        sum1 += __shfl_xor_sync(0xffffffffu, sum1, 1);
        sum1 += __shfl_xor_sync(0xffffffffu, sum1, 2);
        l0 = l0*sc0 + sum0; l1 = l1*sc1 + sum1;
        #pragma unroll
        for (int nt = 0; nt < 4; nt++) {
            oacc[nt][0] *= sc0; oacc[nt][1] *= sc0;
            oacc[nt][2] *= sc1; oacc[nt][3] *= sc1;
        }
        __syncwarp();

        // ---- O += P V ----
        #pragma unroll
        for (int ks = 0; ks < 8; ks++) {
            const int k0 = ks*8;
            const int pr = warp*16;
            unsigned ah[4], al[4];
            ah[0] = fu(sPh[(pr+g  )*68 + k0+tg  ]);
            ah[1] = fu(sPh[(pr+g+8)*68 + k0+tg  ]);
            ah[2] = fu(sPh[(pr+g  )*68 + k0+tg+4]);
            ah[3] = fu(sPh[(pr+g+8)*68 + k0+tg+4]);
            al[0] = fu(sPl[(pr+g  )*68 + k0+tg  ]);
            al[1] = fu(sPl[(pr+g+8)*68 + k0+tg  ]);
            al[2] = fu(sPl[(pr+g  )*68 + k0+tg+4]);
            al[3] = fu(sPl[(pr+g+8)*68 + k0+tg+4]);
            #pragma unroll
            for (int nt = 0; nt < 4; nt++) {
                unsigned bh[2], bl[2];
                bh[0] = fu(sVh[(k0+tg  )*40 + nt*8 + g]);
                bh[1] = fu(sVh[(k0+tg+4)*40 + nt*8 + g]);
                bl[0] = fu(sVl[(k0+tg  )*40 + nt*8 + g]);
                bl[1] = fu(sVl[(k0+tg+4)*40 + nt*8 + g]);
                mma8(oacc[nt], ah, bh);
                mma8(oacc[nt], ah, bl);
                mma8(oacc[nt], al, bh);
            }
        }
    }

    const float inv0 = 1.f/l0, inv1 = 1.f/l1;
    const size_t ob0 = (rowbase + qrow)*CIN + h*CH;
    const size_t ob1 = (rowbase + qrow + 8)*CIN + h*CH;
    #pragma unroll
    for (int nt = 0; nt < 4; nt++) {
        const int col = nt*8 + 2*tg;
        *(float2*)&g_O[ob0 + col] = make_float2(oacc[nt][0]*inv0, oacc[nt][1]*inv0);
        *(float2*)&g_O[ob1 + col] = make_float2(oacc[nt][2]*inv1, oacc[nt][3]*inv1);
    }
}

// =====================================================================
// GEMM 3: out = (O*G) @ wo, 3xTF32.  Same shape machinery as proj.
// =====================================================================
__global__ void __launch_bounds__(128)
outproj_mma_kernel(float* __restrict__ out)
{
    extern __shared__ float sh[];
    float* sAh = sh;
    float* sAl = sAh + 64*68;
    float* sBh = sAl + 64*68;
    float* sBl = sBh + 64*72;

    const int tid  = threadIdx.x;
    const int warp = tid >> 5, lane = tid & 31;
    const int g = lane >> 2, tg = lane & 3;
    const int wm = warp >> 1, wn = warp & 1;
    const int n0 = blockIdx.x * 64;        // 0 or 64
    const int m0 = blockIdx.y * 64;

    float acc[2][4][4];
    #pragma unroll
    for (int a = 0; a < 2; a++)
        #pragma unroll
        for (int b = 0; b < 4; b++)
            #pragma unroll
            for (int c = 0; c < 4; c++) acc[a][b][c] = 0.f;

    for (int kc = 0; kc < 128; kc += 64) {
        __syncthreads();
        for (int idx = tid; idx < 1024; idx += 128) {
            const int r = idx >> 4, c4 = (idx & 15) << 2;
            const size_t ga = (size_t)(m0+r)*CIN + kc + c4;
            const float4 o4 = *(const float4*)&g_O[ga];
            const float4 g4 = *(const float4*)&g_Gp[ga];
            float4 h4, l4;
            split2(o4.x*g4.x, h4.x, l4.x); split2(o4.y*g4.y, h4.y, l4.y);
            split2(o4.z*g4.z, h4.z, l4.z); split2(o4.w*g4.w, h4.w, l4.w);
            *(float4*)&sAh[r*68 + c4] = h4;
            *(float4*)&sAl[r*68 + c4] = l4;
            *(float4*)&sBh[r*72 + c4] = *(const float4*)&g_WOh[(size_t)(kc+r)*CIN + n0 + c4];
            *(float4*)&sBl[r*72 + c4] = *(const float4*)&g_WOl[(size_t)(kc+r)*CIN + n0 + c4];
        }
        __syncthreads();
        #pragma unroll
        for (int ks = 0; ks < 8; ks++) {
            const int k0 = ks*8;
            unsigned ah[2][4], al[2][4];
            #pragma unroll
            for (int mt = 0; mt < 2; mt++) {
                const int mr = wm*32 + mt*16;
                ah[mt][0] = fu(sAh[(mr+g  )*68 + k0+tg  ]);
                ah[mt][1] = fu(sAh[(mr+g+8)*68 + k0+tg  ]);
                ah[mt][2] = fu(sAh[(mr+g  )*68 + k0+tg+4]);
                ah[mt][3] = fu(sAh[(mr+g+8)*68 + k0+tg+4]);
                al[mt][0] = fu(sAl[(mr+g  )*68 + k0+tg  ]);
                al[mt][1] = fu(sAl[(mr+g+8)*68 + k0+tg  ]);
                al[mt][2] = fu(sAl[(mr+g  )*68 + k0+tg+4]);
                al[mt][3] = fu(sAl[(mr+g+8)*68 + k0+tg+4]);
            }
            #pragma unroll
            for (int nt = 0; nt < 4; nt++) {
                const int nc = wn*32 + nt*8;
                unsigned bh[2], bl[2];
                bh[0] = fu(sBh[(k0+tg  )*72 + nc + g]);
                bh[1] = fu(sBh[(k0+tg+4)*72 + nc + g]);
                bl[0] = fu(sBl[(k0+tg  )*72 + nc + g]);
                bl[1] = fu(sBl[(k0+tg+4)*72 + nc + g]);
                #pragma unroll
                for (int mt = 0; mt < 2; mt++) {
                    mma8(acc[mt][nt], ah[mt], bh);
                    mma8(acc[mt][nt], ah[mt], bl);
                    mma8(acc[mt][nt], al[mt], bh);
                }
            }
        }
    }

    #pragma unroll
    for (int mt = 0; mt < 2; mt++) {
        const int r0 = m0 + wm*32 + mt*16 + g;
        #pragma unroll
        for (int nt = 0; nt < 4; nt++) {
            const int col = n0 + wn*32 + nt*8 + 2*tg;
            *(float2*)&out[(size_t)r0*CIN + col]     = make_float2(acc[mt][nt][0], acc[mt][nt][1]);
            *(float2*)&out[(size_t)(r0+8)*CIN + col] = make_float2(acc[mt][nt][2], acc[mt][nt][3]);
        }
    }
}

// =====================================================================
// launch
// =====================================================================
extern "C" void kernel_launch(void* const* d_in, const int* in_sizes, int n_in,
                              void* d_out, int out_size)
{
    (void)in_sizes; (void)n_in; (void)out_size;
    const float* z    = (const float*)d_in[0];
    const float* mask = (const float*)d_in[1];
    const float* lnw  = (const float*)d_in[2];
    const float* lnb  = (const float*)d_in[3];
    const float* wtri = (const float*)d_in[4];
    const float* wq   = (const float*)d_in[5];
    const float* wk   = (const float*)d_in[6];
    const float* wv   = (const float*)d_in[7];
    const float* wg   = (const float*)d_in[8];
    const float* wo   = (const float*)d_in[9];

    const size_t gemm_sh = (size_t)(2*64*68 + 2*64*72) * sizeof(float);   // 71680 B
    const size_t attn_sh = (size_t)(4*2304 + 2*2560 + 2*4352 + 64) * sizeof(float); // 92416 B
    cudaFuncSetAttribute(proj_mma_kernel,    cudaFuncAttributeMaxDynamicSharedMemorySize, (int)gemm_sh);
    cudaFuncSetAttribute(outproj_mma_kernel, cudaFuncAttributeMaxDynamicSharedMemorySize, (int)gemm_sh);
    cudaFuncSetAttribute(attn_mma_kernel,    cudaFuncAttributeMaxDynamicSharedMemorySize, (int)attn_sh);

    wsplit_kernel<<<(CIN*WCOLS + CIN*CIN + 255)/256, 256>>>(wq, wk, wv, wg, wtri, wo);
    ln_split_kernel<<<M_TOT/8, 256>>>(z, lnw, lnb);
    proj_mma_kernel<<<dim3(9, M_TOT/64), 128, gemm_sh>>>();
    attn_mma_kernel<<<dim3(NN/64, NN, NH), 128, attn_sh>>>(mask);
    outproj_mma_kernel<<<dim3(2, M_TOT/64), 128, gemm_sh>>>((float*)d_out);
}

// round 3
// speedup vs baseline: 1.4164x; 1.3592x over previous
#include <cuda_runtime.h>
#include <math.h>

// ---------------- problem constants ----------------
#define NN   384
#define CIN  128
#define NH   4
#define CH   32
#define M_TOT (NN*NN)                   // 147456
#define QK_SCALE 0.17677669529663687f   // 1/sqrt(32)
#define WCOLS 576                        // 512 proj cols + 4 tri + pad

// ---------------- scratch (device globals; no allocs) ----------------
__device__ float g_LAh[(size_t)M_TOT*CIN];       // LN(z) tf32-hi
__device__ float g_LAl[(size_t)M_TOT*CIN];       // LN(z) tf32-lo
__device__ float g_Wh [(size_t)CIN*WCOLS];       // packed weights hi
__device__ float g_Wl [(size_t)CIN*WCOLS];
__device__ float g_WO [(size_t)CIN*CIN];         // wo (tf32-rounded)
__device__ float g_Qh [(size_t)NH*M_TOT*CH];     // head-major [h][m][c]
__device__ float g_Ql [(size_t)NH*M_TOT*CH];
__device__ float g_Kh [(size_t)NH*M_TOT*CH];
__device__ float g_Kl [(size_t)NH*M_TOT*CH];
__device__ float g_V  [(size_t)NH*M_TOT*CH];     // tf32-rounded, head-major
__device__ float g_G  [(size_t)M_TOT*CIN];       // sigmoid gate, m-major fp32
__device__ float g_TRI[(size_t)NH*M_TOT];
__device__ float g_O  [(size_t)M_TOT*CIN];       // attn out, m-major

// ---------------- helpers ----------------
__device__ __forceinline__ unsigned f2tf(float x) {
    unsigned u; asm("cvt.rna.tf32.f32 %0, %1;" : "=r"(u) : "f"(x)); return u;
}
__device__ __forceinline__ void split2(float x, float& hi, float& lo) {
    hi = __uint_as_float(f2tf(x));
    lo = __uint_as_float(f2tf(x - hi));
}
__device__ __forceinline__ unsigned fu(float x) { return __float_as_uint(x); }

__device__ __forceinline__ void mma8(float* d, const unsigned* a, const unsigned* b) {
    asm volatile(
        "mma.sync.aligned.m16n8k8.row.col.f32.tf32.tf32.f32 "
        "{%0,%1,%2,%3},{%4,%5,%6,%7},{%8,%9},{%0,%1,%2,%3};\n"
        : "+f"(d[0]), "+f"(d[1]), "+f"(d[2]), "+f"(d[3])
        : "r"(a[0]), "r"(a[1]), "r"(a[2]), "r"(a[3]), "r"(b[0]), "r"(b[1]));
}

// =====================================================================
// prep 1: LayerNorm + tf32 split  (1 warp per row)
// =====================================================================
__global__ void __launch_bounds__(256)
ln_split_kernel(const float* __restrict__ z,
                const float* __restrict__ lnw, const float* __restrict__ lnb)
{
    const int row  = blockIdx.x*8 + (threadIdx.x >> 5);
    const int lane = threadIdx.x & 31;
    const float4 v = *(const float4*)(z + (size_t)row*CIN + lane*4);
    float s1 = v.x+v.y+v.z+v.w;
    float s2 = v.x*v.x + v.y*v.y + v.z*v.z + v.w*v.w;
    #pragma unroll
    for (int o = 16; o; o >>= 1) {
        s1 += __shfl_xor_sync(0xffffffffu, s1, o);
        s2 += __shfl_xor_sync(0xffffffffu, s2, o);
    }
    const float mu  = s1 * (1.f/128.f);
    const float var = s2 * (1.f/128.f) - mu*mu;
    const float inv = rsqrtf(var + 1e-5f);
    const float4 w = *(const float4*)(lnw + lane*4);
    const float4 b = *(const float4*)(lnb + lane*4);
    float y[4] = { (v.x-mu)*inv*w.x + b.x, (v.y-mu)*inv*w.y + b.y,
                   (v.z-mu)*inv*w.z + b.z, (v.w-mu)*inv*w.w + b.w };
    float4 hi4, lo4;
    split2(y[0], hi4.x, lo4.x); split2(y[1], hi4.y, lo4.y);
    split2(y[2], hi4.z, lo4.z); split2(y[3], hi4.w, lo4.w);
    *(float4*)&g_LAh[(size_t)row*CIN + lane*4] = hi4;
    *(float4*)&g_LAl[(size_t)row*CIN + lane*4] = lo4;
}

// =====================================================================
// prep 2: split/round weights
// =====================================================================
__global__ void __launch_bounds__(256)
wsplit_kernel(const float* __restrict__ wq, const float* __restrict__ wk,
              const float* __restrict__ wv, const float* __restrict__ wg,
              const float* __restrict__ wtri, const float* __restrict__ wo)
{
    const int idx = blockIdx.x*256 + threadIdx.x;
    if (idx < CIN*WCOLS) {
        const int k = idx / WCOLS, n = idx % WCOLS;
        float v;
        if      (n < 128) v = wq[k*128 + n];
        else if (n < 256) v = wk[k*128 + n-128];
        else if (n < 384) v = wv[k*128 + n-256];
        else if (n < 512) v = wg[k*128 + n-384];
        else if (n < 516) v = wtri[k*4 + n-512];
        else              v = 0.f;
        float hi, lo; split2(v, hi, lo);
        g_Wh[idx] = hi; g_Wl[idx] = lo;
    } else if (idx < CIN*WCOLS + CIN*CIN) {
        const int j = idx - CIN*WCOLS;
        g_WO[j] = __uint_as_float(f2tf(wo[j]));
    }
}

// =====================================================================
// GEMM 1: C[M,576] = LN(z) @ W.  3xTF32 for Q,K,tri; 1xTF32 for V,G.
// BM=BN=64, 128 thr (4 warps 2x2).  Epilogues write attn-friendly layouts.
// =====================================================================
__global__ void __launch_bounds__(128)
proj_mma_kernel()
{
    extern __shared__ float sh[];
    float* sAh = sh;                 // [64][68]
    float* sAl = sAh + 64*68;
    float* sBh = sAl + 64*68;        // [64][72]
    float* sBl = sBh + 64*72;

    const int tid  = threadIdx.x;
    const int warp = tid >> 5, lane = tid & 31;
    const int g = lane >> 2, tg = lane & 3;
    const int wm = warp >> 1, wn = warp & 1;
    const int ntb = blockIdx.x;            // 0..8
    const int m0  = blockIdx.y * 64;
    const int n0  = ntb * 64;
    const bool do3x = (ntb < 4) || (ntb == 8);
    const int ntmax = (ntb == 8) ? ((wn == 0) ? 1 : 0) : 4;

    float acc[2][4][4];
    #pragma unroll
    for (int a = 0; a < 2; a++)
        #pragma unroll
        for (int b = 0; b < 4; b++)
            #pragma unroll
            for (int c = 0; c < 4; c++) acc[a][b][c] = 0.f;

    for (int kc = 0; kc < 128; kc += 64) {
        __syncthreads();
        for (int idx = tid; idx < 1024; idx += 128) {
            const int r = idx >> 4, c4 = (idx & 15) << 2;
            *(float4*)&sAh[r*68 + c4] = *(const float4*)&g_LAh[(size_t)(m0+r)*CIN + kc + c4];
            *(float4*)&sBh[r*72 + c4] = *(const float4*)&g_Wh[(size_t)(kc+r)*WCOLS + n0 + c4];
            if (do3x) {
                *(float4*)&sAl[r*68 + c4] = *(const float4*)&g_LAl[(size_t)(m0+r)*CIN + kc + c4];
                *(float4*)&sBl[r*72 + c4] = *(const float4*)&g_Wl[(size_t)(kc+r)*WCOLS + n0 + c4];
            }
        }
        __syncthreads();
        #pragma unroll
        for (int ks = 0; ks < 8; ks++) {
            const int k0 = ks*8;
            unsigned ah[2][4], al[2][4];
            #pragma unroll
            for (int mt = 0; mt < 2; mt++) {
                const int mr = wm*32 + mt*16;
                ah[mt][0] = fu(sAh[(mr+g  )*68 + k0+tg  ]);
                ah[mt][1] = fu(sAh[(mr+g+8)*68 + k0+tg  ]);
                ah[mt][2] = fu(sAh[(mr+g  )*68 + k0+tg+4]);
                ah[mt][3] = fu(sAh[(mr+g+8)*68 + k0+tg+4]);
                if (do3x) {
                    al[mt][0] = fu(sAl[(mr+g  )*68 + k0+tg  ]);
                    al[mt][1] = fu(sAl[(mr+g+8)*68 + k0+tg  ]);
                    al[mt][2] = fu(sAl[(mr+g  )*68 + k0+tg+4]);
                    al[mt][3] = fu(sAl[(mr+g+8)*68 + k0+tg+4]);
                }
            }
            for (int nt = 0; nt < ntmax; nt++) {
                const int nc = wn*32 + nt*8;
                unsigned bh[2], bl[2];
                bh[0] = fu(sBh[(k0+tg  )*72 + nc + g]);
                bh[1] = fu(sBh[(k0+tg+4)*72 + nc + g]);
                if (do3x) {
                    bl[0] = fu(sBl[(k0+tg  )*72 + nc + g]);
                    bl[1] = fu(sBl[(k0+tg+4)*72 + nc + g]);
                }
                #pragma unroll
                for (int mt = 0; mt < 2; mt++) {
                    mma8(acc[mt][nt], ah[mt], bh);
                    if (do3x) {
                        mma8(acc[mt][nt], ah[mt], bl);
                        mma8(acc[mt][nt], al[mt], bh);
                    }
                }
            }
        }
    }

    // ---- epilogues ----
    if (ntb < 8) {
        const int cbase = (ntb & 1)*64;
        const int kind  = ntb >> 1;          // 0=Q 1=K 2=V 3=G
        #pragma unroll
        for (int mt = 0; mt < 2; mt++) {
            const int r0 = m0 + wm*32 + mt*16 + g;   // global m (row)
            #pragma unroll
            for (int nt = 0; nt < 4; nt++) {
                const int col = cbase + wn*32 + nt*8 + 2*tg;
                const int h = col >> 5, c0 = col & 31;
                const size_t hm0 = ((size_t)h*M_TOT + r0)*CH + c0;
                const size_t hm1 = ((size_t)h*M_TOT + r0 + 8)*CH + c0;
                float v0 = acc[mt][nt][0], v1 = acc[mt][nt][1];
                float v2 = acc[mt][nt][2], v3 = acc[mt][nt][3];
                if (kind == 0) {
                    v0*=QK_SCALE; v1*=QK_SCALE; v2*=QK_SCALE; v3*=QK_SCALE;
                    float h0,l0_,h1,l1_,h2,l2_,h3,l3_;
                    split2(v0,h0,l0_); split2(v1,h1,l1_);
                    split2(v2,h2,l2_); split2(v3,h3,l3_);
                    *(float2*)&g_Qh[hm0] = make_float2(h0,h1);
                    *(float2*)&g_Ql[hm0] = make_float2(l0_,l1_);
                    *(float2*)&g_Qh[hm1] = make_float2(h2,h3);
                    *(float2*)&g_Ql[hm1] = make_float2(l2_,l3_);
                } else if (kind == 1) {
                    float h0,l0_,h1,l1_,h2,l2_,h3,l3_;
                    split2(v0,h0,l0_); split2(v1,h1,l1_);
                    split2(v2,h2,l2_); split2(v3,h3,l3_);
                    *(float2*)&g_Kh[hm0] = make_float2(h0,h1);
                    *(float2*)&g_Kl[hm0] = make_float2(l0_,l1_);
                    *(float2*)&g_Kh[hm1] = make_float2(h2,h3);
                    *(float2*)&g_Kl[hm1] = make_float2(l2_,l3_);
                } else if (kind == 2) {
                    *(float2*)&g_V[hm0] = make_float2(__uint_as_float(f2tf(v0)),
                                                      __uint_as_float(f2tf(v1)));
                    *(float2*)&g_V[hm1] = make_float2(__uint_as_float(f2tf(v2)),
                                                      __uint_as_float(f2tf(v3)));
                } else {
                    *(float2*)&g_G[(size_t)r0*CIN + col] =
                        make_float2(1.f/(1.f+__expf(-v0)), 1.f/(1.f+__expf(-v1)));
                    *(float2*)&g_G[(size_t)(r0+8)*CIN + col] =
                        make_float2(1.f/(1.f+__expf(-v2)), 1.f/(1.f+__expf(-v3)));
                }
            }
        }
    } else if (wn == 0 && tg < 2) {
        #pragma unroll
        for (int mt = 0; mt < 2; mt++) {
            const int r0 = m0 + wm*32 + mt*16 + g;
            const int c0 = 2*tg;
            g_TRI[(size_t)c0*M_TOT     + r0]   = acc[mt][0][0];
            g_TRI[(size_t)(c0+1)*M_TOT + r0]   = acc[mt][0][1];
            g_TRI[(size_t)c0*M_TOT     + r0+8] = acc[mt][0][2];
            g_TRI[(size_t)(c0+1)*M_TOT + r0+8] = acc[mt][0][3];
        }
    }
}

// =====================================================================
// flash attention: S = 3xTF32, PV = 1xTF32.  Block = 64 queries x (i,h).
// Pre-split/pre-rounded operands -> smem fill is pure float4 copies.
// =====================================================================
__global__ void __launch_bounds__(128)
attn_mma_kernel(const float* __restrict__ mask)
{
    extern __shared__ float sh[];
    float* sQh = sh;             // [64][36]
    float* sQl = sQh + 2304;
    float* sKh = sQl + 2304;     // [64][36]
    float* sKl = sKh + 2304;
    float* sV  = sKl + 2304;     // [64][40]
    float* sP  = sV  + 2560;     // [64][68]
    float* sMb = sP  + 4352;     // [64]

    const int tid  = threadIdx.x;
    const int warp = tid >> 5, lane = tid & 31;
    const int g = lane >> 2, tg = lane & 3;
    const int q0 = blockIdx.x * 64;
    const int i  = blockIdx.y;
    const int h  = blockIdx.z;
    const size_t rowbase = (size_t)i * NN;
    const size_t hbase   = (size_t)h * M_TOT;

    // Q tile (pre-split)
    for (int idx = tid; idx < 512; idx += 128) {
        const int r = idx >> 3, c4 = (idx & 7) << 2;
        const size_t gidx = (hbase + rowbase + q0 + r)*CH + c4;
        *(float4*)&sQh[r*36 + c4] = *(const float4*)&g_Qh[gidx];
        *(float4*)&sQl[r*36 + c4] = *(const float4*)&g_Ql[gidx];
    }

    const int qrow = q0 + warp*16 + g;
    const float* triP0 = g_TRI + hbase + (size_t)qrow*NN;
    const float* triP1 = triP0 + (size_t)8*NN;

    float m0v = -1e30f, m1v = -1e30f, l0 = 0.f, l1 = 0.f;
    float oacc[4][4];
    #pragma unroll
    for (int a = 0; a < 4; a++)
        #pragma unroll
        for (int b = 0; b < 4; b++) oacc[a][b] = 0.f;

    for (int kb = 0; kb < NN; kb += 64) {
        __syncthreads();
        for (int idx = tid; idx < 512; idx += 128) {
            const int r = idx >> 3, c4 = (idx & 7) << 2;
            const size_t gidx = (hbase + rowbase + kb + r)*CH + c4;
            *(float4*)&sKh[r*36 + c4] = *(const float4*)&g_Kh[gidx];
            *(float4*)&sKl[r*36 + c4] = *(const float4*)&g_Kl[gidx];
            *(float4*)&sV [r*40 + c4] = *(const float4*)&g_V [gidx];
        }
        if (tid < 64) sMb[tid] = 1e9f * (mask[rowbase + kb + tid] - 1.f);
        __syncthreads();

        // ---- S = Q K^T  (3xTF32) ----
        float s[8][4];
        #pragma unroll
        for (int a = 0; a < 8; a++)
            #pragma unroll
            for (int b = 0; b < 4; b++) s[a][b] = 0.f;

        #pragma unroll
        for (int ks = 0; ks < 4; ks++) {
            const int k0 = ks*8;
            const int mr = warp*16;
            unsigned ah[4], al[4];
            ah[0] = fu(sQh[(mr+g  )*36 + k0+tg  ]);
            ah[1] = fu(sQh[(mr+g+8)*36 + k0+tg  ]);
            ah[2] = fu(sQh[(mr+g  )*36 + k0+tg+4]);
            ah[3] = fu(sQh[(mr+g+8)*36 + k0+tg+4]);
            al[0] = fu(sQl[(mr+g  )*36 + k0+tg  ]);
            al[1] = fu(sQl[(mr+g+8)*36 + k0+tg  ]);
            al[2] = fu(sQl[(mr+g  )*36 + k0+tg+4]);
            al[3] = fu(sQl[(mr+g+8)*36 + k0+tg+4]);
            #pragma unroll
            for (int nt = 0; nt < 8; nt++) {
                unsigned bh[2], bl[2];
                bh[0] = fu(sKh[(nt*8+g)*36 + k0+tg  ]);
                bh[1] = fu(sKh[(nt*8+g)*36 + k0+tg+4]);
                bl[0] = fu(sKl[(nt*8+g)*36 + k0+tg  ]);
                bl[1] = fu(sKl[(nt*8+g)*36 + k0+tg+4]);
                mma8(s[nt], ah, bh);
                mma8(s[nt], ah, bl);
                mma8(s[nt], al, bh);
            }
        }

        // ---- bias + online softmax ----
        float cm0 = -1e30f, cm1 = -1e30f;
        #pragma unroll
        for (int nt = 0; nt < 8; nt++) {
            const int col = nt*8 + 2*tg;
            const float2 t0 = *(const float2*)&triP0[kb + col];
            const float2 t1 = *(const float2*)&triP1[kb + col];
            const float mb0 = sMb[col], mb1 = sMb[col+1];
            s[nt][0] += t0.x + mb0; s[nt][1] += t0.y + mb1;
            s[nt][2] += t1.x + mb0; s[nt][3] += t1.y + mb1;
            cm0 = fmaxf(cm0, fmaxf(s[nt][0], s[nt][1]));
            cm1 = fmaxf(cm1, fmaxf(s[nt][2], s[nt][3]));
        }
        cm0 = fmaxf(cm0, __shfl_xor_sync(0xffffffffu, cm0, 1));
        cm0 = fmaxf(cm0, __shfl_xor_sync(0xffffffffu, cm0, 2));
        cm1 = fmaxf(cm1, __shfl_xor_sync(0xffffffffu, cm1, 1));
        cm1 = fmaxf(cm1, __shfl_xor_sync(0xffffffffu, cm1, 2));
        const float nm0 = fmaxf(m0v, cm0), nm1 = fmaxf(m1v, cm1);
        const float sc0 = __expf(m0v - nm0), sc1 = __expf(m1v - nm1);
        m0v = nm0; m1v = nm1;

        float sum0 = 0.f, sum1 = 0.f;
        const int prow0 = (warp*16+g)*68, prow1 = prow0 + 8*68;
        #pragma unroll
        for (int nt = 0; nt < 8; nt++) {
            const int col = nt*8 + 2*tg;
            const float p0 = __expf(s[nt][0]-nm0), p1 = __expf(s[nt][1]-nm0);
            const float p2 = __expf(s[nt][2]-nm1), p3 = __expf(s[nt][3]-nm1);
            sum0 += p0 + p1; sum1 += p2 + p3;
            sP[prow0+col]   = __uint_as_float(f2tf(p0));
            sP[prow0+col+1] = __uint_as_float(f2tf(p1));
            sP[prow1+col]   = __uint_as_float(f2tf(p2));
            sP[prow1+col+1] = __uint_as_float(f2tf(p3));
        }
        sum0 += __shfl_xor_sync(0xffffffffu, sum0, 1);
        sum0 += __shfl_xor_sync(0xffffffffu, sum0, 2);
        sum1 += __shfl_xor_sync(0xffffffffu, sum1, 1);
        sum1 += __shfl_xor_sync(0xffffffffu, sum1, 2);
        l0 = l0*sc0 + sum0; l1 = l1*sc1 + sum1;
        #pragma unroll
        for (int nt = 0; nt < 4; nt++) {
            oacc[nt][0] *= sc0; oacc[nt][1] *= sc0;
            oacc[nt][2] *= sc1; oacc[nt][3] *= sc1;
        }
        __syncwarp();

        // ---- O += P V  (1xTF32) ----
        #pragma unroll
        for (int ks = 0; ks < 8; ks++) {
            const int k0 = ks*8;
            const int pr = warp*16;
            unsigned ah[4];
            ah[0] = fu(sP[(pr+g  )*68 + k0+tg  ]);
            ah[1] = fu(sP[(pr+g+8)*68 + k0+tg  ]);
            ah[2] = fu(sP[(pr+g  )*68 + k0+tg+4]);
            ah[3] = fu(sP[(pr+g+8)*68 + k0+tg+4]);
            #pragma unroll
            for (int nt = 0; nt < 4; nt++) {
                unsigned bh[2];
                bh[0] = fu(sV[(k0+tg  )*40 + nt*8 + g]);
                bh[1] = fu(sV[(k0+tg+4)*40 + nt*8 + g]);
                mma8(oacc[nt], ah, bh);
            }
        }
    }

    const float inv0 = 1.f/l0, inv1 = 1.f/l1;
    const size_t ob0 = (rowbase + qrow)*CIN + h*CH;
    const size_t ob1 = (rowbase + qrow + 8)*CIN + h*CH;
    #pragma unroll
    for (int nt = 0; nt < 4; nt++) {
        const int col = nt*8 + 2*tg;
        *(float2*)&g_O[ob0 + col] = make_float2(oacc[nt][0]*inv0, oacc[nt][1]*inv0);
        *(float2*)&g_O[ob1 + col] = make_float2(oacc[nt][2]*inv1, oacc[nt][3]*inv1);
    }
}

// =====================================================================
// GEMM 3: out = (O*G) @ wo, 1xTF32.
// =====================================================================
__global__ void __launch_bounds__(128)
outproj_mma_kernel(float* __restrict__ out)
{
    extern __shared__ float sh[];
    float* sA = sh;              // [64][68]
    float* sB = sA + 64*68;      // [64][72]

    const int tid  = threadIdx.x;
    const int warp = tid >> 5, lane = tid & 31;
    const int g = lane >> 2, tg = lane & 3;
    const int wm = warp >> 1, wn = warp & 1;
    const int n0 = blockIdx.x * 64;
    const int m0 = blockIdx.y * 64;

    float acc[2][4][4];
    #pragma unroll
    for (int a = 0; a < 2; a++)
        #pragma unroll
        for (int b = 0; b < 4; b++)
            #pragma unroll
            for (int c = 0; c < 4; c++) acc[a][b][c] = 0.f;

    for (int kc = 0; kc < 128; kc += 64) {
        __syncthreads();
        for (int idx = tid; idx < 1024; idx += 128) {
            const int r = idx >> 4, c4 = (idx & 15) << 2;
            const size_t ga = (size_t)(m0+r)*CIN + kc + c4;
            const float4 o4 = *(const float4*)&g_O[ga];
            const float4 g4 = *(const float4*)&g_G[ga];
            float4 a4;
            a4.x = __uint_as_float(f2tf(o4.x*g4.x));
            a4.y = __uint_as_float(f2tf(o4.y*g4.y));
            a4.z = __uint_as_float(f2tf(o4.z*g4.z));
            a4.w = __uint_as_float(f2tf(o4.w*g4.w));
            *(float4*)&sA[r*68 + c4] = a4;
            *(float4*)&sB[r*72 + c4] = *(const float4*)&g_WO[(size_t)(kc+r)*CIN + n0 + c4];
        }
        __syncthreads();
        #pragma unroll
        for (int ks = 0; ks < 8; ks++) {
            const int k0 = ks*8;
            unsigned ah[2][4];
            #pragma unroll
            for (int mt = 0; mt < 2; mt++) {
                const int mr = wm*32 + mt*16;
                ah[mt][0] = fu(sA[(mr+g  )*68 + k0+tg  ]);
                ah[mt][1] = fu(sA[(mr+g+8)*68 + k0+tg  ]);
                ah[mt][2] = fu(sA[(mr+g  )*68 + k0+tg+4]);
                ah[mt][3] = fu(sA[(mr+g+8)*68 + k0+tg+4]);
            }
            #pragma unroll
            for (int nt = 0; nt < 4; nt++) {
                const int nc = wn*32 + nt*8;
                unsigned bh[2];
                bh[0] = fu(sB[(k0+tg  )*72 + nc + g]);
                bh[1] = fu(sB[(k0+tg+4)*72 + nc + g]);
                #pragma unroll
                for (int mt = 0; mt < 2; mt++)
                    mma8(acc[mt][nt], ah[mt], bh);
            }
        }
    }

    #pragma unroll
    for (int mt = 0; mt < 2; mt++) {
        const int r0 = m0 + wm*32 + mt*16 + g;
        #pragma unroll
        for (int nt = 0; nt < 4; nt++) {
            const int col = n0 + wn*32 + nt*8 + 2*tg;
            *(float2*)&out[(size_t)r0*CIN + col]     = make_float2(acc[mt][nt][0], acc[mt][nt][1]);
            *(float2*)&out[(size_t)(r0+8)*CIN + col] = make_float2(acc[mt][nt][2], acc[mt][nt][3]);
        }
    }
}

// =====================================================================
// launch
// =====================================================================
extern "C" void kernel_launch(void* const* d_in, const int* in_sizes, int n_in,
                              void* d_out, int out_size)
{
    (void)in_sizes; (void)n_in; (void)out_size;
    const float* z    = (const float*)d_in[0];
    const float* mask = (const float*)d_in[1];
    const float* lnw  = (const float*)d_in[2];
    const float* lnb  = (const float*)d_in[3];
    const float* wtri = (const float*)d_in[4];
    const float* wq   = (const float*)d_in[5];
    const float* wk   = (const float*)d_in[6];
    const float* wv   = (const float*)d_in[7];
    const float* wg   = (const float*)d_in[8];
    const float* wo   = (const float*)d_in[9];

    const size_t proj_sh = (size_t)(2*64*68 + 2*64*72) * sizeof(float);           // 71680
    const size_t attn_sh = (size_t)(4*2304 + 2560 + 4352 + 64) * sizeof(float);    // 64768
    const size_t out_sh  = (size_t)(64*68 + 64*72) * sizeof(float);                // 35840
    cudaFuncSetAttribute(proj_mma_kernel,    cudaFuncAttributeMaxDynamicSharedMemorySize, (int)proj_sh);
    cudaFuncSetAttribute(attn_mma_kernel,    cudaFuncAttributeMaxDynamicSharedMemorySize, (int)attn_sh);
    cudaFuncSetAttribute(outproj_mma_kernel, cudaFuncAttributeMaxDynamicSharedMemorySize, (int)out_sh);

    wsplit_kernel<<<(CIN*WCOLS + CIN*CIN + 255)/256, 256>>>(wq, wk, wv, wg, wtri, wo);
    ln_split_kernel<<<M_TOT/8, 256>>>(z, lnw, lnb);
    proj_mma_kernel<<<dim3(9, M_TOT/64), 128, proj_sh>>>();
    attn_mma_kernel<<<dim3(NN/64, NN, NH), 128, attn_sh>>>(mask);
    outproj_mma_kernel<<<dim3(2, M_TOT/64), 128, out_sh>>>((float*)d_out);
}

// round 4
// speedup vs baseline: 1.8422x; 1.3006x over previous
#include <cuda_runtime.h>
#include <math.h>

// ---------------- problem constants ----------------
#define NN   384
#define CIN  128
#define NH   4
#define CH   32
#define M_TOT (NN*NN)                   // 147456
#define QK_SCALE 0.17677669529663687f   // 1/sqrt(32)
#define WCOLS 576                        // 512 proj cols + 4 tri + pad

// ---------------- scratch (device globals; no allocs) ----------------
__device__ float g_LAh[(size_t)M_TOT*CIN];       // LN(z) tf32-hi
__device__ float g_LAl[(size_t)M_TOT*CIN];       // LN(z) tf32-lo
__device__ float g_Wh [(size_t)CIN*WCOLS];       // packed weights hi
__device__ float g_Wl [(size_t)CIN*WCOLS];
__device__ float g_WO [(size_t)CIN*CIN];         // wo (tf32-rounded)
__device__ float g_Qh [(size_t)NH*M_TOT*CH];     // head-major [h][m][c]
__device__ float g_Ql [(size_t)NH*M_TOT*CH];
__device__ float g_Kh [(size_t)NH*M_TOT*CH];
__device__ float g_Kl [(size_t)NH*M_TOT*CH];
__device__ float g_V  [(size_t)NH*M_TOT*CH];     // tf32-rounded, head-major
__device__ float g_G  [(size_t)M_TOT*CIN];       // sigmoid gate, m-major fp32
__device__ float g_TRI[(size_t)NH*M_TOT];
__device__ float g_O  [(size_t)M_TOT*CIN];       // attn out, m-major

// ---------------- helpers ----------------
__device__ __forceinline__ unsigned f2tf(float x) {
    unsigned u; asm("cvt.rna.tf32.f32 %0, %1;" : "=r"(u) : "f"(x)); return u;
}
__device__ __forceinline__ void split2(float x, float& hi, float& lo) {
    hi = __uint_as_float(f2tf(x));
    lo = __uint_as_float(f2tf(x - hi));
}
__device__ __forceinline__ unsigned fu(float x) { return __float_as_uint(x); }

__device__ __forceinline__ void mma8(float* d, const unsigned* a, const unsigned* b) {
    asm volatile(
        "mma.sync.aligned.m16n8k8.row.col.f32.tf32.tf32.f32 "
        "{%0,%1,%2,%3},{%4,%5,%6,%7},{%8,%9},{%0,%1,%2,%3};\n"
        : "+f"(d[0]), "+f"(d[1]), "+f"(d[2]), "+f"(d[3])
        : "r"(a[0]), "r"(a[1]), "r"(a[2]), "r"(a[3]), "r"(b[0]), "r"(b[1]));
}

// =====================================================================
// prep 1: LayerNorm + tf32 split  (1 warp per row)
// =====================================================================
__global__ void __launch_bounds__(256)
ln_split_kernel(const float* __restrict__ z,
                const float* __restrict__ lnw, const float* __restrict__ lnb)
{
    const int row  = blockIdx.x*8 + (threadIdx.x >> 5);
    const int lane = threadIdx.x & 31;
    const float4 v = *(const float4*)(z + (size_t)row*CIN + lane*4);
    float s1 = v.x+v.y+v.z+v.w;
    float s2 = v.x*v.x + v.y*v.y + v.z*v.z + v.w*v.w;
    #pragma unroll
    for (int o = 16; o; o >>= 1) {
        s1 += __shfl_xor_sync(0xffffffffu, s1, o);
        s2 += __shfl_xor_sync(0xffffffffu, s2, o);
    }
    const float mu  = s1 * (1.f/128.f);
    const float var = s2 * (1.f/128.f) - mu*mu;
    const float inv = rsqrtf(var + 1e-5f);
    const float4 w = *(const float4*)(lnw + lane*4);
    const float4 b = *(const float4*)(lnb + lane*4);
    float y[4] = { (v.x-mu)*inv*w.x + b.x, (v.y-mu)*inv*w.y + b.y,
                   (v.z-mu)*inv*w.z + b.z, (v.w-mu)*inv*w.w + b.w };
    float4 hi4, lo4;
    split2(y[0], hi4.x, lo4.x); split2(y[1], hi4.y, lo4.y);
    split2(y[2], hi4.z, lo4.z); split2(y[3], hi4.w, lo4.w);
    *(float4*)&g_LAh[(size_t)row*CIN + lane*4] = hi4;
    *(float4*)&g_LAl[(size_t)row*CIN + lane*4] = lo4;
}

// =====================================================================
// prep 2: split/round weights
// =====================================================================
__global__ void __launch_bounds__(256)
wsplit_kernel(const float* __restrict__ wq, const float* __restrict__ wk,
              const float* __restrict__ wv, const float* __restrict__ wg,
              const float* __restrict__ wtri, const float* __restrict__ wo)
{
    const int idx = blockIdx.x*256 + threadIdx.x;
    if (idx < CIN*WCOLS) {
        const int k = idx / WCOLS, n = idx % WCOLS;
        float v;
        if      (n < 128) v = wq[k*128 + n];
        else if (n < 256) v = wk[k*128 + n-128];
        else if (n < 384) v = wv[k*128 + n-256];
        else if (n < 512) v = wg[k*128 + n-384];
        else if (n < 516) v = wtri[k*4 + n-512];
        else              v = 0.f;
        float hi, lo; split2(v, hi, lo);
        g_Wh[idx] = hi; g_Wl[idx] = lo;
    } else if (idx < CIN*WCOLS + CIN*CIN) {
        const int j = idx - CIN*WCOLS;
        g_WO[j] = __uint_as_float(f2tf(wo[j]));
    }
}

// =====================================================================
// GEMM 1: C[M,576] = LN(z) @ W.  3xTF32 for Q,K,tri; 1xTF32 for V,G.
// BM=BN=64, kc=32 chunks (small smem -> 6 CTAs/SM).
// =====================================================================
__global__ void __launch_bounds__(128)
proj_mma_kernel()
{
    extern __shared__ float sh[];
    float* sAh = sh;                 // [64][36]
    float* sAl = sAh + 64*36;
    float* sBh = sAl + 64*36;        // [32][72]
    float* sBl = sBh + 32*72;

    const int tid  = threadIdx.x;
    const int warp = tid >> 5, lane = tid & 31;
    const int g = lane >> 2, tg = lane & 3;
    const int wm = warp >> 1, wn = warp & 1;
    const int ntb = blockIdx.x;            // 0..8
    const int m0  = blockIdx.y * 64;
    const int n0  = ntb * 64;
    const bool do3x = (ntb < 4) || (ntb == 8);
    const int ntmax = (ntb == 8) ? ((wn == 0) ? 1 : 0) : 4;

    float acc[2][4][4];
    #pragma unroll
    for (int a = 0; a < 2; a++)
        #pragma unroll
        for (int b = 0; b < 4; b++)
            #pragma unroll
            for (int c = 0; c < 4; c++) acc[a][b][c] = 0.f;

    for (int kc = 0; kc < 128; kc += 32) {
        __syncthreads();
        for (int idx = tid; idx < 512; idx += 128) {
            const int ra = idx >> 3, ca = (idx & 7) << 2;       // A: 64 rows x 32 k
            const int rb = idx >> 4, cb = (idx & 15) << 2;      // B: 32 k x 64 n
            *(float4*)&sAh[ra*36 + ca] = *(const float4*)&g_LAh[(size_t)(m0+ra)*CIN + kc + ca];
            *(float4*)&sBh[rb*72 + cb] = *(const float4*)&g_Wh[(size_t)(kc+rb)*WCOLS + n0 + cb];
            if (do3x) {
                *(float4*)&sAl[ra*36 + ca] = *(const float4*)&g_LAl[(size_t)(m0+ra)*CIN + kc + ca];
                *(float4*)&sBl[rb*72 + cb] = *(const float4*)&g_Wl[(size_t)(kc+rb)*WCOLS + n0 + cb];
            }
        }
        __syncthreads();
        #pragma unroll
        for (int ks = 0; ks < 4; ks++) {
            const int k0 = ks*8;
            unsigned ah[2][4], al[2][4];
            #pragma unroll
            for (int mt = 0; mt < 2; mt++) {
                const int mr = wm*32 + mt*16;
                ah[mt][0] = fu(sAh[(mr+g  )*36 + k0+tg  ]);
                ah[mt][1] = fu(sAh[(mr+g+8)*36 + k0+tg  ]);
                ah[mt][2] = fu(sAh[(mr+g  )*36 + k0+tg+4]);
                ah[mt][3] = fu(sAh[(mr+g+8)*36 + k0+tg+4]);
                if (do3x) {
                    al[mt][0] = fu(sAl[(mr+g  )*36 + k0+tg  ]);
                    al[mt][1] = fu(sAl[(mr+g+8)*36 + k0+tg  ]);
                    al[mt][2] = fu(sAl[(mr+g  )*36 + k0+tg+4]);
                    al[mt][3] = fu(sAl[(mr+g+8)*36 + k0+tg+4]);
                }
            }
            for (int nt = 0; nt < ntmax; nt++) {
                const int nc = wn*32 + nt*8;
                unsigned bh[2], bl[2];
                bh[0] = fu(sBh[(k0+tg  )*72 + nc + g]);
                bh[1] = fu(sBh[(k0+tg+4)*72 + nc + g]);
                if (do3x) {
                    bl[0] = fu(sBl[(k0+tg  )*72 + nc + g]);
                    bl[1] = fu(sBl[(k0+tg+4)*72 + nc + g]);
                }
                #pragma unroll
                for (int mt = 0; mt < 2; mt++) {
                    mma8(acc[mt][nt], ah[mt], bh);
                    if (do3x) {
                        mma8(acc[mt][nt], ah[mt], bl);
                        mma8(acc[mt][nt], al[mt], bh);
                    }
                }
            }
        }
    }

    // ---- epilogues ----
    if (ntb < 8) {
        const int cbase = (ntb & 1)*64;
        const int kind  = ntb >> 1;          // 0=Q 1=K 2=V 3=G
        #pragma unroll
        for (int mt = 0; mt < 2; mt++) {
            const int r0 = m0 + wm*32 + mt*16 + g;
            #pragma unroll
            for (int nt = 0; nt < 4; nt++) {
                const int col = cbase + wn*32 + nt*8 + 2*tg;
                const int h = col >> 5, c0 = col & 31;
                const size_t hm0 = ((size_t)h*M_TOT + r0)*CH + c0;
                const size_t hm1 = ((size_t)h*M_TOT + r0 + 8)*CH + c0;
                float v0 = acc[mt][nt][0], v1 = acc[mt][nt][1];
                float v2 = acc[mt][nt][2], v3 = acc[mt][nt][3];
                if (kind == 0) {
                    v0*=QK_SCALE; v1*=QK_SCALE; v2*=QK_SCALE; v3*=QK_SCALE;
                    float h0,l0_,h1,l1_,h2,l2_,h3,l3_;
                    split2(v0,h0,l0_); split2(v1,h1,l1_);
                    split2(v2,h2,l2_); split2(v3,h3,l3_);
                    *(float2*)&g_Qh[hm0] = make_float2(h0,h1);
                    *(float2*)&g_Ql[hm0] = make_float2(l0_,l1_);
                    *(float2*)&g_Qh[hm1] = make_float2(h2,h3);
                    *(float2*)&g_Ql[hm1] = make_float2(l2_,l3_);
                } else if (kind == 1) {
                    float h0,l0_,h1,l1_,h2,l2_,h3,l3_;
                    split2(v0,h0,l0_); split2(v1,h1,l1_);
                    split2(v2,h2,l2_); split2(v3,h3,l3_);
                    *(float2*)&g_Kh[hm0] = make_float2(h0,h1);
                    *(float2*)&g_Kl[hm0] = make_float2(l0_,l1_);
                    *(float2*)&g_Kh[hm1] = make_float2(h2,h3);
                    *(float2*)&g_Kl[hm1] = make_float2(l2_,l3_);
                } else if (kind == 2) {
                    *(float2*)&g_V[hm0] = make_float2(__uint_as_float(f2tf(v0)),
                                                      __uint_as_float(f2tf(v1)));
                    *(float2*)&g_V[hm1] = make_float2(__uint_as_float(f2tf(v2)),
                                                      __uint_as_float(f2tf(v3)));
                } else {
                    *(float2*)&g_G[(size_t)r0*CIN + col] =
                        make_float2(1.f/(1.f+__expf(-v0)), 1.f/(1.f+__expf(-v1)));
                    *(float2*)&g_G[(size_t)(r0+8)*CIN + col] =
                        make_float2(1.f/(1.f+__expf(-v2)), 1.f/(1.f+__expf(-v3)));
                }
            }
        }
    } else if (wn == 0 && tg < 2) {
        #pragma unroll
        for (int mt = 0; mt < 2; mt++) {
            const int r0 = m0 + wm*32 + mt*16 + g;
            const int c0 = 2*tg;
            g_TRI[(size_t)c0*M_TOT     + r0]   = acc[mt][0][0];
            g_TRI[(size_t)(c0+1)*M_TOT + r0]   = acc[mt][0][1];
            g_TRI[(size_t)c0*M_TOT     + r0+8] = acc[mt][0][2];
            g_TRI[(size_t)(c0+1)*M_TOT + r0+8] = acc[mt][0][3];
        }
    }
}

// =====================================================================
// flash attention: S = 3xTF32, PV = 1xTF32.
// Q fragments register-resident; P re-fragmented via warp shuffles
// (no smem P buffer).  smem = K(hi/lo) + V + mask = 27.9 KB.
// =====================================================================
__global__ void __launch_bounds__(128)
attn_mma_kernel(const float* __restrict__ mask)
{
    extern __shared__ float sh[];
    float* sKh = sh;             // [64][36]
    float* sKl = sKh + 2304;     // [64][36]
    float* sV  = sKl + 2304;     // [64][36]
    float* sMb = sV  + 2304;     // [64]

    const int tid  = threadIdx.x;
    const int warp = tid >> 5, lane = tid & 31;
    const int g = lane >> 2, tg = lane & 3;
    const int q0 = blockIdx.x * 64;
    const int i  = blockIdx.y;
    const int h  = blockIdx.z;
    const size_t rowbase = (size_t)i * NN;
    const size_t hbase   = (size_t)h * M_TOT;

    // ---- stage Q tile through the K buffers, keep fragments in regs ----
    for (int idx = tid; idx < 512; idx += 128) {
        const int r = idx >> 3, c4 = (idx & 7) << 2;
        const size_t gidx = (hbase + rowbase + q0 + r)*CH + c4;
        *(float4*)&sKh[r*36 + c4] = *(const float4*)&g_Qh[gidx];
        *(float4*)&sKl[r*36 + c4] = *(const float4*)&g_Ql[gidx];
    }
    __syncthreads();
    unsigned qh[4][4], ql[4][4];
    {
        const int mr = warp*16;
        #pragma unroll
        for (int ks = 0; ks < 4; ks++) {
            const int k0 = ks*8;
            qh[ks][0] = fu(sKh[(mr+g  )*36 + k0+tg  ]);
            qh[ks][1] = fu(sKh[(mr+g+8)*36 + k0+tg  ]);
            qh[ks][2] = fu(sKh[(mr+g  )*36 + k0+tg+4]);
            qh[ks][3] = fu(sKh[(mr+g+8)*36 + k0+tg+4]);
            ql[ks][0] = fu(sKl[(mr+g  )*36 + k0+tg  ]);
            ql[ks][1] = fu(sKl[(mr+g+8)*36 + k0+tg  ]);
            ql[ks][2] = fu(sKl[(mr+g  )*36 + k0+tg+4]);
            ql[ks][3] = fu(sKl[(mr+g+8)*36 + k0+tg+4]);
        }
    }

    const int qrow = q0 + warp*16 + g;
    const float* triP0 = g_TRI + hbase + (size_t)qrow*NN;
    const float* triP1 = triP0 + (size_t)8*NN;

    float m0v = -1e30f, m1v = -1e30f, l0 = 0.f, l1 = 0.f;
    float oacc[4][4];
    #pragma unroll
    for (int a = 0; a < 4; a++)
        #pragma unroll
        for (int b = 0; b < 4; b++) oacc[a][b] = 0.f;

    for (int kb = 0; kb < NN; kb += 64) {
        __syncthreads();
        for (int idx = tid; idx < 512; idx += 128) {
            const int r = idx >> 3, c4 = (idx & 7) << 2;
            const size_t gidx = (hbase + rowbase + kb + r)*CH + c4;
            *(float4*)&sKh[r*36 + c4] = *(const float4*)&g_Kh[gidx];
            *(float4*)&sKl[r*36 + c4] = *(const float4*)&g_Kl[gidx];
            *(float4*)&sV [r*36 + c4] = *(const float4*)&g_V [gidx];
        }
        if (tid < 64) sMb[tid] = 1e9f * (mask[rowbase + kb + tid] - 1.f);
        __syncthreads();

        // ---- S = Q K^T  (3xTF32) ----
        float s[8][4];
        #pragma unroll
        for (int a = 0; a < 8; a++)
            #pragma unroll
            for (int b = 0; b < 4; b++) s[a][b] = 0.f;

        #pragma unroll
        for (int ks = 0; ks < 4; ks++) {
            const int k0 = ks*8;
            #pragma unroll
            for (int nt = 0; nt < 8; nt++) {
                unsigned bh[2], bl[2];
                bh[0] = fu(sKh[(nt*8+g)*36 + k0+tg  ]);
                bh[1] = fu(sKh[(nt*8+g)*36 + k0+tg+4]);
                bl[0] = fu(sKl[(nt*8+g)*36 + k0+tg  ]);
                bl[1] = fu(sKl[(nt*8+g)*36 + k0+tg+4]);
                mma8(s[nt], qh[ks], bh);
                mma8(s[nt], qh[ks], bl);
                mma8(s[nt], ql[ks], bh);
            }
        }

        // ---- bias + online softmax ----
        float cm0 = -1e30f, cm1 = -1e30f;
        #pragma unroll
        for (int nt = 0; nt < 8; nt++) {
            const int col = nt*8 + 2*tg;
            const float2 t0 = *(const float2*)&triP0[kb + col];
            const float2 t1 = *(const float2*)&triP1[kb + col];
            const float mb0 = sMb[col], mb1 = sMb[col+1];
            s[nt][0] += t0.x + mb0; s[nt][1] += t0.y + mb1;
            s[nt][2] += t1.x + mb0; s[nt][3] += t1.y + mb1;
            cm0 = fmaxf(cm0, fmaxf(s[nt][0], s[nt][1]));
            cm1 = fmaxf(cm1, fmaxf(s[nt][2], s[nt][3]));
        }
        cm0 = fmaxf(cm0, __shfl_xor_sync(0xffffffffu, cm0, 1));
        cm0 = fmaxf(cm0, __shfl_xor_sync(0xffffffffu, cm0, 2));
        cm1 = fmaxf(cm1, __shfl_xor_sync(0xffffffffu, cm1, 1));
        cm1 = fmaxf(cm1, __shfl_xor_sync(0xffffffffu, cm1, 2));
        const float nm0 = fmaxf(m0v, cm0), nm1 = fmaxf(m1v, cm1);
        const float sc0 = __expf(m0v - nm0), sc1 = __expf(m1v - nm1);
        m0v = nm0; m1v = nm1;

        float sum0 = 0.f, sum1 = 0.f;
        #pragma unroll
        for (int nt = 0; nt < 8; nt++) {
            const float p0 = __expf(s[nt][0]-nm0), p1 = __expf(s[nt][1]-nm0);
            const float p2 = __expf(s[nt][2]-nm1), p3 = __expf(s[nt][3]-nm1);
            sum0 += p0 + p1; sum1 += p2 + p3;
            s[nt][0] = __uint_as_float(f2tf(p0));
            s[nt][1] = __uint_as_float(f2tf(p1));
            s[nt][2] = __uint_as_float(f2tf(p2));
            s[nt][3] = __uint_as_float(f2tf(p3));
        }
        sum0 += __shfl_xor_sync(0xffffffffu, sum0, 1);
        sum0 += __shfl_xor_sync(0xffffffffu, sum0, 2);
        sum1 += __shfl_xor_sync(0xffffffffu, sum1, 1);
        sum1 += __shfl_xor_sync(0xffffffffu, sum1, 2);
        l0 = l0*sc0 + sum0; l1 = l1*sc1 + sum1;
        #pragma unroll
        for (int nt = 0; nt < 4; nt++) {
            oacc[nt][0] *= sc0; oacc[nt][1] *= sc0;
            oacc[nt][2] *= sc1; oacc[nt][3] *= sc1;
        }

        // ---- O += P V  (1xTF32); A-frag of P built by quad shuffles ----
        const int base  = lane & ~3;              // g*4
        const int srcA  = base + (tg >> 1);
        const int srcB  = srcA + 2;
        const bool odd  = tg & 1;
        #pragma unroll
        for (int ks = 0; ks < 8; ks++) {
            const float x0 = __shfl_sync(0xffffffffu, s[ks][0], srcA);
            const float x1 = __shfl_sync(0xffffffffu, s[ks][1], srcA);
            const float x2 = __shfl_sync(0xffffffffu, s[ks][2], srcA);
            const float x3 = __shfl_sync(0xffffffffu, s[ks][3], srcA);
            const float y0 = __shfl_sync(0xffffffffu, s[ks][0], srcB);
            const float y1 = __shfl_sync(0xffffffffu, s[ks][1], srcB);
            const float y2 = __shfl_sync(0xffffffffu, s[ks][2], srcB);
            const float y3 = __shfl_sync(0xffffffffu, s[ks][3], srcB);
            unsigned a[4];
            a[0] = fu(odd ? x1 : x0);
            a[1] = fu(odd ? x3 : x2);
            a[2] = fu(odd ? y1 : y0);
            a[3] = fu(odd ? y3 : y2);
            const int k0 = ks*8;
            #pragma unroll
            for (int nt = 0; nt < 4; nt++) {
                unsigned bh[2];
                bh[0] = fu(sV[(k0+tg  )*36 + nt*8 + g]);
                bh[1] = fu(sV[(k0+tg+4)*36 + nt*8 + g]);
                mma8(oacc[nt], a, bh);
            }
        }
    }

    const float inv0 = 1.f/l0, inv1 = 1.f/l1;
    const size_t ob0 = (rowbase + qrow)*CIN + h*CH;
    const size_t ob1 = (rowbase + qrow + 8)*CIN + h*CH;
    #pragma unroll
    for (int nt = 0; nt < 4; nt++) {
        const int col = nt*8 + 2*tg;
        *(float2*)&g_O[ob0 + col] = make_float2(oacc[nt][0]*inv0, oacc[nt][1]*inv0);
        *(float2*)&g_O[ob1 + col] = make_float2(oacc[nt][2]*inv1, oacc[nt][3]*inv1);
    }
}

// =====================================================================
// GEMM 3: out = (O*G) @ wo, 1xTF32, kc=32 chunks.
// =====================================================================
__global__ void __launch_bounds__(128)
outproj_mma_kernel(float* __restrict__ out)
{
    extern __shared__ float sh[];
    float* sA = sh;              // [64][36]
    float* sB = sA + 64*36;      // [32][72]

    const int tid  = threadIdx.x;
    const int warp = tid >> 5, lane = tid & 31;
    const int g = lane >> 2, tg = lane & 3;
    const int wm = warp >> 1, wn = warp & 1;
    const int n0 = blockIdx.x * 64;
    const int m0 = blockIdx.y * 64;

    float acc[2][4][4];
    #pragma unroll
    for (int a = 0; a < 2; a++)
        #pragma unroll
        for (int b = 0; b < 4; b++)
            #pragma unroll
            for (int c = 0; c < 4; c++) acc[a][b][c] = 0.f;

    for (int kc = 0; kc < 128; kc += 32) {
        __syncthreads();
        for (int idx = tid; idx < 512; idx += 128) {
            const int ra = idx >> 3, ca = (idx & 7) << 2;
            const size_t ga = (size_t)(m0+ra)*CIN + kc + ca;
            const float4 o4 = *(const float4*)&g_O[ga];
            const float4 g4 = *(const float4*)&g_G[ga];
            float4 a4;
            a4.x = __uint_as_float(f2tf(o4.x*g4.x));
            a4.y = __uint_as_float(f2tf(o4.y*g4.y));
            a4.z = __uint_as_float(f2tf(o4.z*g4.z));
            a4.w = __uint_as_float(f2tf(o4.w*g4.w));
            *(float4*)&sA[ra*36 + ca] = a4;
            const int rb = idx >> 4, cb = (idx & 15) << 2;
            *(float4*)&sB[rb*72 + cb] = *(const float4*)&g_WO[(size_t)(kc+rb)*CIN + n0 + cb];
        }
        __syncthreads();
        #pragma unroll
        for (int ks = 0; ks < 4; ks++) {
            const int k0 = ks*8;
            unsigned ah[2][4];
            #pragma unroll
            for (int mt = 0; mt < 2; mt++) {
                const int mr = wm*32 + mt*16;
                ah[mt][0] = fu(sA[(mr+g  )*36 + k0+tg  ]);
                ah[mt][1] = fu(sA[(mr+g+8)*36 + k0+tg  ]);
                ah[mt][2] = fu(sA[(mr+g  )*36 + k0+tg+4]);
                ah[mt][3] = fu(sA[(mr+g+8)*36 + k0+tg+4]);
            }
            #pragma unroll
            for (int nt = 0; nt < 4; nt++) {
                const int nc = wn*32 + nt*8;
                unsigned bh[2];
                bh[0] = fu(sB[(k0+tg  )*72 + nc + g]);
                bh[1] = fu(sB[(k0+tg+4)*72 + nc + g]);
                #pragma unroll
                for (int mt = 0; mt < 2; mt++)
                    mma8(acc[mt][nt], ah[mt], bh);
            }
        }
    }

    #pragma unroll
    for (int mt = 0; mt < 2; mt++) {
        const int r0 = m0 + wm*32 + mt*16 + g;
        #pragma unroll
        for (int nt = 0; nt < 4; nt++) {
            const int col = n0 + wn*32 + nt*8 + 2*tg;
            *(float2*)&out[(size_t)r0*CIN + col]     = make_float2(acc[mt][nt][0], acc[mt][nt][1]);
            *(float2*)&out[(size_t)(r0+8)*CIN + col] = make_float2(acc[mt][nt][2], acc[mt][nt][3]);
        }
    }
}

// =====================================================================
// launch
// =====================================================================
extern "C" void kernel_launch(void* const* d_in, const int* in_sizes, int n_in,
                              void* d_out, int out_size)
{
    (void)in_sizes; (void)n_in; (void)out_size;
    const float* z    = (const float*)d_in[0];
    const float* mask = (const float*)d_in[1];
    const float* lnw  = (const float*)d_in[2];
    const float* lnb  = (const float*)d_in[3];
    const float* wtri = (const float*)d_in[4];
    const float* wq   = (const float*)d_in[5];
    const float* wk   = (const float*)d_in[6];
    const float* wv   = (const float*)d_in[7];
    const float* wg   = (const float*)d_in[8];
    const float* wo   = (const float*)d_in[9];

    const size_t proj_sh = (size_t)(2*64*36 + 2*32*72) * sizeof(float);    // 36864
    const size_t attn_sh = (size_t)(3*2304 + 64) * sizeof(float);          // 27904
    const size_t out_sh  = (size_t)(64*36 + 32*72) * sizeof(float);        // 18432

    wsplit_kernel<<<(CIN*WCOLS + CIN*CIN + 255)/256, 256>>>(wq, wk, wv, wg, wtri, wo);
    ln_split_kernel<<<M_TOT/8, 256>>>(z, lnw, lnb);
    proj_mma_kernel<<<dim3(9, M_TOT/64), 128, proj_sh>>>();
    attn_mma_kernel<<<dim3(NN/64, NN, NH), 128, attn_sh>>>(mask);
    outproj_mma_kernel<<<dim3(2, M_TOT/64), 128, out_sh>>>((float*)d_out);
}

// round 5
// speedup vs baseline: 2.5377x; 1.3776x over previous
#include <cuda_runtime.h>
#include <cuda_bf16.h>
#include <math.h>

// ---------------- problem constants ----------------
#define NN   384
#define CIN  128
#define NH   4
#define CH   32
#define M_TOT (NN*NN)                   // 147456
#define QK_SCALE 0.17677669529663687f   // 1/sqrt(32)
#define WCOLS 576                        // 512 proj cols + 4 tri + pad

// ---------------- scratch (device globals; no allocs) ----------------
// LN(z): packed bf16x2 hi/lo planes, [m][64 words] (k pairs packed)
__device__ unsigned g_Ah[(size_t)M_TOT*64];
__device__ unsigned g_Al[(size_t)M_TOT*64];
// weights transposed+packed: [n][64 kwords]
__device__ unsigned g_Wth[(size_t)WCOLS*64];
__device__ unsigned g_Wtl[(size_t)WCOLS*64];
__device__ float    g_WO [(size_t)CIN*CIN];      // wo (tf32-rounded) for outproj
// Q/K head-major packed bf16x2 hi/lo planes: [h][m][16 words]
__device__ unsigned g_Qph[(size_t)NH*M_TOT*16];
__device__ unsigned g_Qpl[(size_t)NH*M_TOT*16];
__device__ unsigned g_Kph[(size_t)NH*M_TOT*16];
__device__ unsigned g_Kpl[(size_t)NH*M_TOT*16];
__device__ float g_V  [(size_t)NH*M_TOT*CH];     // tf32-rounded, head-major
__device__ float g_G  [(size_t)M_TOT*CIN];       // sigmoid gate, m-major
__device__ float g_TRI[(size_t)NH*M_TOT];
__device__ float g_O  [(size_t)M_TOT*CIN];       // attn out, m-major

// ---------------- helpers ----------------
__device__ __forceinline__ unsigned f2tf(float x) {
    unsigned u; asm("cvt.rna.tf32.f32 %0, %1;" : "=r"(u) : "f"(x)); return u;
}
__device__ __forceinline__ unsigned fu(float x) { return __float_as_uint(x); }

// pack two floats to bf16x2 (lo half = first element)
__device__ __forceinline__ unsigned packbf(float a, float b) {
    __nv_bfloat162 t = __floats2bfloat162_rn(a, b);
    return *(unsigned*)&t;
}
// bf16 2-term split of a pair -> (hi word, lo word)
__device__ __forceinline__ void splitbf2(float a, float b, unsigned& hw, unsigned& lw) {
    __nv_bfloat16 ha = __float2bfloat16_rn(a);
    __nv_bfloat16 hb = __float2bfloat16_rn(b);
    float ra = a - __bfloat162float(ha);
    float rb = b - __bfloat162float(hb);
    __nv_bfloat162 h; h.x = ha; h.y = hb;
    hw = *(unsigned*)&h;
    lw = packbf(ra, rb);
}

// tf32 m16n8k8: D += A*B
__device__ __forceinline__ void mma8(float* d, const unsigned* a, const unsigned* b) {
    asm volatile(
        "mma.sync.aligned.m16n8k8.row.col.f32.tf32.tf32.f32 "
        "{%0,%1,%2,%3},{%4,%5,%6,%7},{%8,%9},{%0,%1,%2,%3};\n"
        : "+f"(d[0]), "+f"(d[1]), "+f"(d[2]), "+f"(d[3])
        : "r"(a[0]), "r"(a[1]), "r"(a[2]), "r"(a[3]), "r"(b[0]), "r"(b[1]));
}
// bf16 m16n8k16: D += A*B
__device__ __forceinline__ void mma16(float* d, const unsigned* a, const unsigned* b) {
    asm volatile(
        "mma.sync.aligned.m16n8k16.row.col.f32.bf16.bf16.f32 "
        "{%0,%1,%2,%3},{%4,%5,%6,%7},{%8,%9},{%0,%1,%2,%3};\n"
        : "+f"(d[0]), "+f"(d[1]), "+f"(d[2]), "+f"(d[3])
        : "r"(a[0]), "r"(a[1]), "r"(a[2]), "r"(a[3]), "r"(b[0]), "r"(b[1]));
}

// =====================================================================
// prep 1: LayerNorm + bf16-split pack (1 warp per row)
// =====================================================================
__global__ void __launch_bounds__(256)
ln_split_kernel(const float* __restrict__ z,
                const float* __restrict__ lnw, const float* __restrict__ lnb)
{
    const int row  = blockIdx.x*8 + (threadIdx.x >> 5);
    const int lane = threadIdx.x & 31;
    const float4 v = *(const float4*)(z + (size_t)row*CIN + lane*4);
    float s1 = v.x+v.y+v.z+v.w;
    float s2 = v.x*v.x + v.y*v.y + v.z*v.z + v.w*v.w;
    #pragma unroll
    for (int o = 16; o; o >>= 1) {
        s1 += __shfl_xor_sync(0xffffffffu, s1, o);
        s2 += __shfl_xor_sync(0xffffffffu, s2, o);
    }
    const float mu  = s1 * (1.f/128.f);
    const float var = s2 * (1.f/128.f) - mu*mu;
    const float inv = rsqrtf(var + 1e-5f);
    const float4 w = *(const float4*)(lnw + lane*4);
    const float4 b = *(const float4*)(lnb + lane*4);
    const float y0 = (v.x-mu)*inv*w.x + b.x;
    const float y1 = (v.y-mu)*inv*w.y + b.y;
    const float y2 = (v.z-mu)*inv*w.z + b.z;
    const float y3 = (v.w-mu)*inv*w.w + b.w;
    unsigned h0,l0,h1,l1;
    splitbf2(y0,y1,h0,l0);
    splitbf2(y2,y3,h1,l1);
    const size_t base = (size_t)row*64 + lane*2;
    g_Ah[base] = h0; g_Ah[base+1] = h1;
    g_Al[base] = l0; g_Al[base+1] = l1;
}

// =====================================================================
// prep 2: weights -> transposed packed bf16 planes (+ wo tf32)
// =====================================================================
__global__ void __launch_bounds__(256)
wsplit_kernel(const float* __restrict__ wq, const float* __restrict__ wk,
              const float* __restrict__ wv, const float* __restrict__ wg,
              const float* __restrict__ wtri, const float* __restrict__ wo)
{
    const int idx = blockIdx.x*256 + threadIdx.x;
    if (idx < WCOLS*64) {
        const int n = idx >> 6, kw = idx & 63;
        const int k0 = kw*2;
        float v0, v1;
        if      (n < 128) { v0 = wq[k0*128 + n];          v1 = wq[(k0+1)*128 + n]; }
        else if (n < 256) { v0 = wk[k0*128 + n-128];      v1 = wk[(k0+1)*128 + n-128]; }
        else if (n < 384) { v0 = wv[k0*128 + n-256];      v1 = wv[(k0+1)*128 + n-256]; }
        else if (n < 512) { v0 = wg[k0*128 + n-384];      v1 = wg[(k0+1)*128 + n-384]; }
        else if (n < 516) { v0 = wtri[k0*4 + n-512];      v1 = wtri[(k0+1)*4 + n-512]; }
        else              { v0 = 0.f; v1 = 0.f; }
        unsigned hw, lw; splitbf2(v0, v1, hw, lw);
        g_Wth[idx] = hw; g_Wtl[idx] = lw;
    } else if (idx < WCOLS*64 + CIN*CIN) {
        const int j = idx - WCOLS*64;
        g_WO[j] = __uint_as_float(f2tf(wo[j]));
    }
}

// =====================================================================
// GEMM 1: C[M,576] = LN(z) @ W, uniform split-bf16 (3 x m16n8k16).
// BM=BN=64, kc=32 chunks. 128 thr (4 warps 2x2).
// =====================================================================
__global__ void __launch_bounds__(128, 4)
proj_mma_kernel()
{
    extern __shared__ unsigned shp[];
    unsigned* sAh = shp;                // [64][20] words (16 used)
    unsigned* sAl = sAh + 64*20;
    unsigned* sBh = sAl + 64*20;        // [64 n][20] words
    unsigned* sBl = sBh + 64*20;

    const int tid  = threadIdx.x;
    const int warp = tid >> 5, lane = tid & 31;
    const int g = lane >> 2, tg = lane & 3;
    const int wm = warp >> 1, wn = warp & 1;
    const int ntb = blockIdx.x;            // 0..8
    const int m0  = blockIdx.y * 64;
    const int n0  = ntb * 64;
    const int ntmax = (ntb == 8) ? ((wn == 0) ? 1 : 0) : 4;

    float acc[2][4][4];
    #pragma unroll
    for (int a = 0; a < 2; a++)
        #pragma unroll
        for (int b = 0; b < 4; b++)
            #pragma unroll
            for (int c = 0; c < 4; c++) acc[a][b][c] = 0.f;

    for (int kc = 0; kc < 128; kc += 32) {
        const int kw0 = kc >> 1;           // word offset in global planes
        __syncthreads();
        for (int idx = tid; idx < 256; idx += 128) {
            const int r = idx >> 2, w4 = (idx & 3) << 2;
            *(uint4*)&sAh[r*20 + w4] = *(const uint4*)&g_Ah[(size_t)(m0+r)*64 + kw0 + w4];
            *(uint4*)&sAl[r*20 + w4] = *(const uint4*)&g_Al[(size_t)(m0+r)*64 + kw0 + w4];
            *(uint4*)&sBh[r*20 + w4] = *(const uint4*)&g_Wth[(size_t)(n0+r)*64 + kw0 + w4];
            *(uint4*)&sBl[r*20 + w4] = *(const uint4*)&g_Wtl[(size_t)(n0+r)*64 + kw0 + w4];
        }
        __syncthreads();
        #pragma unroll
        for (int sub = 0; sub < 2; sub++) {
            const int w0 = sub*8;
            unsigned ah[2][4], al[2][4];
            #pragma unroll
            for (int mt = 0; mt < 2; mt++) {
                const int mr = wm*32 + mt*16;
                ah[mt][0] = sAh[(mr+g  )*20 + w0+tg  ];
                ah[mt][1] = sAh[(mr+g+8)*20 + w0+tg  ];
                ah[mt][2] = sAh[(mr+g  )*20 + w0+tg+4];
                ah[mt][3] = sAh[(mr+g+8)*20 + w0+tg+4];
                al[mt][0] = sAl[(mr+g  )*20 + w0+tg  ];
                al[mt][1] = sAl[(mr+g+8)*20 + w0+tg  ];
                al[mt][2] = sAl[(mr+g  )*20 + w0+tg+4];
                al[mt][3] = sAl[(mr+g+8)*20 + w0+tg+4];
            }
            for (int nt = 0; nt < ntmax; nt++) {
                const int nc = wn*32 + nt*8 + g;
                unsigned bh[2], bl[2];
                bh[0] = sBh[nc*20 + w0+tg  ];
                bh[1] = sBh[nc*20 + w0+tg+4];
                bl[0] = sBl[nc*20 + w0+tg  ];
                bl[1] = sBl[nc*20 + w0+tg+4];
                #pragma unroll
                for (int mt = 0; mt < 2; mt++) {
                    mma16(acc[mt][nt], ah[mt], bh);
                    mma16(acc[mt][nt], ah[mt], bl);
                    mma16(acc[mt][nt], al[mt], bh);
                }
            }
        }
    }

    // ---- epilogues ----
    if (ntb < 8) {
        const int cbase = (ntb & 1)*64;
        const int kind  = ntb >> 1;          // 0=Q 1=K 2=V 3=G
        #pragma unroll
        for (int mt = 0; mt < 2; mt++) {
            const int r0 = m0 + wm*32 + mt*16 + g;
            #pragma unroll
            for (int nt = 0; nt < 4; nt++) {
                const int col = cbase + wn*32 + nt*8 + 2*tg;
                const int h = col >> 5, c0 = col & 31;
                float v0 = acc[mt][nt][0], v1 = acc[mt][nt][1];
                float v2 = acc[mt][nt][2], v3 = acc[mt][nt][3];
                if (kind == 0 || kind == 1) {
                    if (kind == 0) { v0*=QK_SCALE; v1*=QK_SCALE; v2*=QK_SCALE; v3*=QK_SCALE; }
                    unsigned* dh = (kind == 0) ? g_Qph : g_Kph;
                    unsigned* dl = (kind == 0) ? g_Qpl : g_Kpl;
                    const size_t w0i = ((size_t)h*M_TOT + r0)*16 + (c0>>1);
                    const size_t w1i = ((size_t)h*M_TOT + r0 + 8)*16 + (c0>>1);
                    unsigned hw, lw;
                    splitbf2(v0, v1, hw, lw); dh[w0i] = hw; dl[w0i] = lw;
                    splitbf2(v2, v3, hw, lw); dh[w1i] = hw; dl[w1i] = lw;
                } else if (kind == 2) {
                    const size_t hm0 = ((size_t)h*M_TOT + r0)*CH + c0;
                    const size_t hm1 = ((size_t)h*M_TOT + r0 + 8)*CH + c0;
                    *(float2*)&g_V[hm0] = make_float2(__uint_as_float(f2tf(v0)),
                                                      __uint_as_float(f2tf(v1)));
                    *(float2*)&g_V[hm1] = make_float2(__uint_as_float(f2tf(v2)),
                                                      __uint_as_float(f2tf(v3)));
                } else {
                    *(float2*)&g_G[(size_t)r0*CIN + col] =
                        make_float2(1.f/(1.f+__expf(-v0)), 1.f/(1.f+__expf(-v1)));
                    *(float2*)&g_G[(size_t)(r0+8)*CIN + col] =
                        make_float2(1.f/(1.f+__expf(-v2)), 1.f/(1.f+__expf(-v3)));
                }
            }
        }
    } else if (wn == 0 && tg < 2) {
        #pragma unroll
        for (int mt = 0; mt < 2; mt++) {
            const int r0 = m0 + wm*32 + mt*16 + g;
            const int c0 = 2*tg;
            g_TRI[(size_t)c0*M_TOT     + r0]   = acc[mt][0][0];
            g_TRI[(size_t)(c0+1)*M_TOT + r0]   = acc[mt][0][1];
            g_TRI[(size_t)c0*M_TOT     + r0+8] = acc[mt][0][2];
            g_TRI[(size_t)(c0+1)*M_TOT + r0+8] = acc[mt][0][3];
        }
    }
}

// =====================================================================
// flash attention: S = split-bf16 (3 x m16n8k16), PV = 1xTF32.
// Q frags in regs; P re-fragmented via quad shuffles.  smem = 19.7 KB.
// =====================================================================
__global__ void __launch_bounds__(128, 4)
attn_mma_kernel(const float* __restrict__ mask)
{
    extern __shared__ unsigned sha[];
    unsigned* sKh = sha;            // [64][20] words
    unsigned* sKl = sKh + 64*20;    // [64][20]
    float*    sV  = (float*)(sKl + 64*20);   // [64][36]
    float*    sMb = sV + 64*36;     // [64]

    const int tid  = threadIdx.x;
    const int warp = tid >> 5, lane = tid & 31;
    const int g = lane >> 2, tg = lane & 3;
    const int q0 = blockIdx.x * 64;
    const int i  = blockIdx.y;
    const int h  = blockIdx.z;
    const size_t rowbase = (size_t)i * NN;
    const size_t hbase   = (size_t)h * M_TOT;

    // ---- stage Q tile through K buffers, keep fragments in regs ----
    for (int idx = tid; idx < 256; idx += 128) {
        const int r = idx >> 2, w4 = (idx & 3) << 2;
        const size_t gw = (hbase + rowbase + q0 + r)*16 + w4;
        *(uint4*)&sKh[r*20 + w4] = *(const uint4*)&g_Qph[gw];
        *(uint4*)&sKl[r*20 + w4] = *(const uint4*)&g_Qpl[gw];
    }
    __syncthreads();
    unsigned qh[2][4], ql[2][4];
    {
        const int mr = warp*16;
        #pragma unroll
        for (int ck = 0; ck < 2; ck++) {
            const int w0 = ck*8;
            qh[ck][0] = sKh[(mr+g  )*20 + w0+tg  ];
            qh[ck][1] = sKh[(mr+g+8)*20 + w0+tg  ];
            qh[ck][2] = sKh[(mr+g  )*20 + w0+tg+4];
            qh[ck][3] = sKh[(mr+g+8)*20 + w0+tg+4];
            ql[ck][0] = sKl[(mr+g  )*20 + w0+tg  ];
            ql[ck][1] = sKl[(mr+g+8)*20 + w0+tg  ];
            ql[ck][2] = sKl[(mr+g  )*20 + w0+tg+4];
            ql[ck][3] = sKl[(mr+g+8)*20 + w0+tg+4];
        }
    }

    const int qrow = q0 + warp*16 + g;
    const float* triP0 = g_TRI + hbase + (size_t)qrow*NN;
    const float* triP1 = triP0 + (size_t)8*NN;

    float m0v = -1e30f, m1v = -1e30f, l0 = 0.f, l1 = 0.f;
    float oacc[4][4];
    #pragma unroll
    for (int a = 0; a < 4; a++)
        #pragma unroll
        for (int b = 0; b < 4; b++) oacc[a][b] = 0.f;

    for (int kb = 0; kb < NN; kb += 64) {
        __syncthreads();
        for (int idx = tid; idx < 256; idx += 128) {
            const int r = idx >> 2, w4 = (idx & 3) << 2;
            const size_t gw = (hbase + rowbase + kb + r)*16 + w4;
            *(uint4*)&sKh[r*20 + w4] = *(const uint4*)&g_Kph[gw];
            *(uint4*)&sKl[r*20 + w4] = *(const uint4*)&g_Kpl[gw];
        }
        for (int idx = tid; idx < 512; idx += 128) {
            const int r = idx >> 3, c4 = (idx & 7) << 2;
            *(float4*)&sV[r*36 + c4] = *(const float4*)&g_V[(hbase + rowbase + kb + r)*CH + c4];
        }
        if (tid < 64) sMb[tid] = 1e9f * (mask[rowbase + kb + tid] - 1.f);
        __syncthreads();

        // ---- S = Q K^T  (split-bf16) ----
        float s[8][4];
        #pragma unroll
        for (int a = 0; a < 8; a++)
            #pragma unroll
            for (int b = 0; b < 4; b++) s[a][b] = 0.f;

        #pragma unroll
        for (int ck = 0; ck < 2; ck++) {
            const int w0 = ck*8;
            #pragma unroll
            for (int nt = 0; nt < 8; nt++) {
                const int nr = (nt*8+g)*20;
                unsigned bh[2], bl[2];
                bh[0] = sKh[nr + w0+tg  ];
                bh[1] = sKh[nr + w0+tg+4];
                bl[0] = sKl[nr + w0+tg  ];
                bl[1] = sKl[nr + w0+tg+4];
                mma16(s[nt], qh[ck], bh);
                mma16(s[nt], qh[ck], bl);
                mma16(s[nt], ql[ck], bh);
            }
        }

        // ---- bias + online softmax ----
        float cm0 = -1e30f, cm1 = -1e30f;
        #pragma unroll
        for (int nt = 0; nt < 8; nt++) {
            const int col = nt*8 + 2*tg;
            const float2 t0 = *(const float2*)&triP0[kb + col];
            const float2 t1 = *(const float2*)&triP1[kb + col];
            const float mb0 = sMb[col], mb1 = sMb[col+1];
            s[nt][0] += t0.x + mb0; s[nt][1] += t0.y + mb1;
            s[nt][2] += t1.x + mb0; s[nt][3] += t1.y + mb1;
            cm0 = fmaxf(cm0, fmaxf(s[nt][0], s[nt][1]));
            cm1 = fmaxf(cm1, fmaxf(s[nt][2], s[nt][3]));
        }
        cm0 = fmaxf(cm0, __shfl_xor_sync(0xffffffffu, cm0, 1));
        cm0 = fmaxf(cm0, __shfl_xor_sync(0xffffffffu, cm0, 2));
        cm1 = fmaxf(cm1, __shfl_xor_sync(0xffffffffu, cm1, 1));
        cm1 = fmaxf(cm1, __shfl_xor_sync(0xffffffffu, cm1, 2));
        const float nm0 = fmaxf(m0v, cm0), nm1 = fmaxf(m1v, cm1);
        const float sc0 = __expf(m0v - nm0), sc1 = __expf(m1v - nm1);
        m0v = nm0; m1v = nm1;

        float sum0 = 0.f, sum1 = 0.f;
        #pragma unroll
        for (int nt = 0; nt < 8; nt++) {
            const float p0 = __expf(s[nt][0]-nm0), p1 = __expf(s[nt][1]-nm0);
            const float p2 = __expf(s[nt][2]-nm1), p3 = __expf(s[nt][3]-nm1);
            sum0 += p0 + p1; sum1 += p2 + p3;
            s[nt][0] = __uint_as_float(f2tf(p0));
            s[nt][1] = __uint_as_float(f2tf(p1));
            s[nt][2] = __uint_as_float(f2tf(p2));
            s[nt][3] = __uint_as_float(f2tf(p3));
        }
        sum0 += __shfl_xor_sync(0xffffffffu, sum0, 1);
        sum0 += __shfl_xor_sync(0xffffffffu, sum0, 2);
        sum1 += __shfl_xor_sync(0xffffffffu, sum1, 1);
        sum1 += __shfl_xor_sync(0xffffffffu, sum1, 2);
        l0 = l0*sc0 + sum0; l1 = l1*sc1 + sum1;
        #pragma unroll
        for (int nt = 0; nt < 4; nt++) {
            oacc[nt][0] *= sc0; oacc[nt][1] *= sc0;
            oacc[nt][2] *= sc1; oacc[nt][3] *= sc1;
        }

        // ---- O += P V  (1xTF32); A-frag of P via quad shuffles ----
        const int base  = lane & ~3;
        const int srcA  = base + (tg >> 1);
        const int srcB  = srcA + 2;
        const bool odd  = tg & 1;
        #pragma unroll
        for (int ks = 0; ks < 8; ks++) {
            const float x0 = __shfl_sync(0xffffffffu, s[ks][0], srcA);
            const float x1 = __shfl_sync(0xffffffffu, s[ks][1], srcA);
            const float x2 = __shfl_sync(0xffffffffu, s[ks][2], srcA);
            const float x3 = __shfl_sync(0xffffffffu, s[ks][3], srcA);
            const float y0 = __shfl_sync(0xffffffffu, s[ks][0], srcB);
            const float y1 = __shfl_sync(0xffffffffu, s[ks][1], srcB);
            const float y2 = __shfl_sync(0xffffffffu, s[ks][2], srcB);
            const float y3 = __shfl_sync(0xffffffffu, s[ks][3], srcB);
            unsigned a[4];
            a[0] = fu(odd ? x1 : x0);
            a[1] = fu(odd ? x3 : x2);
            a[2] = fu(odd ? y1 : y0);
            a[3] = fu(odd ? y3 : y2);
            const int k0 = ks*8;
            #pragma unroll
            for (int nt = 0; nt < 4; nt++) {
                unsigned bh[2];
                bh[0] = fu(sV[(k0+tg  )*36 + nt*8 + g]);
                bh[1] = fu(sV[(k0+tg+4)*36 + nt*8 + g]);
                mma8(oacc[nt], a, bh);
            }
        }
    }

    const float inv0 = 1.f/l0, inv1 = 1.f/l1;
    const size_t ob0 = (rowbase + qrow)*CIN + h*CH;
    const size_t ob1 = (rowbase + qrow + 8)*CIN + h*CH;
    #pragma unroll
    for (int nt = 0; nt < 4; nt++) {
        const int col = nt*8 + 2*tg;
        *(float2*)&g_O[ob0 + col] = make_float2(oacc[nt][0]*inv0, oacc[nt][1]*inv0);
        *(float2*)&g_O[ob1 + col] = make_float2(oacc[nt][2]*inv1, oacc[nt][3]*inv1);
    }
}

// =====================================================================
// GEMM 3: out = (O*G) @ wo, 1xTF32, kc=32 chunks.
// =====================================================================
__global__ void __launch_bounds__(128)
outproj_mma_kernel(float* __restrict__ out)
{
    extern __shared__ float sh[];
    float* sA = sh;              // [64][36]
    float* sB = sA + 64*36;      // [32][72]

    const int tid  = threadIdx.x;
    const int warp = tid >> 5, lane = tid & 31;
    const int g = lane >> 2, tg = lane & 3;
    const int wm = warp >> 1, wn = warp & 1;
    const int n0 = blockIdx.x * 64;
    const int m0 = blockIdx.y * 64;

    float acc[2][4][4];
    #pragma unroll
    for (int a = 0; a < 2; a++)
        #pragma unroll
        for (int b = 0; b < 4; b++)
            #pragma unroll
            for (int c = 0; c < 4; c++) acc[a][b][c] = 0.f;

    for (int kc = 0; kc < 128; kc += 32) {
        __syncthreads();
        for (int idx = tid; idx < 512; idx += 128) {
            const int ra = idx >> 3, ca = (idx & 7) << 2;
            const size_t ga = (size_t)(m0+ra)*CIN + kc + ca;
            const float4 o4 = *(const float4*)&g_O[ga];
            const float4 g4 = *(const float4*)&g_G[ga];
            float4 a4;
            a4.x = __uint_as_float(f2tf(o4.x*g4.x));
            a4.y = __uint_as_float(f2tf(o4.y*g4.y));
            a4.z = __uint_as_float(f2tf(o4.z*g4.z));
            a4.w = __uint_as_float(f2tf(o4.w*g4.w));
            *(float4*)&sA[ra*36 + ca] = a4;
            const int rb = idx >> 4, cb = (idx & 15) << 2;
            *(float4*)&sB[rb*72 + cb] = *(const float4*)&g_WO[(size_t)(kc+rb)*CIN + n0 + cb];
        }
        __syncthreads();
        #pragma unroll
        for (int ks = 0; ks < 4; ks++) {
            const int k0 = ks*8;
            unsigned ah[2][4];
            #pragma unroll
            for (int mt = 0; mt < 2; mt++) {
                const int mr = wm*32 + mt*16;
                ah[mt][0] = fu(sA[(mr+g  )*36 + k0+tg  ]);
                ah[mt][1] = fu(sA[(mr+g+8)*36 + k0+tg  ]);
                ah[mt][2] = fu(sA[(mr+g  )*36 + k0+tg+4]);
                ah[mt][3] = fu(sA[(mr+g+8)*36 + k0+tg+4]);
            }
            #pragma unroll
            for (int nt = 0; nt < 4; nt++) {
                const int nc = wn*32 + nt*8;
                unsigned bh[2];
                bh[0] = fu(sB[(k0+tg  )*72 + nc + g]);
                bh[1] = fu(sB[(k0+tg+4)*72 + nc + g]);
                #pragma unroll
                for (int mt = 0; mt < 2; mt++)
                    mma8(acc[mt][nt], ah[mt], bh);
            }
        }
    }

    #pragma unroll
    for (int mt = 0; mt < 2; mt++) {
        const int r0 = m0 + wm*32 + mt*16 + g;
        #pragma unroll
        for (int nt = 0; nt < 4; nt++) {
            const int col = n0 + wn*32 + nt*8 + 2*tg;
            *(float2*)&out[(size_t)r0*CIN + col]     = make_float2(acc[mt][nt][0], acc[mt][nt][1]);
            *(float2*)&out[(size_t)(r0+8)*CIN + col] = make_float2(acc[mt][nt][2], acc[mt][nt][3]);
        }
    }
}

// =====================================================================
// launch
// =====================================================================
extern "C" void kernel_launch(void* const* d_in, const int* in_sizes, int n_in,
                              void* d_out, int out_size)
{
    (void)in_sizes; (void)n_in; (void)out_size;
    const float* z    = (const float*)d_in[0];
    const float* mask = (const float*)d_in[1];
    const float* lnw  = (const float*)d_in[2];
    const float* lnb  = (const float*)d_in[3];
    const float* wtri = (const float*)d_in[4];
    const float* wq   = (const float*)d_in[5];
    const float* wk   = (const float*)d_in[6];
    const float* wv   = (const float*)d_in[7];
    const float* wg   = (const float*)d_in[8];
    const float* wo   = (const float*)d_in[9];

    const size_t proj_sh = (size_t)(4*64*20) * sizeof(unsigned);                    // 20480
    const size_t attn_sh = (size_t)(2*64*20) * 4 + (size_t)(64*36 + 64) * 4;        // 19712
    const size_t out_sh  = (size_t)(64*36 + 32*72) * sizeof(float);                 // 18432

    wsplit_kernel<<<(WCOLS*64 + CIN*CIN + 255)/256, 256>>>(wq, wk, wv, wg, wtri, wo);
    ln_split_kernel<<<M_TOT/8, 256>>>(z, lnw, lnb);
    proj_mma_kernel<<<dim3(9, M_TOT/64), 128, proj_sh>>>();
    attn_mma_kernel<<<dim3(NN/64, NN, NH), 128, attn_sh>>>(mask);
    outproj_mma_kernel<<<dim3(2, M_TOT/64), 128, out_sh>>>((float*)d_out);
}

// round 6
// speedup vs baseline: 2.8261x; 1.1136x over previous
#include <cuda_runtime.h>
#include <cuda_bf16.h>
#include <cuda_fp16.h>
#include <math.h>

// ---------------- problem constants ----------------
#define NN   384
#define CIN  128
#define NH   4
#define CH   32
#define M_TOT (NN*NN)                   // 147456
#define MW   (M_TOT/2)
#define QK_SCALE 0.17677669529663687f   // 1/sqrt(32)
#define WCOLS 576                        // 512 proj cols + 4 tri + pad

// ---------------- scratch (device globals; no allocs) ----------------
__device__ unsigned g_Ah[(size_t)M_TOT*64];      // LN(z) bf16x2 hi plane
__device__ unsigned g_Al[(size_t)M_TOT*64];      // lo plane
__device__ unsigned g_Wth[(size_t)WCOLS*64];     // weights^T packed bf16x2 hi
__device__ unsigned g_Wtl[(size_t)WCOLS*64];
__device__ unsigned g_WOt[(size_t)CIN*64];       // wo^T packed half2
__device__ unsigned g_Qph[(size_t)NH*M_TOT*16];  // Q head-major bf16x2 hi/lo
__device__ unsigned g_Qpl[(size_t)NH*M_TOT*16];
__device__ unsigned g_Kph[(size_t)NH*M_TOT*16];
__device__ unsigned g_Kpl[(size_t)NH*M_TOT*16];
__device__ __half   g_Vh16[(size_t)NH*M_TOT*CH]; // V half, [h][m][c]
__device__ unsigned g_Vt [(size_t)NH*CH*MW];     // V^T packed half2 [h][c][m/2]
__device__ float g_G  [(size_t)M_TOT*CIN];       // sigmoid gate
__device__ float g_TRI[(size_t)NH*M_TOT];
__device__ float g_O  [(size_t)M_TOT*CIN];       // attn out, m-major

// ---------------- helpers ----------------
__device__ __forceinline__ unsigned fu(float x) { return __float_as_uint(x); }
__device__ __forceinline__ unsigned pack2h(float a, float b) {
    __half2 t = __floats2half2_rn(a, b);
    return *(unsigned*)&t;
}
__device__ __forceinline__ unsigned packbf(float a, float b) {
    __nv_bfloat162 t = __floats2bfloat162_rn(a, b);
    return *(unsigned*)&t;
}
__device__ __forceinline__ void splitbf2(float a, float b, unsigned& hw, unsigned& lw) {
    __nv_bfloat16 ha = __float2bfloat16_rn(a);
    __nv_bfloat16 hb = __float2bfloat16_rn(b);
    float ra = a - __bfloat162float(ha);
    float rb = b - __bfloat162float(hb);
    __nv_bfloat162 h; h.x = ha; h.y = hb;
    hw = *(unsigned*)&h;
    lw = packbf(ra, rb);
}
// bf16 m16n8k16
__device__ __forceinline__ void mma16(float* d, const unsigned* a, const unsigned* b) {
    asm volatile(
        "mma.sync.aligned.m16n8k16.row.col.f32.bf16.bf16.f32 "
        "{%0,%1,%2,%3},{%4,%5,%6,%7},{%8,%9},{%0,%1,%2,%3};\n"
        : "+f"(d[0]), "+f"(d[1]), "+f"(d[2]), "+f"(d[3])
        : "r"(a[0]), "r"(a[1]), "r"(a[2]), "r"(a[3]), "r"(b[0]), "r"(b[1]));
}
// fp16 m16n8k16
__device__ __forceinline__ void mma16h(float* d, const unsigned* a, const unsigned* b) {
    asm volatile(
        "mma.sync.aligned.m16n8k16.row.col.f32.f16.f16.f32 "
        "{%0,%1,%2,%3},{%4,%5,%6,%7},{%8,%9},{%0,%1,%2,%3};\n"
        : "+f"(d[0]), "+f"(d[1]), "+f"(d[2]), "+f"(d[3])
        : "r"(a[0]), "r"(a[1]), "r"(a[2]), "r"(a[3]), "r"(b[0]), "r"(b[1]));
}

// =====================================================================
// prep 1: LayerNorm + bf16-split pack (1 warp per row)
// =====================================================================
__global__ void __launch_bounds__(256)
ln_split_kernel(const float* __restrict__ z,
                const float* __restrict__ lnw, const float* __restrict__ lnb)
{
    const int row  = blockIdx.x*8 + (threadIdx.x >> 5);
    const int lane = threadIdx.x & 31;
    const float4 v = *(const float4*)(z + (size_t)row*CIN + lane*4);
    float s1 = v.x+v.y+v.z+v.w;
    float s2 = v.x*v.x + v.y*v.y + v.z*v.z + v.w*v.w;
    #pragma unroll
    for (int o = 16; o; o >>= 1) {
        s1 += __shfl_xor_sync(0xffffffffu, s1, o);
        s2 += __shfl_xor_sync(0xffffffffu, s2, o);
    }
    const float mu  = s1 * (1.f/128.f);
    const float var = s2 * (1.f/128.f) - mu*mu;
    const float inv = rsqrtf(var + 1e-5f);
    const float4 w = *(const float4*)(lnw + lane*4);
    const float4 b = *(const float4*)(lnb + lane*4);
    const float y0 = (v.x-mu)*inv*w.x + b.x;
    const float y1 = (v.y-mu)*inv*w.y + b.y;
    const float y2 = (v.z-mu)*inv*w.z + b.z;
    const float y3 = (v.w-mu)*inv*w.w + b.w;
    unsigned h0,l0,h1,l1;
    splitbf2(y0,y1,h0,l0);
    splitbf2(y2,y3,h1,l1);
    const size_t base = (size_t)row*64 + lane*2;
    g_Ah[base] = h0; g_Ah[base+1] = h1;
    g_Al[base] = l0; g_Al[base+1] = l1;
}

// =====================================================================
// prep 2: weights -> transposed packed bf16 planes; wo -> packed half2
// =====================================================================
__global__ void __launch_bounds__(256)
wsplit_kernel(const float* __restrict__ wq, const float* __restrict__ wk,
              const float* __restrict__ wv, const float* __restrict__ wg,
              const float* __restrict__ wtri, const float* __restrict__ wo)
{
    const int idx = blockIdx.x*256 + threadIdx.x;
    if (idx < WCOLS*64) {
        const int n = idx >> 6, kw = idx & 63;
        const int k0 = kw*2;
        float v0, v1;
        if      (n < 128) { v0 = wq[k0*128 + n];          v1 = wq[(k0+1)*128 + n]; }
        else if (n < 256) { v0 = wk[k0*128 + n-128];      v1 = wk[(k0+1)*128 + n-128]; }
        else if (n < 384) { v0 = wv[k0*128 + n-256];      v1 = wv[(k0+1)*128 + n-256]; }
        else if (n < 512) { v0 = wg[k0*128 + n-384];      v1 = wg[(k0+1)*128 + n-384]; }
        else if (n < 516) { v0 = wtri[k0*4 + n-512];      v1 = wtri[(k0+1)*4 + n-512]; }
        else              { v0 = 0.f; v1 = 0.f; }
        unsigned hw, lw; splitbf2(v0, v1, hw, lw);
        g_Wth[idx] = hw; g_Wtl[idx] = lw;
    } else if (idx < WCOLS*64 + CIN*64) {
        const int j = idx - WCOLS*64;
        const int n = j >> 6, kw = j & 63;
        g_WOt[j] = pack2h(wo[(2*kw)*128 + n], wo[(2*kw+1)*128 + n]);
    }
}

// =====================================================================
// GEMM 1: C[M,576] = LN(z) @ W, split-bf16 (3 x m16n8k16).
// =====================================================================
__global__ void __launch_bounds__(128, 4)
proj_mma_kernel()
{
    extern __shared__ unsigned shp[];
    unsigned* sAh = shp;                // [64][20] words
    unsigned* sAl = sAh + 64*20;
    unsigned* sBh = sAl + 64*20;
    unsigned* sBl = sBh + 64*20;

    const int tid  = threadIdx.x;
    const int warp = tid >> 5, lane = tid & 31;
    const int g = lane >> 2, tg = lane & 3;
    const int wm = warp >> 1, wn = warp & 1;
    const int ntb = blockIdx.x;            // 0..8
    const int m0  = blockIdx.y * 64;
    const int n0  = ntb * 64;
    const int ntmax = (ntb == 8) ? ((wn == 0) ? 1 : 0) : 4;

    float acc[2][4][4];
    #pragma unroll
    for (int a = 0; a < 2; a++)
        #pragma unroll
        for (int b = 0; b < 4; b++)
            #pragma unroll
            for (int c = 0; c < 4; c++) acc[a][b][c] = 0.f;

    for (int kc = 0; kc < 128; kc += 32) {
        const int kw0 = kc >> 1;
        __syncthreads();
        for (int idx = tid; idx < 256; idx += 128) {
            const int r = idx >> 2, w4 = (idx & 3) << 2;
            *(uint4*)&sAh[r*20 + w4] = *(const uint4*)&g_Ah[(size_t)(m0+r)*64 + kw0 + w4];
            *(uint4*)&sAl[r*20 + w4] = *(const uint4*)&g_Al[(size_t)(m0+r)*64 + kw0 + w4];
            *(uint4*)&sBh[r*20 + w4] = *(const uint4*)&g_Wth[(size_t)(n0+r)*64 + kw0 + w4];
            *(uint4*)&sBl[r*20 + w4] = *(const uint4*)&g_Wtl[(size_t)(n0+r)*64 + kw0 + w4];
        }
        __syncthreads();
        #pragma unroll
        for (int sub = 0; sub < 2; sub++) {
            const int w0 = sub*8;
            unsigned ah[2][4], al[2][4];
            #pragma unroll
            for (int mt = 0; mt < 2; mt++) {
                const int mr = wm*32 + mt*16;
                ah[mt][0] = sAh[(mr+g  )*20 + w0+tg  ];
                ah[mt][1] = sAh[(mr+g+8)*20 + w0+tg  ];
                ah[mt][2] = sAh[(mr+g  )*20 + w0+tg+4];
                ah[mt][3] = sAh[(mr+g+8)*20 + w0+tg+4];
                al[mt][0] = sAl[(mr+g  )*20 + w0+tg  ];
                al[mt][1] = sAl[(mr+g+8)*20 + w0+tg  ];
                al[mt][2] = sAl[(mr+g  )*20 + w0+tg+4];
                al[mt][3] = sAl[(mr+g+8)*20 + w0+tg+4];
            }
            for (int nt = 0; nt < ntmax; nt++) {
                const int nc = wn*32 + nt*8 + g;
                unsigned bh[2], bl[2];
                bh[0] = sBh[nc*20 + w0+tg  ];
                bh[1] = sBh[nc*20 + w0+tg+4];
                bl[0] = sBl[nc*20 + w0+tg  ];
                bl[1] = sBl[nc*20 + w0+tg+4];
                #pragma unroll
                for (int mt = 0; mt < 2; mt++) {
                    mma16(acc[mt][nt], ah[mt], bh);
                    mma16(acc[mt][nt], ah[mt], bl);
                    mma16(acc[mt][nt], al[mt], bh);
                }
            }
        }
    }

    // ---- epilogues ----
    if (ntb < 8) {
        const int cbase = (ntb & 1)*64;
        const int kind  = ntb >> 1;          // 0=Q 1=K 2=V 3=G
        #pragma unroll
        for (int mt = 0; mt < 2; mt++) {
            const int r0 = m0 + wm*32 + mt*16 + g;
            #pragma unroll
            for (int nt = 0; nt < 4; nt++) {
                const int col = cbase + wn*32 + nt*8 + 2*tg;
                const int h = col >> 5, c0 = col & 31;
                float v0 = acc[mt][nt][0], v1 = acc[mt][nt][1];
                float v2 = acc[mt][nt][2], v3 = acc[mt][nt][3];
                if (kind == 0 || kind == 1) {
                    if (kind == 0) { v0*=QK_SCALE; v1*=QK_SCALE; v2*=QK_SCALE; v3*=QK_SCALE; }
                    unsigned* dh = (kind == 0) ? g_Qph : g_Kph;
                    unsigned* dl = (kind == 0) ? g_Qpl : g_Kpl;
                    const size_t w0i = ((size_t)h*M_TOT + r0)*16 + (c0>>1);
                    const size_t w1i = ((size_t)h*M_TOT + r0 + 8)*16 + (c0>>1);
                    unsigned hw, lw;
                    splitbf2(v0, v1, hw, lw); dh[w0i] = hw; dl[w0i] = lw;
                    splitbf2(v2, v3, hw, lw); dh[w1i] = hw; dl[w1i] = lw;
                } else if (kind == 2) {
                    const size_t hm0 = ((size_t)h*M_TOT + r0)*CH + c0;
                    const size_t hm1 = ((size_t)h*M_TOT + r0 + 8)*CH + c0;
                    *(__half2*)&g_Vh16[hm0] = __floats2half2_rn(v0, v1);
                    *(__half2*)&g_Vh16[hm1] = __floats2half2_rn(v2, v3);
                } else {
                    *(float2*)&g_G[(size_t)r0*CIN + col] =
                        make_float2(1.f/(1.f+__expf(-v0)), 1.f/(1.f+__expf(-v1)));
                    *(float2*)&g_G[(size_t)(r0+8)*CIN + col] =
                        make_float2(1.f/(1.f+__expf(-v2)), 1.f/(1.f+__expf(-v3)));
                }
            }
        }
    } else if (wn == 0 && tg < 2) {
        #pragma unroll
        for (int mt = 0; mt < 2; mt++) {
            const int r0 = m0 + wm*32 + mt*16 + g;
            const int c0 = 2*tg;
            g_TRI[(size_t)c0*M_TOT     + r0]   = acc[mt][0][0];
            g_TRI[(size_t)(c0+1)*M_TOT + r0]   = acc[mt][0][1];
            g_TRI[(size_t)c0*M_TOT     + r0+8] = acc[mt][0][2];
            g_TRI[(size_t)(c0+1)*M_TOT + r0+8] = acc[mt][0][3];
        }
    }
}

// =====================================================================
// prep 3: V -> transposed packed half2 planes [h][c][m/2]
// =====================================================================
__global__ void __launch_bounds__(128)
vt_pack_kernel()
{
    __shared__ __half tile[64][32];
    const int h  = blockIdx.x;
    const int mb = blockIdx.y;           // 0..2303
    const int tid = threadIdx.x;
    const size_t base = ((size_t)h*M_TOT + (size_t)mb*64)*CH;
    for (int t = tid; t < 256; t += 128) {
        const int r = t >> 2, cw = (t & 3) << 3;
        *(uint4*)&tile[r][cw] = *(const uint4*)&g_Vh16[base + (size_t)r*CH + cw];
    }
    __syncthreads();
    const int c = tid >> 2, mp0 = (tid & 3) << 3;
    const size_t ob = ((size_t)(h*CH + c))*MW + mb*32 + mp0;
    unsigned w[8];
    #pragma unroll
    for (int j = 0; j < 8; j++) {
        __half2 t2; t2.x = tile[2*(mp0+j)][c]; t2.y = tile[2*(mp0+j)+1][c];
        w[j] = *(unsigned*)&t2;
    }
    *(uint4*)&g_Vt[ob]   = make_uint4(w[0], w[1], w[2], w[3]);
    *(uint4*)&g_Vt[ob+4] = make_uint4(w[4], w[5], w[6], w[7]);
}

// =====================================================================
// flash attention: S = split-bf16 (3 x m16n8k16), PV = fp16 m16n8k16.
// P fragments packed DIRECTLY from S accumulators (FA-2 layout trick).
// smem = 15.1 KB.
// =====================================================================
__global__ void __launch_bounds__(128, 5)
attn_mma_kernel(const float* __restrict__ mask)
{
    extern __shared__ unsigned sha[];
    unsigned* sKh = sha;            // [64][20] words
    unsigned* sKl = sKh + 64*20;    // [64][20]
    unsigned* sVt = sKl + 64*20;    // [32 c][36] words (V^T packed half2)
    float*    sMb = (float*)(sVt + 32*36);   // [64]

    const int tid  = threadIdx.x;
    const int warp = tid >> 5, lane = tid & 31;
    const int g = lane >> 2, tg = lane & 3;
    const int q0 = blockIdx.x * 64;
    const int i  = blockIdx.y;
    const int h  = blockIdx.z;
    const size_t rowbase = (size_t)i * NN;
    const size_t hbase   = (size_t)h * M_TOT;

    // ---- stage Q tile through K buffers, keep fragments in regs ----
    for (int idx = tid; idx < 256; idx += 128) {
        const int r = idx >> 2, w4 = (idx & 3) << 2;
        const size_t gw = (hbase + rowbase + q0 + r)*16 + w4;
        *(uint4*)&sKh[r*20 + w4] = *(const uint4*)&g_Qph[gw];
        *(uint4*)&sKl[r*20 + w4] = *(const uint4*)&g_Qpl[gw];
    }
    __syncthreads();
    unsigned qh[2][4], ql[2][4];
    {
        const int mr = warp*16;
        #pragma unroll
        for (int ck = 0; ck < 2; ck++) {
            const int w0 = ck*8;
            qh[ck][0] = sKh[(mr+g  )*20 + w0+tg  ];
            qh[ck][1] = sKh[(mr+g+8)*20 + w0+tg  ];
            qh[ck][2] = sKh[(mr+g  )*20 + w0+tg+4];
            qh[ck][3] = sKh[(mr+g+8)*20 + w0+tg+4];
            ql[ck][0] = sKl[(mr+g  )*20 + w0+tg  ];
            ql[ck][1] = sKl[(mr+g+8)*20 + w0+tg  ];
            ql[ck][2] = sKl[(mr+g  )*20 + w0+tg+4];
            ql[ck][3] = sKl[(mr+g+8)*20 + w0+tg+4];
        }
    }

    const int qrow = q0 + warp*16 + g;
    const float* triP0 = g_TRI + hbase + (size_t)qrow*NN;
    const float* triP1 = triP0 + (size_t)8*NN;

    float m0v = -1e30f, m1v = -1e30f, l0 = 0.f, l1 = 0.f;
    float oacc[4][4];
    #pragma unroll
    for (int a = 0; a < 4; a++)
        #pragma unroll
        for (int b = 0; b < 4; b++) oacc[a][b] = 0.f;

    for (int kb = 0; kb < NN; kb += 64) {
        __syncthreads();
        for (int idx = tid; idx < 256; idx += 128) {
            const int r = idx >> 2, w4 = (idx & 3) << 2;
            const size_t gw = (hbase + rowbase + kb + r)*16 + w4;
            *(uint4*)&sKh[r*20 + w4] = *(const uint4*)&g_Kph[gw];
            *(uint4*)&sKl[r*20 + w4] = *(const uint4*)&g_Kpl[gw];
        }
        {
            const size_t mw0 = (rowbase + kb) >> 1;
            for (int idx = tid; idx < 256; idx += 128) {
                const int r = idx >> 3, w4 = (idx & 7) << 2;
                *(uint4*)&sVt[r*36 + w4] = *(const uint4*)&g_Vt[((size_t)(h*CH + r))*MW + mw0 + w4];
            }
        }
        if (tid < 64) sMb[tid] = 1e9f * (mask[rowbase + kb + tid] - 1.f);
        __syncthreads();

        // ---- S = Q K^T  (split-bf16) ----
        float s[8][4];
        #pragma unroll
        for (int a = 0; a < 8; a++)
            #pragma unroll
            for (int b = 0; b < 4; b++) s[a][b] = 0.f;

        #pragma unroll
        for (int ck = 0; ck < 2; ck++) {
            const int w0 = ck*8;
            #pragma unroll
            for (int nt = 0; nt < 8; nt++) {
                const int nr = (nt*8+g)*20;
                unsigned bh[2], bl[2];
                bh[0] = sKh[nr + w0+tg  ];
                bh[1] = sKh[nr + w0+tg+4];
                bl[0] = sKl[nr + w0+tg  ];
                bl[1] = sKl[nr + w0+tg+4];
                mma16(s[nt], qh[ck], bh);
                mma16(s[nt], qh[ck], bl);
                mma16(s[nt], ql[ck], bh);
            }
        }

        // ---- bias + online softmax ----
        float cm0 = -1e30f, cm1 = -1e30f;
        #pragma unroll
        for (int nt = 0; nt < 8; nt++) {
            const int col = nt*8 + 2*tg;
            const float2 t0 = *(const float2*)&triP0[kb + col];
            const float2 t1 = *(const float2*)&triP1[kb + col];
            const float mb0 = sMb[col], mb1 = sMb[col+1];
            s[nt][0] += t0.x + mb0; s[nt][1] += t0.y + mb1;
            s[nt][2] += t1.x + mb0; s[nt][3] += t1.y + mb1;
            cm0 = fmaxf(cm0, fmaxf(s[nt][0], s[nt][1]));
            cm1 = fmaxf(cm1, fmaxf(s[nt][2], s[nt][3]));
        }
        cm0 = fmaxf(cm0, __shfl_xor_sync(0xffffffffu, cm0, 1));
        cm0 = fmaxf(cm0, __shfl_xor_sync(0xffffffffu, cm0, 2));
        cm1 = fmaxf(cm1, __shfl_xor_sync(0xffffffffu, cm1, 1));
        cm1 = fmaxf(cm1, __shfl_xor_sync(0xffffffffu, cm1, 2));
        const float nm0 = fmaxf(m0v, cm0), nm1 = fmaxf(m1v, cm1);
        const float sc0 = __expf(m0v - nm0), sc1 = __expf(m1v - nm1);
        m0v = nm0; m1v = nm1;

        float sum0 = 0.f, sum1 = 0.f;
        #pragma unroll
        for (int nt = 0; nt < 8; nt++) {
            const float p0 = __expf(s[nt][0]-nm0), p1 = __expf(s[nt][1]-nm0);
            const float p2 = __expf(s[nt][2]-nm1), p3 = __expf(s[nt][3]-nm1);
            sum0 += p0 + p1; sum1 += p2 + p3;
            s[nt][0] = p0; s[nt][1] = p1; s[nt][2] = p2; s[nt][3] = p3;
        }
        sum0 += __shfl_xor_sync(0xffffffffu, sum0, 1);
        sum0 += __shfl_xor_sync(0xffffffffu, sum0, 2);
        sum1 += __shfl_xor_sync(0xffffffffu, sum1, 1);
        sum1 += __shfl_xor_sync(0xffffffffu, sum1, 2);
        l0 = l0*sc0 + sum0; l1 = l1*sc1 + sum1;
        #pragma unroll
        for (int nt = 0; nt < 4; nt++) {
            oacc[nt][0] *= sc0; oacc[nt][1] *= sc0;
            oacc[nt][2] *= sc1; oacc[nt][3] *= sc1;
        }

        // ---- O += P V  (fp16): A-frag packed directly from S accum ----
        #pragma unroll
        for (int j = 0; j < 4; j++) {        // 16-key chunks
            unsigned a[4];
            a[0] = pack2h(s[2*j  ][0], s[2*j  ][1]);
            a[1] = pack2h(s[2*j  ][2], s[2*j  ][3]);
            a[2] = pack2h(s[2*j+1][0], s[2*j+1][1]);
            a[3] = pack2h(s[2*j+1][2], s[2*j+1][3]);
            #pragma unroll
            for (int nt = 0; nt < 4; nt++) {
                const int cr = (nt*8 + g)*36;
                unsigned b[2];
                b[0] = sVt[cr + j*8 + tg    ];
                b[1] = sVt[cr + j*8 + tg + 4];
                mma16h(oacc[nt], a, b);
            }
        }
    }

    const float inv0 = 1.f/l0, inv1 = 1.f/l1;
    const size_t ob0 = (rowbase + qrow)*CIN + h*CH;
    const size_t ob1 = (rowbase + qrow + 8)*CIN + h*CH;
    #pragma unroll
    for (int nt = 0; nt < 4; nt++) {
        const int col = nt*8 + 2*tg;
        *(float2*)&g_O[ob0 + col] = make_float2(oacc[nt][0]*inv0, oacc[nt][1]*inv0);
        *(float2*)&g_O[ob1 + col] = make_float2(oacc[nt][2]*inv1, oacc[nt][3]*inv1);
    }
}

// =====================================================================
// GEMM 3: out = (O*G) @ wo, fp16 m16n8k16, kc=32 chunks.
// =====================================================================
__global__ void __launch_bounds__(128, 6)
outproj_mma_kernel(float* __restrict__ out)
{
    extern __shared__ unsigned sho[];
    unsigned* sA = sho;             // [64 m][20] words (16 used)
    unsigned* sB = sA + 64*20;      // [64 n][20]

    const int tid  = threadIdx.x;
    const int warp = tid >> 5, lane = tid & 31;
    const int g = lane >> 2, tg = lane & 3;
    const int wm = warp >> 1, wn = warp & 1;
    const int n0 = blockIdx.x * 64;
    const int m0 = blockIdx.y * 64;

    float acc[2][4][4];
    #pragma unroll
    for (int a = 0; a < 2; a++)
        #pragma unroll
        for (int b = 0; b < 4; b++)
            #pragma unroll
            for (int c = 0; c < 4; c++) acc[a][b][c] = 0.f;

    for (int kc = 0; kc < 128; kc += 32) {
        __syncthreads();
        for (int idx = tid; idx < 512; idx += 128) {
            const int ra = idx >> 3, ca = (idx & 7) << 2;   // 4 floats -> 2 words
            const size_t ga = (size_t)(m0+ra)*CIN + kc + ca;
            const float4 o4 = *(const float4*)&g_O[ga];
            const float4 g4 = *(const float4*)&g_G[ga];
            sA[ra*20 + (ca>>1)    ] = pack2h(o4.x*g4.x, o4.y*g4.y);
            sA[ra*20 + (ca>>1) + 1] = pack2h(o4.z*g4.z, o4.w*g4.w);
        }
        for (int idx = tid; idx < 256; idx += 128) {
            const int r = idx >> 2, w4 = (idx & 3) << 2;
            *(uint4*)&sB[r*20 + w4] = *(const uint4*)&g_WOt[(size_t)(n0+r)*64 + (kc>>1) + w4];
        }
        __syncthreads();
        #pragma unroll
        for (int ck = 0; ck < 2; ck++) {
            const int w0 = ck*8;
            unsigned ah[2][4];
            #pragma unroll
            for (int mt = 0; mt < 2; mt++) {
                const int mr = wm*32 + mt*16;
                ah[mt][0] = sA[(mr+g  )*20 + w0+tg  ];
                ah[mt][1] = sA[(mr+g+8)*20 + w0+tg  ];
                ah[mt][2] = sA[(mr+g  )*20 + w0+tg+4];
                ah[mt][3] = sA[(mr+g+8)*20 + w0+tg+4];
            }
            #pragma unroll
            for (int nt = 0; nt < 4; nt++) {
                const int nc = wn*32 + nt*8 + g;
                unsigned b[2];
                b[0] = sB[nc*20 + w0+tg  ];
                b[1] = sB[nc*20 + w0+tg+4];
                #pragma unroll
                for (int mt = 0; mt < 2; mt++)
                    mma16h(acc[mt][nt], ah[mt], b);
            }
        }
    }

    #pragma unroll
    for (int mt = 0; mt < 2; mt++) {
        const int r0 = m0 + wm*32 + mt*16 + g;
        #pragma unroll
        for (int nt = 0; nt < 4; nt++) {
            const int col = n0 + wn*32 + nt*8 + 2*tg;
            *(float2*)&out[(size_t)r0*CIN + col]     = make_float2(acc[mt][nt][0], acc[mt][nt][1]);
            *(float2*)&out[(size_t)(r0+8)*CIN + col] = make_float2(acc[mt][nt][2], acc[mt][nt][3]);
        }
    }
}

// =====================================================================
// launch
// =====================================================================
extern "C" void kernel_launch(void* const* d_in, const int* in_sizes, int n_in,
                              void* d_out, int out_size)
{
    (void)in_sizes; (void)n_in; (void)out_size;
    const float* z    = (const float*)d_in[0];
    const float* mask = (const float*)d_in[1];
    const float* lnw  = (const float*)d_in[2];
    const float* lnb  = (const float*)d_in[3];
    const float* wtri = (const float*)d_in[4];
    const float* wq   = (const float*)d_in[5];
    const float* wk   = (const float*)d_in[6];
    const float* wv   = (const float*)d_in[7];
    const float* wg   = (const float*)d_in[8];
    const float* wo   = (const float*)d_in[9];

    const size_t proj_sh = (size_t)(4*64*20) * 4;                    // 20480
    const size_t attn_sh = (size_t)(2*64*20 + 32*36) * 4 + 64*4;     // 15104
    const size_t out_sh  = (size_t)(2*64*20) * 4;                    // 10240

    wsplit_kernel<<<(WCOLS*64 + CIN*64 + 255)/256, 256>>>(wq, wk, wv, wg, wtri, wo);
    ln_split_kernel<<<M_TOT/8, 256>>>(z, lnw, lnb);
    proj_mma_kernel<<<dim3(9, M_TOT/64), 128, proj_sh>>>();
    vt_pack_kernel<<<dim3(NH, M_TOT/64), 128>>>();
    attn_mma_kernel<<<dim3(NN/64, NN, NH), 128, attn_sh>>>(mask);
    outproj_mma_kernel<<<dim3(2, M_TOT/64), 128, out_sh>>>((float*)d_out);
}

// round 7
// speedup vs baseline: 2.9227x; 1.0342x over previous
#include <cuda_runtime.h>
#include <cuda_bf16.h>
#include <cuda_fp16.h>
#include <math.h>

// ---------------- problem constants ----------------
#define NN   384
#define CIN  128
#define NH   4
#define CH   32
#define M_TOT (NN*NN)                   // 147456
#define MW   (M_TOT/2)
#define QK_SCALE 0.17677669529663687f   // 1/sqrt(32)
#define WCOLS 576                        // 512 proj cols + 4 tri + pad

// ---------------- scratch (device globals; no allocs) ----------------
__device__ unsigned g_Ah[(size_t)M_TOT*64];      // LN(z) bf16x2 hi plane
__device__ unsigned g_Al[(size_t)M_TOT*64];      // lo plane
__device__ unsigned g_Wth[(size_t)WCOLS*64];     // weights^T packed bf16x2 hi
__device__ unsigned g_Wtl[(size_t)WCOLS*64];
__device__ unsigned g_WOt[(size_t)CIN*64];       // wo^T packed half2
__device__ unsigned g_Qph[(size_t)NH*M_TOT*16];  // Q head-major bf16x2 hi/lo
__device__ unsigned g_Qpl[(size_t)NH*M_TOT*16];
__device__ unsigned g_Kph[(size_t)NH*M_TOT*16];
__device__ unsigned g_Kpl[(size_t)NH*M_TOT*16];
__device__ __half   g_Vh16[(size_t)NH*M_TOT*CH]; // V half, [h][m][c]
__device__ unsigned g_Vt [(size_t)NH*CH*MW];     // V^T packed half2 [h][c][m/2]
__device__ float g_G  [(size_t)M_TOT*CIN];       // sigmoid gate
__device__ float g_TRI[(size_t)NH*M_TOT];
__device__ float g_O  [(size_t)M_TOT*CIN];       // attn out, m-major

// ---------------- helpers ----------------
__device__ __forceinline__ unsigned pack2h(float a, float b) {
    __half2 t = __floats2half2_rn(a, b);
    return *(unsigned*)&t;
}
__device__ __forceinline__ unsigned packbf(float a, float b) {
    __nv_bfloat162 t = __floats2bfloat162_rn(a, b);
    return *(unsigned*)&t;
}
__device__ __forceinline__ void splitbf2(float a, float b, unsigned& hw, unsigned& lw) {
    __nv_bfloat16 ha = __float2bfloat16_rn(a);
    __nv_bfloat16 hb = __float2bfloat16_rn(b);
    float ra = a - __bfloat162float(ha);
    float rb = b - __bfloat162float(hb);
    __nv_bfloat162 h; h.x = ha; h.y = hb;
    hw = *(unsigned*)&h;
    lw = packbf(ra, rb);
}
__device__ __forceinline__ unsigned f2tf(float x) {
    unsigned u; asm("cvt.rna.tf32.f32 %0, %1;" : "=r"(u) : "f"(x)); return u;
}
__device__ __forceinline__ unsigned sm_u32(const void* p) {
    return (unsigned)__cvta_generic_to_shared(p);
}
__device__ __forceinline__ void ldsm4(unsigned* r, unsigned addr) {
    asm volatile("ldmatrix.sync.aligned.m8n8.x4.shared.b16 {%0,%1,%2,%3}, [%4];"
        : "=r"(r[0]), "=r"(r[1]), "=r"(r[2]), "=r"(r[3]) : "r"(addr));
}
// bf16 m16n8k16
__device__ __forceinline__ void mma16(float* d, const unsigned* a, const unsigned* b) {
    asm volatile(
        "mma.sync.aligned.m16n8k16.row.col.f32.bf16.bf16.f32 "
        "{%0,%1,%2,%3},{%4,%5,%6,%7},{%8,%9},{%0,%1,%2,%3};\n"
        : "+f"(d[0]), "+f"(d[1]), "+f"(d[2]), "+f"(d[3])
        : "r"(a[0]), "r"(a[1]), "r"(a[2]), "r"(a[3]), "r"(b[0]), "r"(b[1]));
}
// fp16 m16n8k16
__device__ __forceinline__ void mma16h(float* d, const unsigned* a, const unsigned* b) {
    asm volatile(
        "mma.sync.aligned.m16n8k16.row.col.f32.f16.f16.f32 "
        "{%0,%1,%2,%3},{%4,%5,%6,%7},{%8,%9},{%0,%1,%2,%3};\n"
        : "+f"(d[0]), "+f"(d[1]), "+f"(d[2]), "+f"(d[3])
        : "r"(a[0]), "r"(a[1]), "r"(a[2]), "r"(a[3]), "r"(b[0]), "r"(b[1]));
}

// =====================================================================
// prep 1: LayerNorm + bf16-split pack (1 warp per row)
// =====================================================================
__global__ void __launch_bounds__(256)
ln_split_kernel(const float* __restrict__ z,
                const float* __restrict__ lnw, const float* __restrict__ lnb)
{
    const int row  = blockIdx.x*8 + (threadIdx.x >> 5);
    const int lane = threadIdx.x & 31;
    const float4 v = *(const float4*)(z + (size_t)row*CIN + lane*4);
    float s1 = v.x+v.y+v.z+v.w;
    float s2 = v.x*v.x + v.y*v.y + v.z*v.z + v.w*v.w;
    #pragma unroll
    for (int o = 16; o; o >>= 1) {
        s1 += __shfl_xor_sync(0xffffffffu, s1, o);
        s2 += __shfl_xor_sync(0xffffffffu, s2, o);
    }
    const float mu  = s1 * (1.f/128.f);
    const float var = s2 * (1.f/128.f) - mu*mu;
    const float inv = rsqrtf(var + 1e-5f);
    const float4 w = *(const float4*)(lnw + lane*4);
    const float4 b = *(const float4*)(lnb + lane*4);
    const float y0 = (v.x-mu)*inv*w.x + b.x;
    const float y1 = (v.y-mu)*inv*w.y + b.y;
    const float y2 = (v.z-mu)*inv*w.z + b.z;
    const float y3 = (v.w-mu)*inv*w.w + b.w;
    unsigned h0,l0,h1,l1;
    splitbf2(y0,y1,h0,l0);
    splitbf2(y2,y3,h1,l1);
    const size_t base = (size_t)row*64 + lane*2;
    g_Ah[base] = h0; g_Ah[base+1] = h1;
    g_Al[base] = l0; g_Al[base+1] = l1;
}

// =====================================================================
// prep 2: weights -> transposed packed bf16 planes; wo -> packed half2
// =====================================================================
__global__ void __launch_bounds__(256)
wsplit_kernel(const float* __restrict__ wq, const float* __restrict__ wk,
              const float* __restrict__ wv, const float* __restrict__ wg,
              const float* __restrict__ wtri, const float* __restrict__ wo)
{
    const int idx = blockIdx.x*256 + threadIdx.x;
    if (idx < WCOLS*64) {
        const int n = idx >> 6, kw = idx & 63;
        const int k0 = kw*2;
        float v0, v1;
        if      (n < 128) { v0 = wq[k0*128 + n];          v1 = wq[(k0+1)*128 + n]; }
        else if (n < 256) { v0 = wk[k0*128 + n-128];      v1 = wk[(k0+1)*128 + n-128]; }
        else if (n < 384) { v0 = wv[k0*128 + n-256];      v1 = wv[(k0+1)*128 + n-256]; }
        else if (n < 512) { v0 = wg[k0*128 + n-384];      v1 = wg[(k0+1)*128 + n-384]; }
        else if (n < 516) { v0 = wtri[k0*4 + n-512];      v1 = wtri[(k0+1)*4 + n-512]; }
        else              { v0 = 0.f; v1 = 0.f; }
        unsigned hw, lw; splitbf2(v0, v1, hw, lw);
        g_Wth[idx] = hw; g_Wtl[idx] = lw;
    } else if (idx < WCOLS*64 + CIN*64) {
        const int j = idx - WCOLS*64;
        const int n = j >> 6, kw = j & 63;
        g_WOt[j] = pack2h(wo[(2*kw)*128 + n], wo[(2*kw+1)*128 + n]);
    }
}

// =====================================================================
// GEMM 1: C[M,576] = LN(z) @ W, split-bf16 (3 x m16n8k16), ldmatrix loads.
// =====================================================================
__global__ void __launch_bounds__(128, 4)
proj_mma_kernel()
{
    extern __shared__ unsigned shp[];
    unsigned* sAh = shp;                // [64][20] words
    unsigned* sAl = sAh + 64*20;
    unsigned* sBh = sAl + 64*20;
    unsigned* sBl = sBh + 64*20;

    const int tid  = threadIdx.x;
    const int warp = tid >> 5, lane = tid & 31;
    const int g = lane >> 2, tg = lane & 3;
    const int wm = warp >> 1, wn = warp & 1;
    const int ntb = blockIdx.x;            // 0..8
    const int m0  = blockIdx.y * 64;
    const int n0  = ntb * 64;

    const unsigned aAh = sm_u32(sAh), aAl = sm_u32(sAl);
    const unsigned aBh = sm_u32(sBh), aBl = sm_u32(sBl);
    // ldmatrix lane geometry
    const int arow = ((lane>>3)&1)*8 + (lane&7);   // A: m1/m3 rows +8
    const int awof = (lane>>4)*4;                   // A: m2/m3 words +4
    const int krow = ((lane>>4)&1)*8 + (lane&7);    // B: m2/m3 rows +8
    const int kwof = ((lane>>3)&1)*4;               // B: m1/m3 words +4

    float acc[2][4][4];
    #pragma unroll
    for (int a = 0; a < 2; a++)
        #pragma unroll
        for (int b = 0; b < 4; b++)
            #pragma unroll
            for (int c = 0; c < 4; c++) acc[a][b][c] = 0.f;

    for (int kc = 0; kc < 128; kc += 32) {
        const int kw0 = kc >> 1;
        __syncthreads();
        for (int idx = tid; idx < 256; idx += 128) {
            const int r = idx >> 2, w4 = (idx & 3) << 2;
            *(uint4*)&sAh[r*20 + w4] = *(const uint4*)&g_Ah[(size_t)(m0+r)*64 + kw0 + w4];
            *(uint4*)&sAl[r*20 + w4] = *(const uint4*)&g_Al[(size_t)(m0+r)*64 + kw0 + w4];
            *(uint4*)&sBh[r*20 + w4] = *(const uint4*)&g_Wth[(size_t)(n0+r)*64 + kw0 + w4];
            *(uint4*)&sBl[r*20 + w4] = *(const uint4*)&g_Wtl[(size_t)(n0+r)*64 + kw0 + w4];
        }
        __syncthreads();
        #pragma unroll
        for (int sub = 0; sub < 2; sub++) {
            const int w0 = sub*8;
            unsigned ah[2][4], al[2][4];
            #pragma unroll
            for (int mt = 0; mt < 2; mt++) {
                const unsigned offa = ((wm*32 + mt*16 + arow)*20 + w0 + awof) << 2;
                ldsm4(ah[mt], aAh + offa);
                ldsm4(al[mt], aAl + offa);
            }
            #pragma unroll
            for (int p = 0; p < 2; p++) {
                const unsigned offb = ((wn*32 + p*16 + krow)*20 + w0 + kwof) << 2;
                unsigned bh[4], bl[4];
                ldsm4(bh, aBh + offb);
                ldsm4(bl, aBl + offb);
                #pragma unroll
                for (int mt = 0; mt < 2; mt++) {
                    mma16(acc[mt][2*p],   ah[mt], bh);
                    mma16(acc[mt][2*p],   ah[mt], bl);
                    mma16(acc[mt][2*p],   al[mt], bh);
                    mma16(acc[mt][2*p+1], ah[mt], bh+2);
                    mma16(acc[mt][2*p+1], ah[mt], bl+2);
                    mma16(acc[mt][2*p+1], al[mt], bh+2);
                }
            }
        }
    }

    // ---- epilogues ----
    if (ntb < 8) {
        const int cbase = (ntb & 1)*64;
        const int kind  = ntb >> 1;          // 0=Q 1=K 2=V 3=G
        #pragma unroll
        for (int mt = 0; mt < 2; mt++) {
            const int r0 = m0 + wm*32 + mt*16 + g;
            #pragma unroll
            for (int nt = 0; nt < 4; nt++) {
                const int col = cbase + wn*32 + nt*8 + 2*tg;
                const int h = col >> 5, c0 = col & 31;
                float v0 = acc[mt][nt][0], v1 = acc[mt][nt][1];
                float v2 = acc[mt][nt][2], v3 = acc[mt][nt][3];
                if (kind == 0 || kind == 1) {
                    if (kind == 0) { v0*=QK_SCALE; v1*=QK_SCALE; v2*=QK_SCALE; v3*=QK_SCALE; }
                    unsigned* dh = (kind == 0) ? g_Qph : g_Kph;
                    unsigned* dl = (kind == 0) ? g_Qpl : g_Kpl;
                    const size_t w0i = ((size_t)h*M_TOT + r0)*16 + (c0>>1);
                    const size_t w1i = ((size_t)h*M_TOT + r0 + 8)*16 + (c0>>1);
                    unsigned hw, lw;
                    splitbf2(v0, v1, hw, lw); dh[w0i] = hw; dl[w0i] = lw;
                    splitbf2(v2, v3, hw, lw); dh[w1i] = hw; dl[w1i] = lw;
                } else if (kind == 2) {
                    const size_t hm0 = ((size_t)h*M_TOT + r0)*CH + c0;
                    const size_t hm1 = ((size_t)h*M_TOT + r0 + 8)*CH + c0;
                    *(__half2*)&g_Vh16[hm0] = __floats2half2_rn(v0, v1);
                    *(__half2*)&g_Vh16[hm1] = __floats2half2_rn(v2, v3);
                } else {
                    *(float2*)&g_G[(size_t)r0*CIN + col] =
                        make_float2(1.f/(1.f+__expf(-v0)), 1.f/(1.f+__expf(-v1)));
                    *(float2*)&g_G[(size_t)(r0+8)*CIN + col] =
                        make_float2(1.f/(1.f+__expf(-v2)), 1.f/(1.f+__expf(-v3)));
                }
            }
        }
    } else if (wn == 0 && tg < 2) {
        #pragma unroll
        for (int mt = 0; mt < 2; mt++) {
            const int r0 = m0 + wm*32 + mt*16 + g;
            const int c0 = 2*tg;
            g_TRI[(size_t)c0*M_TOT     + r0]   = acc[mt][0][0];
            g_TRI[(size_t)(c0+1)*M_TOT + r0]   = acc[mt][0][1];
            g_TRI[(size_t)c0*M_TOT     + r0+8] = acc[mt][0][2];
            g_TRI[(size_t)(c0+1)*M_TOT + r0+8] = acc[mt][0][3];
        }
    }
}

// =====================================================================
// prep 3: V -> transposed packed half2 planes [h][c][m/2]
// =====================================================================
__global__ void __launch_bounds__(128)
vt_pack_kernel()
{
    __shared__ __half tile[64][32];
    const int h  = blockIdx.x;
    const int mb = blockIdx.y;
    const int tid = threadIdx.x;
    const size_t base = ((size_t)h*M_TOT + (size_t)mb*64)*CH;
    for (int t = tid; t < 256; t += 128) {
        const int r = t >> 2, cw = (t & 3) << 3;
        *(uint4*)&tile[r][cw] = *(const uint4*)&g_Vh16[base + (size_t)r*CH + cw];
    }
    __syncthreads();
    const int c = tid >> 2, mp0 = (tid & 3) << 3;
    const size_t ob = ((size_t)(h*CH + c))*MW + mb*32 + mp0;
    unsigned w[8];
    #pragma unroll
    for (int j = 0; j < 8; j++) {
        __half2 t2; t2.x = tile[2*(mp0+j)][c]; t2.y = tile[2*(mp0+j)+1][c];
        w[j] = *(unsigned*)&t2;
    }
    *(uint4*)&g_Vt[ob]   = make_uint4(w[0], w[1], w[2], w[3]);
    *(uint4*)&g_Vt[ob+4] = make_uint4(w[4], w[5], w[6], w[7]);
}

// =====================================================================
// flash attention: S = split-bf16, PV = fp16, ldmatrix operand loads,
// NO online max (scores bounded; mask bias -> exp underflows to 0).
// =====================================================================
__global__ void __launch_bounds__(128, 5)
attn_mma_kernel(const float* __restrict__ mask)
{
    extern __shared__ unsigned sha[];
    unsigned* sKh = sha;            // [64][20] words
    unsigned* sKl = sKh + 64*20;
    unsigned* sVt = sKl + 64*20;    // [32][36] words
    float*    sMb = (float*)(sVt + 32*36);   // [64]

    const int tid  = threadIdx.x;
    const int warp = tid >> 5, lane = tid & 31;
    const int g = lane >> 2, tg = lane & 3;
    const int q0 = blockIdx.x * 64;
    const int i  = blockIdx.y;
    const int h  = blockIdx.z;
    const size_t rowbase = (size_t)i * NN;
    const size_t hbase   = (size_t)h * M_TOT;

    const unsigned aKh = sm_u32(sKh), aKl = sm_u32(sKl), aVt = sm_u32(sVt);
    const int arow = ((lane>>3)&1)*8 + (lane&7);
    const int awof = (lane>>4)*4;
    const int krow = ((lane>>4)&1)*8 + (lane&7);
    const int kwof = ((lane>>3)&1)*4;

    // ---- stage Q tile through K buffers, fragments via ldmatrix ----
    for (int idx = tid; idx < 256; idx += 128) {
        const int r = idx >> 2, w4 = (idx & 3) << 2;
        const size_t gw = (hbase + rowbase + q0 + r)*16 + w4;
        *(uint4*)&sKh[r*20 + w4] = *(const uint4*)&g_Qph[gw];
        *(uint4*)&sKl[r*20 + w4] = *(const uint4*)&g_Qpl[gw];
    }
    __syncthreads();
    unsigned qh[2][4], ql[2][4];
    #pragma unroll
    for (int ck = 0; ck < 2; ck++) {
        const unsigned offq = ((warp*16 + arow)*20 + ck*8 + awof) << 2;
        ldsm4(qh[ck], aKh + offq);
        ldsm4(ql[ck], aKl + offq);
    }

    const int qrow = q0 + warp*16 + g;
    const float* triP0 = g_TRI + hbase + (size_t)qrow*NN;
    const float* triP1 = triP0 + (size_t)8*NN;

    float l0 = 0.f, l1 = 0.f;
    float oacc[4][4];
    #pragma unroll
    for (int a = 0; a < 4; a++)
        #pragma unroll
        for (int b = 0; b < 4; b++) oacc[a][b] = 0.f;

    for (int kb = 0; kb < NN; kb += 64) {
        __syncthreads();
        for (int idx = tid; idx < 256; idx += 128) {
            const int r = idx >> 2, w4 = (idx & 3) << 2;
            const size_t gw = (hbase + rowbase + kb + r)*16 + w4;
            *(uint4*)&sKh[r*20 + w4] = *(const uint4*)&g_Kph[gw];
            *(uint4*)&sKl[r*20 + w4] = *(const uint4*)&g_Kpl[gw];
        }
        {
            const size_t mw0 = (rowbase + kb) >> 1;
            for (int idx = tid; idx < 256; idx += 128) {
                const int r = idx >> 3, w4 = (idx & 7) << 2;
                *(uint4*)&sVt[r*36 + w4] = *(const uint4*)&g_Vt[((size_t)(h*CH + r))*MW + mw0 + w4];
            }
        }
        if (tid < 64) sMb[tid] = 1e9f * (mask[rowbase + kb + tid] - 1.f);
        __syncthreads();

        // ---- S = Q K^T  (split-bf16, ldmatrix B) ----
        float s[8][4];
        #pragma unroll
        for (int a = 0; a < 8; a++)
            #pragma unroll
            for (int b = 0; b < 4; b++) s[a][b] = 0.f;

        #pragma unroll
        for (int ck = 0; ck < 2; ck++) {
            #pragma unroll
            for (int p = 0; p < 4; p++) {
                const unsigned off = ((p*16 + krow)*20 + ck*8 + kwof) << 2;
                unsigned bh[4], bl[4];
                ldsm4(bh, aKh + off);
                ldsm4(bl, aKl + off);
                mma16(s[2*p],   qh[ck], bh);
                mma16(s[2*p],   qh[ck], bl);
                mma16(s[2*p],   ql[ck], bh);
                mma16(s[2*p+1], qh[ck], bh+2);
                mma16(s[2*p+1], qh[ck], bl+2);
                mma16(s[2*p+1], ql[ck], bh+2);
            }
        }

        // ---- bias + exp (no max subtraction; scores bounded) ----
        #pragma unroll
        for (int nt = 0; nt < 8; nt++) {
            const int col = nt*8 + 2*tg;
            const float2 t0 = *(const float2*)&triP0[kb + col];
            const float2 t1 = *(const float2*)&triP1[kb + col];
            const float2 mb = *(const float2*)&sMb[col];
            s[nt][0] = __expf(s[nt][0] + t0.x + mb.x);
            s[nt][1] = __expf(s[nt][1] + t0.y + mb.y);
            s[nt][2] = __expf(s[nt][2] + t1.x + mb.x);
            s[nt][3] = __expf(s[nt][3] + t1.y + mb.y);
            l0 += s[nt][0] + s[nt][1];
            l1 += s[nt][2] + s[nt][3];
        }

        // ---- O += P V  (fp16, ldmatrix B, A packed from S accum) ----
        #pragma unroll
        for (int j = 0; j < 4; j++) {
            unsigned a[4];
            a[0] = pack2h(s[2*j  ][0], s[2*j  ][1]);
            a[1] = pack2h(s[2*j  ][2], s[2*j  ][3]);
            a[2] = pack2h(s[2*j+1][0], s[2*j+1][1]);
            a[3] = pack2h(s[2*j+1][2], s[2*j+1][3]);
            #pragma unroll
            for (int p = 0; p < 2; p++) {
                const unsigned off = ((p*16 + krow)*36 + j*8 + kwof) << 2;
                unsigned b[4];
                ldsm4(b, aVt + off);
                mma16h(oacc[2*p],   a, b);
                mma16h(oacc[2*p+1], a, b+2);
            }
        }
    }

    // final l reduction over the quad (columns)
    l0 += __shfl_xor_sync(0xffffffffu, l0, 1);
    l0 += __shfl_xor_sync(0xffffffffu, l0, 2);
    l1 += __shfl_xor_sync(0xffffffffu, l1, 1);
    l1 += __shfl_xor_sync(0xffffffffu, l1, 2);

    const float inv0 = 1.f/l0, inv1 = 1.f/l1;
    const size_t ob0 = (rowbase + qrow)*CIN + h*CH;
    const size_t ob1 = (rowbase + qrow + 8)*CIN + h*CH;
    #pragma unroll
    for (int nt = 0; nt < 4; nt++) {
        const int col = nt*8 + 2*tg;
        *(float2*)&g_O[ob0 + col] = make_float2(oacc[nt][0]*inv0, oacc[nt][1]*inv0);
        *(float2*)&g_O[ob1 + col] = make_float2(oacc[nt][2]*inv1, oacc[nt][3]*inv1);
    }
}

// =====================================================================
// GEMM 3: out = (O*G) @ wo, fp16 m16n8k16, ldmatrix loads.
// =====================================================================
__global__ void __launch_bounds__(128, 6)
outproj_mma_kernel(float* __restrict__ out)
{
    extern __shared__ unsigned sho[];
    unsigned* sA = sho;             // [64][20] words
    unsigned* sB = sA + 64*20;      // [64][20]

    const int tid  = threadIdx.x;
    const int warp = tid >> 5, lane = tid & 31;
    const int g = lane >> 2, tg = lane & 3;
    const int wm = warp >> 1, wn = warp & 1;
    const int n0 = blockIdx.x * 64;
    const int m0 = blockIdx.y * 64;

    const unsigned aA = sm_u32(sA), aB = sm_u32(sB);
    const int arow = ((lane>>3)&1)*8 + (lane&7);
    const int awof = (lane>>4)*4;
    const int krow = ((lane>>4)&1)*8 + (lane&7);
    const int kwof = ((lane>>3)&1)*4;

    float acc[2][4][4];
    #pragma unroll
    for (int a = 0; a < 2; a++)
        #pragma unroll
        for (int b = 0; b < 4; b++)
            #pragma unroll
            for (int c = 0; c < 4; c++) acc[a][b][c] = 0.f;

    for (int kc = 0; kc < 128; kc += 32) {
        __syncthreads();
        for (int idx = tid; idx < 512; idx += 128) {
            const int ra = idx >> 3, ca = (idx & 7) << 2;
            const size_t ga = (size_t)(m0+ra)*CIN + kc + ca;
            const float4 o4 = *(const float4*)&g_O[ga];
            const float4 g4 = *(const float4*)&g_G[ga];
            sA[ra*20 + (ca>>1)    ] = pack2h(o4.x*g4.x, o4.y*g4.y);
            sA[ra*20 + (ca>>1) + 1] = pack2h(o4.z*g4.z, o4.w*g4.w);
        }
        for (int idx = tid; idx < 256; idx += 128) {
            const int r = idx >> 2, w4 = (idx & 3) << 2;
            *(uint4*)&sB[r*20 + w4] = *(const uint4*)&g_WOt[(size_t)(n0+r)*64 + (kc>>1) + w4];
        }
        __syncthreads();
        #pragma unroll
        for (int ck = 0; ck < 2; ck++) {
            const int w0 = ck*8;
            unsigned ah[2][4];
            #pragma unroll
            for (int mt = 0; mt < 2; mt++)
                ldsm4(ah[mt], aA + (((wm*32 + mt*16 + arow)*20 + w0 + awof) << 2));
            #pragma unroll
            for (int p = 0; p < 2; p++) {
                unsigned b[4];
                ldsm4(b, aB + (((wn*32 + p*16 + krow)*20 + w0 + kwof) << 2));
                #pragma unroll
                for (int mt = 0; mt < 2; mt++) {
                    mma16h(acc[mt][2*p],   ah[mt], b);
                    mma16h(acc[mt][2*p+1], ah[mt], b+2);
                }
            }
        }
    }

    #pragma unroll
    for (int mt = 0; mt < 2; mt++) {
        const int r0 = m0 + wm*32 + mt*16 + g;
        #pragma unroll
        for (int nt = 0; nt < 4; nt++) {
            const int col = n0 + wn*32 + nt*8 + 2*tg;
            *(float2*)&out[(size_t)r0*CIN + col]     = make_float2(acc[mt][nt][0], acc[mt][nt][1]);
            *(float2*)&out[(size_t)(r0+8)*CIN + col] = make_float2(acc[mt][nt][2], acc[mt][nt][3]);
        }
    }
}

// =====================================================================
// launch
// =====================================================================
extern "C" void kernel_launch(void* const* d_in, const int* in_sizes, int n_in,
                              void* d_out, int out_size)
{
    (void)in_sizes; (void)n_in; (void)out_size;
    const float* z    = (const float*)d_in[0];
    const float* mask = (const float*)d_in[1];
    const float* lnw  = (const float*)d_in[2];
    const float* lnb  = (const float*)d_in[3];
    const float* wtri = (const float*)d_in[4];
    const float* wq   = (const float*)d_in[5];
    const float* wk   = (const float*)d_in[6];
    const float* wv   = (const float*)d_in[7];
    const float* wg   = (const float*)d_in[8];
    const float* wo   = (const float*)d_in[9];

    const size_t proj_sh = (size_t)(4*64*20) * 4;                    // 20480
    const size_t attn_sh = (size_t)(2*64*20 + 32*36) * 4 + 64*4;     // 15104
    const size_t out_sh  = (size_t)(2*64*20) * 4;                    // 10240

    wsplit_kernel<<<(WCOLS*64 + CIN*64 + 255)/256, 256>>>(wq, wk, wv, wg, wtri, wo);
    ln_split_kernel<<<M_TOT/8, 256>>>(z, lnw, lnb);
    proj_mma_kernel<<<dim3(9, M_TOT/64), 128, proj_sh>>>();
    vt_pack_kernel<<<dim3(NH, M_TOT/64), 128>>>();
    attn_mma_kernel<<<dim3(NN/64, NN, NH), 128, attn_sh>>>(mask);
    outproj_mma_kernel<<<dim3(2, M_TOT/64), 128, out_sh>>>((float*)d_out);
}

// round 8
// speedup vs baseline: 3.2503x; 1.1121x over previous
#include <cuda_runtime.h>
#include <cuda_bf16.h>
#include <cuda_fp16.h>
#include <math.h>

// ---------------- problem constants ----------------
#define NN   384
#define CIN  128
#define NH   4
#define CH   32
#define M_TOT (NN*NN)                   // 147456
#define MW   (M_TOT/2)
#define QK_SCALE 0.17677669529663687f   // 1/sqrt(32)
#define WCOLS 576                        // 512 proj cols + 4 tri + pad

// ---------------- scratch (device globals; no allocs) ----------------
__device__ unsigned g_Ah[(size_t)M_TOT*64];      // LN(z) bf16x2 hi plane
__device__ unsigned g_Al[(size_t)M_TOT*64];      // lo plane
__device__ unsigned g_Wth[(size_t)WCOLS*64];     // weights^T packed bf16x2 hi
__device__ unsigned g_Wtl[(size_t)WCOLS*64];
__device__ unsigned g_WOt[(size_t)CIN*64];       // wo^T packed half2
__device__ unsigned g_Qph[(size_t)NH*M_TOT*16];  // Q head-major bf16x2 hi/lo
__device__ unsigned g_Qpl[(size_t)NH*M_TOT*16];
__device__ unsigned g_Kph[(size_t)NH*M_TOT*16];
__device__ unsigned g_Kpl[(size_t)NH*M_TOT*16];
__device__ __half   g_Vh16[(size_t)NH*M_TOT*CH]; // V half, [h][m][c]
__device__ unsigned g_Vt [(size_t)NH*CH*MW];     // V^T packed half2 [h][c][m/2]
__device__ float g_G  [(size_t)M_TOT*CIN];       // sigmoid gate
__device__ float g_TRI[(size_t)NH*M_TOT];
__device__ float g_O  [(size_t)M_TOT*CIN];       // attn out, m-major

// ---------------- helpers ----------------
__device__ __forceinline__ unsigned pack2h(float a, float b) {
    __half2 t = __floats2half2_rn(a, b);
    return *(unsigned*)&t;
}
__device__ __forceinline__ unsigned packbf(float a, float b) {
    __nv_bfloat162 t = __floats2bfloat162_rn(a, b);
    return *(unsigned*)&t;
}
__device__ __forceinline__ void splitbf2(float a, float b, unsigned& hw, unsigned& lw) {
    __nv_bfloat16 ha = __float2bfloat16_rn(a);
    __nv_bfloat16 hb = __float2bfloat16_rn(b);
    float ra = a - __bfloat162float(ha);
    float rb = b - __bfloat162float(hb);
    __nv_bfloat162 h; h.x = ha; h.y = hb;
    hw = *(unsigned*)&h;
    lw = packbf(ra, rb);
}
__device__ __forceinline__ unsigned sm_u32(const void* p) {
    return (unsigned)__cvta_generic_to_shared(p);
}
__device__ __forceinline__ void ldsm4(unsigned* r, unsigned addr) {
    asm volatile("ldmatrix.sync.aligned.m8n8.x4.shared.b16 {%0,%1,%2,%3}, [%4];"
        : "=r"(r[0]), "=r"(r[1]), "=r"(r[2]), "=r"(r[3]) : "r"(addr));
}
__device__ __forceinline__ void cp16(unsigned saddr, const void* gptr) {
    asm volatile("cp.async.cg.shared.global [%0], [%1], 16;" :: "r"(saddr), "l"(gptr));
}
__device__ __forceinline__ void cp_commit() { asm volatile("cp.async.commit_group;"); }
__device__ __forceinline__ void cp_wait0()  { asm volatile("cp.async.wait_group 0;"); }
__device__ __forceinline__ void cp_wait1()  { asm volatile("cp.async.wait_group 1;"); }
// bf16 m16n8k16
__device__ __forceinline__ void mma16(float* d, const unsigned* a, const unsigned* b) {
    asm volatile(
        "mma.sync.aligned.m16n8k16.row.col.f32.bf16.bf16.f32 "
        "{%0,%1,%2,%3},{%4,%5,%6,%7},{%8,%9},{%0,%1,%2,%3};\n"
        : "+f"(d[0]), "+f"(d[1]), "+f"(d[2]), "+f"(d[3])
        : "r"(a[0]), "r"(a[1]), "r"(a[2]), "r"(a[3]), "r"(b[0]), "r"(b[1]));
}
// fp16 m16n8k16
__device__ __forceinline__ void mma16h(float* d, const unsigned* a, const unsigned* b) {
    asm volatile(
        "mma.sync.aligned.m16n8k16.row.col.f32.f16.f16.f32 "
        "{%0,%1,%2,%3},{%4,%5,%6,%7},{%8,%9},{%0,%1,%2,%3};\n"
        : "+f"(d[0]), "+f"(d[1]), "+f"(d[2]), "+f"(d[3])
        : "r"(a[0]), "r"(a[1]), "r"(a[2]), "r"(a[3]), "r"(b[0]), "r"(b[1]));
}

// =====================================================================
// prep 1: LayerNorm + bf16-split pack (1 warp per row)
// =====================================================================
__global__ void __launch_bounds__(256)
ln_split_kernel(const float* __restrict__ z,
                const float* __restrict__ lnw, const float* __restrict__ lnb)
{
    const int row  = blockIdx.x*8 + (threadIdx.x >> 5);
    const int lane = threadIdx.x & 31;
    const float4 v = *(const float4*)(z + (size_t)row*CIN + lane*4);
    float s1 = v.x+v.y+v.z+v.w;
    float s2 = v.x*v.x + v.y*v.y + v.z*v.z + v.w*v.w;
    #pragma unroll
    for (int o = 16; o; o >>= 1) {
        s1 += __shfl_xor_sync(0xffffffffu, s1, o);
        s2 += __shfl_xor_sync(0xffffffffu, s2, o);
    }
    const float mu  = s1 * (1.f/128.f);
    const float var = s2 * (1.f/128.f) - mu*mu;
    const float inv = rsqrtf(var + 1e-5f);
    const float4 w = *(const float4*)(lnw + lane*4);
    const float4 b = *(const float4*)(lnb + lane*4);
    const float y0 = (v.x-mu)*inv*w.x + b.x;
    const float y1 = (v.y-mu)*inv*w.y + b.y;
    const float y2 = (v.z-mu)*inv*w.z + b.z;
    const float y3 = (v.w-mu)*inv*w.w + b.w;
    unsigned h0,l0,h1,l1;
    splitbf2(y0,y1,h0,l0);
    splitbf2(y2,y3,h1,l1);
    const size_t base = (size_t)row*64 + lane*2;
    g_Ah[base] = h0; g_Ah[base+1] = h1;
    g_Al[base] = l0; g_Al[base+1] = l1;
}

// =====================================================================
// prep 2: weights -> transposed packed bf16 planes; wo -> packed half2
// =====================================================================
__global__ void __launch_bounds__(256)
wsplit_kernel(const float* __restrict__ wq, const float* __restrict__ wk,
              const float* __restrict__ wv, const float* __restrict__ wg,
              const float* __restrict__ wtri, const float* __restrict__ wo)
{
    const int idx = blockIdx.x*256 + threadIdx.x;
    if (idx < WCOLS*64) {
        const int n = idx >> 6, kw = idx & 63;
        const int k0 = kw*2;
        float v0, v1;
        if      (n < 128) { v0 = wq[k0*128 + n];          v1 = wq[(k0+1)*128 + n]; }
        else if (n < 256) { v0 = wk[k0*128 + n-128];      v1 = wk[(k0+1)*128 + n-128]; }
        else if (n < 384) { v0 = wv[k0*128 + n-256];      v1 = wv[(k0+1)*128 + n-256]; }
        else if (n < 512) { v0 = wg[k0*128 + n-384];      v1 = wg[(k0+1)*128 + n-384]; }
        else if (n < 516) { v0 = wtri[k0*4 + n-512];      v1 = wtri[(k0+1)*4 + n-512]; }
        else              { v0 = 0.f; v1 = 0.f; }
        unsigned hw, lw; splitbf2(v0, v1, hw, lw);
        g_Wth[idx] = hw; g_Wtl[idx] = lw;
    } else if (idx < WCOLS*64 + CIN*64) {
        const int j = idx - WCOLS*64;
        const int n = j >> 6, kw = j & 63;
        g_WOt[j] = pack2h(wo[(2*kw)*128 + n], wo[(2*kw+1)*128 + n]);
    }
}

// =====================================================================
// GEMM 1: C[M,576] = LN(z) @ W, split-bf16 (3 x m16n8k16), ldmatrix loads.
// =====================================================================
__global__ void __launch_bounds__(128, 4)
proj_mma_kernel()
{
    extern __shared__ unsigned shp[];
    unsigned* sAh = shp;                // [64][20] words
    unsigned* sAl = sAh + 64*20;
    unsigned* sBh = sAl + 64*20;
    unsigned* sBl = sBh + 64*20;

    const int tid  = threadIdx.x;
    const int warp = tid >> 5, lane = tid & 31;
    const int g = lane >> 2, tg = lane & 3;
    const int wm = warp >> 1, wn = warp & 1;
    const int ntb = blockIdx.x;            // 0..8
    const int m0  = blockIdx.y * 64;
    const int n0  = ntb * 64;

    const unsigned aAh = sm_u32(sAh), aAl = sm_u32(sAl);
    const unsigned aBh = sm_u32(sBh), aBl = sm_u32(sBl);
    const int arow = ((lane>>3)&1)*8 + (lane&7);
    const int awof = (lane>>4)*4;
    const int krow = ((lane>>4)&1)*8 + (lane&7);
    const int kwof = ((lane>>3)&1)*4;

    float acc[2][4][4];
    #pragma unroll
    for (int a = 0; a < 2; a++)
        #pragma unroll
        for (int b = 0; b < 4; b++)
            #pragma unroll
            for (int c = 0; c < 4; c++) acc[a][b][c] = 0.f;

    for (int kc = 0; kc < 128; kc += 32) {
        const int kw0 = kc >> 1;
        __syncthreads();
        for (int idx = tid; idx < 256; idx += 128) {
            const int r = idx >> 2, w4 = (idx & 3) << 2;
            *(uint4*)&sAh[r*20 + w4] = *(const uint4*)&g_Ah[(size_t)(m0+r)*64 + kw0 + w4];
            *(uint4*)&sAl[r*20 + w4] = *(const uint4*)&g_Al[(size_t)(m0+r)*64 + kw0 + w4];
            *(uint4*)&sBh[r*20 + w4] = *(const uint4*)&g_Wth[(size_t)(n0+r)*64 + kw0 + w4];
            *(uint4*)&sBl[r*20 + w4] = *(const uint4*)&g_Wtl[(size_t)(n0+r)*64 + kw0 + w4];
        }
        __syncthreads();
        #pragma unroll
        for (int sub = 0; sub < 2; sub++) {
            const int w0 = sub*8;
            unsigned ah[2][4], al[2][4];
            #pragma unroll
            for (int mt = 0; mt < 2; mt++) {
                const unsigned offa = ((wm*32 + mt*16 + arow)*20 + w0 + awof) << 2;
                ldsm4(ah[mt], aAh + offa);
                ldsm4(al[mt], aAl + offa);
            }
            #pragma unroll
            for (int p = 0; p < 2; p++) {
                const unsigned offb = ((wn*32 + p*16 + krow)*20 + w0 + kwof) << 2;
                unsigned bh[4], bl[4];
                ldsm4(bh, aBh + offb);
                ldsm4(bl, aBl + offb);
                #pragma unroll
                for (int mt = 0; mt < 2; mt++) {
                    mma16(acc[mt][2*p],   ah[mt], bh);
                    mma16(acc[mt][2*p],   ah[mt], bl);
                    mma16(acc[mt][2*p],   al[mt], bh);
                    mma16(acc[mt][2*p+1], ah[mt], bh+2);
                    mma16(acc[mt][2*p+1], ah[mt], bl+2);
                    mma16(acc[mt][2*p+1], al[mt], bh+2);
                }
            }
        }
    }

    // ---- epilogues ----
    if (ntb < 8) {
        const int cbase = (ntb & 1)*64;
        const int kind  = ntb >> 1;          // 0=Q 1=K 2=V 3=G
        #pragma unroll
        for (int mt = 0; mt < 2; mt++) {
            const int r0 = m0 + wm*32 + mt*16 + g;
            #pragma unroll
            for (int nt = 0; nt < 4; nt++) {
                const int col = cbase + wn*32 + nt*8 + 2*tg;
                const int h = col >> 5, c0 = col & 31;
                float v0 = acc[mt][nt][0], v1 = acc[mt][nt][1];
                float v2 = acc[mt][nt][2], v3 = acc[mt][nt][3];
                if (kind == 0 || kind == 1) {
                    if (kind == 0) { v0*=QK_SCALE; v1*=QK_SCALE; v2*=QK_SCALE; v3*=QK_SCALE; }
                    unsigned* dh = (kind == 0) ? g_Qph : g_Kph;
                    unsigned* dl = (kind == 0) ? g_Qpl : g_Kpl;
                    const size_t w0i = ((size_t)h*M_TOT + r0)*16 + (c0>>1);
                    const size_t w1i = ((size_t)h*M_TOT + r0 + 8)*16 + (c0>>1);
                    unsigned hw, lw;
                    splitbf2(v0, v1, hw, lw); dh[w0i] = hw; dl[w0i] = lw;
                    splitbf2(v2, v3, hw, lw); dh[w1i] = hw; dl[w1i] = lw;
                } else if (kind == 2) {
                    const size_t hm0 = ((size_t)h*M_TOT + r0)*CH + c0;
                    const size_t hm1 = ((size_t)h*M_TOT + r0 + 8)*CH + c0;
                    *(__half2*)&g_Vh16[hm0] = __floats2half2_rn(v0, v1);
                    *(__half2*)&g_Vh16[hm1] = __floats2half2_rn(v2, v3);
                } else {
                    *(float2*)&g_G[(size_t)r0*CIN + col] =
                        make_float2(1.f/(1.f+__expf(-v0)), 1.f/(1.f+__expf(-v1)));
                    *(float2*)&g_G[(size_t)(r0+8)*CIN + col] =
                        make_float2(1.f/(1.f+__expf(-v2)), 1.f/(1.f+__expf(-v3)));
                }
            }
        }
    } else if (wn == 0 && tg < 2) {
        #pragma unroll
        for (int mt = 0; mt < 2; mt++) {
            const int r0 = m0 + wm*32 + mt*16 + g;
            const int c0 = 2*tg;
            g_TRI[(size_t)c0*M_TOT     + r0]   = acc[mt][0][0];
            g_TRI[(size_t)(c0+1)*M_TOT + r0]   = acc[mt][0][1];
            g_TRI[(size_t)c0*M_TOT     + r0+8] = acc[mt][0][2];
            g_TRI[(size_t)(c0+1)*M_TOT + r0+8] = acc[mt][0][3];
        }
    }
}

// =====================================================================
// prep 3: V -> transposed packed half2 planes [h][c][m/2]
// =====================================================================
__global__ void __launch_bounds__(128)
vt_pack_kernel()
{
    __shared__ __half tile[64][32];
    const int h  = blockIdx.x;
    const int mb = blockIdx.y;
    const int tid = threadIdx.x;
    const size_t base = ((size_t)h*M_TOT + (size_t)mb*64)*CH;
    for (int t = tid; t < 256; t += 128) {
        const int r = t >> 2, cw = (t & 3) << 3;
        *(uint4*)&tile[r][cw] = *(const uint4*)&g_Vh16[base + (size_t)r*CH + cw];
    }
    __syncthreads();
    const int c = tid >> 2, mp0 = (tid & 3) << 3;
    const size_t ob = ((size_t)(h*CH + c))*MW + mb*32 + mp0;
    unsigned w[8];
    #pragma unroll
    for (int j = 0; j < 8; j++) {
        __half2 t2; t2.x = tile[2*(mp0+j)][c]; t2.y = tile[2*(mp0+j)+1][c];
        w[j] = *(unsigned*)&t2;
    }
    *(uint4*)&g_Vt[ob]   = make_uint4(w[0], w[1], w[2], w[3]);
    *(uint4*)&g_Vt[ob+4] = make_uint4(w[4], w[5], w[6], w[7]);
}

// =====================================================================
// flash attention, 128 queries/block (8 warps), cp.async double-buffered
// K/V stages, S = split-bf16, PV = fp16, ldmatrix operand loads.
// stage s (3712 words): Kh [64][20] | Kl [64][20] | Vt [32][36]
// =====================================================================
#define STG_W 3712
__global__ void __launch_bounds__(256, 2)
attn_mma_kernel(const float* __restrict__ mask)
{
    extern __shared__ unsigned sha[];
    float* sMbAll = (float*)(sha + 2*STG_W);   // [384]

    const int tid  = threadIdx.x;
    const int warp = tid >> 5, lane = tid & 31;
    const int g = lane >> 2, tg = lane & 3;
    const int q0 = blockIdx.x * 128;
    const int i  = blockIdx.y;
    const int h  = blockIdx.z;
    const size_t rowbase = (size_t)i * NN;
    const size_t hbase   = (size_t)h * M_TOT;

    const int arow = ((lane>>3)&1)*8 + (lane&7);
    const int awof = (lane>>4)*4;
    const int krow = ((lane>>4)&1)*8 + (lane&7);
    const int kwof = ((lane>>3)&1)*4;

    // mask row once per block
    for (int idx = tid; idx < NN; idx += 256)
        sMbAll[idx] = 1e9f * (mask[rowbase + idx] - 1.f);

    // ---- stage Q (two passes through stage0 K buffers) ----
    unsigned qh[2][4], ql[2][4];
    {
        unsigned* sQh = sha;
        unsigned* sQl = sha + 1280;
        const unsigned aQh = sm_u32(sQh), aQl = sm_u32(sQl);
        #pragma unroll
        for (int half = 0; half < 2; half++) {
            const int r = tid >> 2, w4 = (tid & 3) << 2;
            const size_t gw = (hbase + rowbase + q0 + half*64 + r)*16 + w4;
            *(uint4*)&sQh[r*20 + w4] = *(const uint4*)&g_Qph[gw];
            *(uint4*)&sQl[r*20 + w4] = *(const uint4*)&g_Qpl[gw];
            __syncthreads();
            if ((warp >> 2) == half) {
                const int wl = warp & 3;
                #pragma unroll
                for (int ck = 0; ck < 2; ck++) {
                    const unsigned offq = ((wl*16 + arow)*20 + ck*8 + awof) << 2;
                    ldsm4(qh[ck], aQh + offq);
                    ldsm4(ql[ck], aQl + offq);
                }
            }
            __syncthreads();
        }
    }

    const int qrow = q0 + (warp & 3)*16 + (warp >> 2)*64 + g;   // match Q frag row
    const float* triP0 = g_TRI + hbase + (size_t)qrow*NN;
    const float* triP1 = triP0 + (size_t)8*NN;

    float l0 = 0.f, l1 = 0.f;
    float oacc[4][4];
    #pragma unroll
    for (int a = 0; a < 4; a++)
        #pragma unroll
        for (int b = 0; b < 4; b++) oacc[a][b] = 0.f;

    // ---- async fill helper (inlined twice) ----
    const int fr  = tid >> 2,  fw  = (tid & 3) << 2;   // K planes
    const int fvr = tid >> 3,  fvw = (tid & 7) << 2;   // Vt

    // prologue: fill stage 0 with kb=0
    {
        unsigned* st = sha;
        const size_t gw = (hbase + rowbase + 0 + fr)*16 + fw;
        cp16(sm_u32(st + fr*20 + fw),        &g_Kph[gw]);
        cp16(sm_u32(st + 1280 + fr*20 + fw), &g_Kpl[gw]);
        const size_t mw0 = rowbase >> 1;
        cp16(sm_u32(st + 2560 + fvr*36 + fvw), &g_Vt[((size_t)(h*CH + fvr))*MW + mw0 + fvw]);
        cp_commit();
    }

    for (int t = 0; t < 6; t++) {
        const int cur = t & 1;
        if (t < 5) {
            unsigned* st = sha + (1-cur)*STG_W;
            const int kbn = (t+1)*64;
            const size_t gw = (hbase + rowbase + kbn + fr)*16 + fw;
            cp16(sm_u32(st + fr*20 + fw),        &g_Kph[gw]);
            cp16(sm_u32(st + 1280 + fr*20 + fw), &g_Kpl[gw]);
            const size_t mw0 = (rowbase + kbn) >> 1;
            cp16(sm_u32(st + 2560 + fvr*36 + fvw), &g_Vt[((size_t)(h*CH + fvr))*MW + mw0 + fvw]);
            cp_commit();
            cp_wait1();
        } else {
            cp_wait0();
        }
        __syncthreads();

        const unsigned aKh = sm_u32(sha + cur*STG_W);
        const unsigned aKl = aKh + 1280*4;
        const unsigned aVt = aKh + 2560*4;
        const int kb = t*64;

        // ---- S = Q K^T ----
        float s[8][4];
        #pragma unroll
        for (int a = 0; a < 8; a++)
            #pragma unroll
            for (int b = 0; b < 4; b++) s[a][b] = 0.f;

        #pragma unroll
        for (int ck = 0; ck < 2; ck++) {
            #pragma unroll
            for (int p = 0; p < 4; p++) {
                const unsigned off = ((p*16 + krow)*20 + ck*8 + kwof) << 2;
                unsigned bh[4], bl[4];
                ldsm4(bh, aKh + off);
                ldsm4(bl, aKl + off);
                mma16(s[2*p],   qh[ck], bh);
                mma16(s[2*p],   qh[ck], bl);
                mma16(s[2*p],   ql[ck], bh);
                mma16(s[2*p+1], qh[ck], bh+2);
                mma16(s[2*p+1], qh[ck], bl+2);
                mma16(s[2*p+1], ql[ck], bh+2);
            }
        }

        // ---- bias + exp ----
        #pragma unroll
        for (int nt = 0; nt < 8; nt++) {
            const int col = nt*8 + 2*tg;
            const float2 t0 = *(const float2*)&triP0[kb + col];
            const float2 t1 = *(const float2*)&triP1[kb + col];
            const float2 mb = *(const float2*)&sMbAll[kb + col];
            s[nt][0] = __expf(s[nt][0] + t0.x + mb.x);
            s[nt][1] = __expf(s[nt][1] + t0.y + mb.y);
            s[nt][2] = __expf(s[nt][2] + t1.x + mb.x);
            s[nt][3] = __expf(s[nt][3] + t1.y + mb.y);
            l0 += s[nt][0] + s[nt][1];
            l1 += s[nt][2] + s[nt][3];
        }

        // ---- O += P V ----
        #pragma unroll
        for (int j = 0; j < 4; j++) {
            unsigned a[4];
            a[0] = pack2h(s[2*j  ][0], s[2*j  ][1]);
            a[1] = pack2h(s[2*j  ][2], s[2*j  ][3]);
            a[2] = pack2h(s[2*j+1][0], s[2*j+1][1]);
            a[3] = pack2h(s[2*j+1][2], s[2*j+1][3]);
            #pragma unroll
            for (int p = 0; p < 2; p++) {
                const unsigned off = ((p*16 + krow)*36 + j*8 + kwof) << 2;
                unsigned b[4];
                ldsm4(b, aVt + off);
                mma16h(oacc[2*p],   a, b);
                mma16h(oacc[2*p+1], a, b+2);
            }
        }
        __syncthreads();
    }

    l0 += __shfl_xor_sync(0xffffffffu, l0, 1);
    l0 += __shfl_xor_sync(0xffffffffu, l0, 2);
    l1 += __shfl_xor_sync(0xffffffffu, l1, 1);
    l1 += __shfl_xor_sync(0xffffffffu, l1, 2);

    const float inv0 = 1.f/l0, inv1 = 1.f/l1;
    const size_t ob0 = (rowbase + qrow)*CIN + h*CH;
    const size_t ob1 = (rowbase + qrow + 8)*CIN + h*CH;
    #pragma unroll
    for (int nt = 0; nt < 4; nt++) {
        const int col = nt*8 + 2*tg;
        *(float2*)&g_O[ob0 + col] = make_float2(oacc[nt][0]*inv0, oacc[nt][1]*inv0);
        *(float2*)&g_O[ob1 + col] = make_float2(oacc[nt][2]*inv1, oacc[nt][3]*inv1);
    }
}

// =====================================================================
// GEMM 3: out = (O*G) @ wo, fp16 m16n8k16, ldmatrix loads.
// =====================================================================
__global__ void __launch_bounds__(128, 6)
outproj_mma_kernel(float* __restrict__ out)
{
    extern __shared__ unsigned sho[];
    unsigned* sA = sho;             // [64][20] words
    unsigned* sB = sA + 64*20;      // [64][20]

    const int tid  = threadIdx.x;
    const int warp = tid >> 5, lane = tid & 31;
    const int g = lane >> 2, tg = lane & 3;
    const int wm = warp >> 1, wn = warp & 1;
    const int n0 = blockIdx.x * 64;
    const int m0 = blockIdx.y * 64;

    const unsigned aA = sm_u32(sA), aB = sm_u32(sB);
    const int arow = ((lane>>3)&1)*8 + (lane&7);
    const int awof = (lane>>4)*4;
    const int krow = ((lane>>4)&1)*8 + (lane&7);
    const int kwof = ((lane>>3)&1)*4;

    float acc[2][4][4];
    #pragma unroll
    for (int a = 0; a < 2; a++)
        #pragma unroll
        for (int b = 0; b < 4; b++)
            #pragma unroll
            for (int c = 0; c < 4; c++) acc[a][b][c] = 0.f;

    for (int kc = 0; kc < 128; kc += 32) {
        __syncthreads();
        for (int idx = tid; idx < 512; idx += 128) {
            const int ra = idx >> 3, ca = (idx & 7) << 2;
            const size_t ga = (size_t)(m0+ra)*CIN + kc + ca;
            const float4 o4 = *(const float4*)&g_O[ga];
            const float4 g4 = *(const float4*)&g_G[ga];
            sA[ra*20 + (ca>>1)    ] = pack2h(o4.x*g4.x, o4.y*g4.y);
            sA[ra*20 + (ca>>1) + 1] = pack2h(o4.z*g4.z, o4.w*g4.w);
        }
        for (int idx = tid; idx < 256; idx += 128) {
            const int r = idx >> 2, w4 = (idx & 3) << 2;
            *(uint4*)&sB[r*20 + w4] = *(const uint4*)&g_WOt[(size_t)(n0+r)*64 + (kc>>1) + w4];
        }
        __syncthreads();
        #pragma unroll
        for (int ck = 0; ck < 2; ck++) {
            const int w0 = ck*8;
            unsigned ah[2][4];
            #pragma unroll
            for (int mt = 0; mt < 2; mt++)
                ldsm4(ah[mt], aA + (((wm*32 + mt*16 + arow)*20 + w0 + awof) << 2));
            #pragma unroll
            for (int p = 0; p < 2; p++) {
                unsigned b[4];
                ldsm4(b, aB + (((wn*32 + p*16 + krow)*20 + w0 + kwof) << 2));
                #pragma unroll
                for (int mt = 0; mt < 2; mt++) {
                    mma16h(acc[mt][2*p],   ah[mt], b);
                    mma16h(acc[mt][2*p+1], ah[mt], b+2);
                }
            }
        }
    }

    #pragma unroll
    for (int mt = 0; mt < 2; mt++) {
        const int r0 = m0 + wm*32 + mt*16 + g;
        #pragma unroll
        for (int nt = 0; nt < 4; nt++) {
            const int col = n0 + wn*32 + nt*8 + 2*tg;
            *(float2*)&out[(size_t)r0*CIN + col]     = make_float2(acc[mt][nt][0], acc[mt][nt][1]);
            *(float2*)&out[(size_t)(r0+8)*CIN + col] = make_float2(acc[mt][nt][2], acc[mt][nt][3]);
        }
    }
}

// =====================================================================
// launch
// =====================================================================
extern "C" void kernel_launch(void* const* d_in, const int* in_sizes, int n_in,
                              void* d_out, int out_size)
{
    (void)in_sizes; (void)n_in; (void)out_size;
    const float* z    = (const float*)d_in[0];
    const float* mask = (const float*)d_in[1];
    const float* lnw  = (const float*)d_in[2];
    const float* lnb  = (const float*)d_in[3];
    const float* wtri = (const float*)d_in[4];
    const float* wq   = (const float*)d_in[5];
    const float* wk   = (const float*)d_in[6];
    const float* wv   = (const float*)d_in[7];
    const float* wg   = (const float*)d_in[8];
    const float* wo   = (const float*)d_in[9];

    const size_t proj_sh = (size_t)(4*64*20) * 4;                 // 20480
    const size_t attn_sh = (size_t)(2*STG_W) * 4 + NN*4;          // 31232
    const size_t out_sh  = (size_t)(2*64*20) * 4;                 // 10240

    wsplit_kernel<<<(WCOLS*64 + CIN*64 + 255)/256, 256>>>(wq, wk, wv, wg, wtri, wo);
    ln_split_kernel<<<M_TOT/8, 256>>>(z, lnw, lnb);
    proj_mma_kernel<<<dim3(9, M_TOT/64), 128, proj_sh>>>();
    vt_pack_kernel<<<dim3(NH, M_TOT/64), 128>>>();
    attn_mma_kernel<<<dim3(NN/128, NN, NH), 256, attn_sh>>>(mask);
    outproj_mma_kernel<<<dim3(2, M_TOT/64), 128, out_sh>>>((float*)d_out);
}

// round 9
// speedup vs baseline: 3.3710x; 1.0371x over previous
#include <cuda_runtime.h>
#include <cuda_bf16.h>
#include <cuda_fp16.h>
#include <math.h>

// ---------------- problem constants ----------------
#define NN   384
#define CIN  128
#define NH   4
#define CH   32
#define M_TOT (NN*NN)                   // 147456
#define MW   (M_TOT/2)
#define QK_SCALE 0.17677669529663687f   // 1/sqrt(32)
#define WCOLS 576                        // 512 proj cols + 4 tri + pad

// ---------------- scratch (device globals; no allocs) ----------------
__device__ unsigned g_Ah[(size_t)M_TOT*64];      // LN(z) bf16x2 hi plane
__device__ unsigned g_Al[(size_t)M_TOT*64];      // lo plane
__device__ unsigned g_Wth[(size_t)WCOLS*64];     // weights^T packed bf16x2 hi
__device__ unsigned g_Wtl[(size_t)WCOLS*64];
__device__ unsigned g_WOt[(size_t)CIN*64];       // wo^T packed half2
__device__ unsigned g_Qph[(size_t)NH*M_TOT*16];  // Q head-major bf16x2 hi/lo
__device__ unsigned g_Qpl[(size_t)NH*M_TOT*16];
__device__ unsigned g_Kph[(size_t)NH*M_TOT*16];
__device__ unsigned g_Kpl[(size_t)NH*M_TOT*16];
__device__ unsigned g_Vt [(size_t)NH*CH*MW];     // V^T packed half2 [h][c][m/2]
__device__ float g_G  [(size_t)M_TOT*CIN];       // sigmoid gate
__device__ float g_TRI[(size_t)NH*M_TOT];
__device__ float g_O  [(size_t)M_TOT*CIN];       // attn out, m-major

// ---------------- helpers ----------------
__device__ __forceinline__ unsigned pack2h(float a, float b) {
    __half2 t = __floats2half2_rn(a, b);
    return *(unsigned*)&t;
}
__device__ __forceinline__ unsigned packbf(float a, float b) {
    __nv_bfloat162 t = __floats2bfloat162_rn(a, b);
    return *(unsigned*)&t;
}
__device__ __forceinline__ void splitbf2(float a, float b, unsigned& hw, unsigned& lw) {
    __nv_bfloat16 ha = __float2bfloat16_rn(a);
    __nv_bfloat16 hb = __float2bfloat16_rn(b);
    float ra = a - __bfloat162float(ha);
    float rb = b - __bfloat162float(hb);
    __nv_bfloat162 h; h.x = ha; h.y = hb;
    hw = *(unsigned*)&h;
    lw = packbf(ra, rb);
}
__device__ __forceinline__ unsigned sm_u32(const void* p) {
    return (unsigned)__cvta_generic_to_shared(p);
}
__device__ __forceinline__ void ldsm4(unsigned* r, unsigned addr) {
    asm volatile("ldmatrix.sync.aligned.m8n8.x4.shared.b16 {%0,%1,%2,%3}, [%4];"
        : "=r"(r[0]), "=r"(r[1]), "=r"(r[2]), "=r"(r[3]) : "r"(addr));
}
__device__ __forceinline__ void cp16(unsigned saddr, const void* gptr) {
    asm volatile("cp.async.cg.shared.global [%0], [%1], 16;" :: "r"(saddr), "l"(gptr));
}
__device__ __forceinline__ void cp_commit() { asm volatile("cp.async.commit_group;"); }
__device__ __forceinline__ void cp_wait0()  { asm volatile("cp.async.wait_group 0;"); }
__device__ __forceinline__ void cp_wait1()  { asm volatile("cp.async.wait_group 1;"); }
// bf16 m16n8k16
__device__ __forceinline__ void mma16(float* d, const unsigned* a, const unsigned* b) {
    asm volatile(
        "mma.sync.aligned.m16n8k16.row.col.f32.bf16.bf16.f32 "
        "{%0,%1,%2,%3},{%4,%5,%6,%7},{%8,%9},{%0,%1,%2,%3};\n"
        : "+f"(d[0]), "+f"(d[1]), "+f"(d[2]), "+f"(d[3])
        : "r"(a[0]), "r"(a[1]), "r"(a[2]), "r"(a[3]), "r"(b[0]), "r"(b[1]));
}
// fp16 m16n8k16
__device__ __forceinline__ void mma16h(float* d, const unsigned* a, const unsigned* b) {
    asm volatile(
        "mma.sync.aligned.m16n8k16.row.col.f32.f16.f16.f32 "
        "{%0,%1,%2,%3},{%4,%5,%6,%7},{%8,%9},{%0,%1,%2,%3};\n"
        : "+f"(d[0]), "+f"(d[1]), "+f"(d[2]), "+f"(d[3])
        : "r"(a[0]), "r"(a[1]), "r"(a[2]), "r"(a[3]), "r"(b[0]), "r"(b[1]));
}

// =====================================================================
// prep 1: LayerNorm + bf16-split pack (1 warp per row)
// =====================================================================
__global__ void __launch_bounds__(256)
ln_split_kernel(const float* __restrict__ z,
                const float* __restrict__ lnw, const float* __restrict__ lnb)
{
    const int row  = blockIdx.x*8 + (threadIdx.x >> 5);
    const int lane = threadIdx.x & 31;
    const float4 v = *(const float4*)(z + (size_t)row*CIN + lane*4);
    float s1 = v.x+v.y+v.z+v.w;
    float s2 = v.x*v.x + v.y*v.y + v.z*v.z + v.w*v.w;
    #pragma unroll
    for (int o = 16; o; o >>= 1) {
        s1 += __shfl_xor_sync(0xffffffffu, s1, o);
        s2 += __shfl_xor_sync(0xffffffffu, s2, o);
    }
    const float mu  = s1 * (1.f/128.f);
    const float var = s2 * (1.f/128.f) - mu*mu;
    const float inv = rsqrtf(var + 1e-5f);
    const float4 w = *(const float4*)(lnw + lane*4);
    const float4 b = *(const float4*)(lnb + lane*4);
    const float y0 = (v.x-mu)*inv*w.x + b.x;
    const float y1 = (v.y-mu)*inv*w.y + b.y;
    const float y2 = (v.z-mu)*inv*w.z + b.z;
    const float y3 = (v.w-mu)*inv*w.w + b.w;
    unsigned h0,l0,h1,l1;
    splitbf2(y0,y1,h0,l0);
    splitbf2(y2,y3,h1,l1);
    const size_t base = (size_t)row*64 + lane*2;
    g_Ah[base] = h0; g_Ah[base+1] = h1;
    g_Al[base] = l0; g_Al[base+1] = l1;
}

// =====================================================================
// prep 2: weights -> transposed packed bf16 planes; wo -> packed half2
// =====================================================================
__global__ void __launch_bounds__(256)
wsplit_kernel(const float* __restrict__ wq, const float* __restrict__ wk,
              const float* __restrict__ wv, const float* __restrict__ wg,
              const float* __restrict__ wtri, const float* __restrict__ wo)
{
    const int idx = blockIdx.x*256 + threadIdx.x;
    if (idx < WCOLS*64) {
        const int n = idx >> 6, kw = idx & 63;
        const int k0 = kw*2;
        float v0, v1;
        if      (n < 128) { v0 = wq[k0*128 + n];          v1 = wq[(k0+1)*128 + n]; }
        else if (n < 256) { v0 = wk[k0*128 + n-128];      v1 = wk[(k0+1)*128 + n-128]; }
        else if (n < 384) { v0 = wv[k0*128 + n-256];      v1 = wv[(k0+1)*128 + n-256]; }
        else if (n < 512) { v0 = wg[k0*128 + n-384];      v1 = wg[(k0+1)*128 + n-384]; }
        else if (n < 516) { v0 = wtri[k0*4 + n-512];      v1 = wtri[(k0+1)*4 + n-512]; }
        else              { v0 = 0.f; v1 = 0.f; }
        unsigned hw, lw; splitbf2(v0, v1, hw, lw);
        g_Wth[idx] = hw; g_Wtl[idx] = lw;
    } else if (idx < WCOLS*64 + CIN*64) {
        const int j = idx - WCOLS*64;
        const int n = j >> 6, kw = j & 63;
        g_WOt[j] = pack2h(wo[(2*kw)*128 + n], wo[(2*kw+1)*128 + n]);
    }
}

// =====================================================================
// GEMM 1: C[M,576] = LN(z) @ W, split-bf16, ldmatrix, cp.async 2-stage.
// stage (5120 words): Ah[64][20] | Al | Bh | Bl
// V epilogue writes transposed g_Vt directly (fused vt_pack).
// =====================================================================
#define PSTG_W 5120
__global__ void __launch_bounds__(128, 4)
proj_mma_kernel()
{
    extern __shared__ unsigned shp[];

    const int tid  = threadIdx.x;
    const int warp = tid >> 5, lane = tid & 31;
    const int g = lane >> 2, tg = lane & 3;
    const int wm = warp >> 1, wn = warp & 1;
    const int ntb = blockIdx.x;            // 0..8
    const int m0  = blockIdx.y * 64;
    const int n0  = ntb * 64;

    const int arow = ((lane>>3)&1)*8 + (lane&7);
    const int awof = (lane>>4)*4;
    const int krow = ((lane>>4)&1)*8 + (lane&7);
    const int kwof = ((lane>>3)&1)*4;

    float acc[2][4][4];
    #pragma unroll
    for (int a = 0; a < 2; a++)
        #pragma unroll
        for (int b = 0; b < 4; b++)
            #pragma unroll
            for (int c = 0; c < 4; c++) acc[a][b][c] = 0.f;

    // fill geometry: 128 thr, per plane 64 rows x 16 words -> 2 uint4/thread
    const int fr0 = tid >> 1, fw0 = (tid & 1) << 3;   // rows 0..63, word 0 or 8

    // prologue fill stage 0 (kc=0)
    {
        unsigned* st = shp;
        #pragma unroll
        for (int half = 0; half < 2; half++) {
            const int fw = fw0 + half*4;
            const size_t ga = (size_t)(m0+fr0)*64 + fw;
            const size_t gb = (size_t)(n0+fr0)*64 + fw;
            cp16(sm_u32(st +        fr0*20 + fw), &g_Ah[ga]);
            cp16(sm_u32(st + 1280 + fr0*20 + fw), &g_Al[ga]);
            cp16(sm_u32(st + 2560 + fr0*20 + fw), &g_Wth[gb]);
            cp16(sm_u32(st + 3840 + fr0*20 + fw), &g_Wtl[gb]);
        }
        cp_commit();
    }

    for (int t = 0; t < 4; t++) {
        const int cur = t & 1;
        if (t < 3) {
            unsigned* st = shp + (1-cur)*PSTG_W;
            const int kw0 = (t+1)*16;
            #pragma unroll
            for (int half = 0; half < 2; half++) {
                const int fw = fw0 + half*4;
                const size_t ga = (size_t)(m0+fr0)*64 + kw0 + fw;
                const size_t gb = (size_t)(n0+fr0)*64 + kw0 + fw;
                cp16(sm_u32(st +        fr0*20 + fw), &g_Ah[ga]);
                cp16(sm_u32(st + 1280 + fr0*20 + fw), &g_Al[ga]);
                cp16(sm_u32(st + 2560 + fr0*20 + fw), &g_Wth[gb]);
                cp16(sm_u32(st + 3840 + fr0*20 + fw), &g_Wtl[gb]);
            }
            cp_commit();
            cp_wait1();
        } else {
            cp_wait0();
        }
        __syncthreads();

        const unsigned aAh = sm_u32(shp + cur*PSTG_W);
        const unsigned aAl = aAh + 1280*4;
        const unsigned aBh = aAh + 2560*4;
        const unsigned aBl = aAh + 3840*4;

        #pragma unroll
        for (int sub = 0; sub < 2; sub++) {
            const int w0 = sub*8;
            unsigned ah[2][4], al[2][4];
            #pragma unroll
            for (int mt = 0; mt < 2; mt++) {
                const unsigned offa = ((wm*32 + mt*16 + arow)*20 + w0 + awof) << 2;
                ldsm4(ah[mt], aAh + offa);
                ldsm4(al[mt], aAl + offa);
            }
            #pragma unroll
            for (int p = 0; p < 2; p++) {
                const unsigned offb = ((wn*32 + p*16 + krow)*20 + w0 + kwof) << 2;
                unsigned bh[4], bl[4];
                ldsm4(bh, aBh + offb);
                ldsm4(bl, aBl + offb);
                #pragma unroll
                for (int mt = 0; mt < 2; mt++) {
                    mma16(acc[mt][2*p],   ah[mt], bh);
                    mma16(acc[mt][2*p],   ah[mt], bl);
                    mma16(acc[mt][2*p],   al[mt], bh);
                    mma16(acc[mt][2*p+1], ah[mt], bh+2);
                    mma16(acc[mt][2*p+1], ah[mt], bl+2);
                    mma16(acc[mt][2*p+1], al[mt], bh+2);
                }
            }
        }
        __syncthreads();
    }

    // ---- epilogues ----
    if (ntb < 8) {
        const int cbase = (ntb & 1)*64;
        const int kind  = ntb >> 1;          // 0=Q 1=K 2=V 3=G
        if (kind == 2) {
            // fused V transpose: stage 64x64 half tile, write g_Vt [h][c][m/2]
            __half* tileV = (__half*)shp;
            #pragma unroll
            for (int mt = 0; mt < 2; mt++) {
                const int lm = wm*32 + mt*16 + g;
                #pragma unroll
                for (int nt = 0; nt < 4; nt++) {
                    const int lc = wn*32 + nt*8 + 2*tg;
                    *(__half2*)&tileV[lm*64 + lc] =
                        __floats2half2_rn(acc[mt][nt][0], acc[mt][nt][1]);
                    *(__half2*)&tileV[(lm+8)*64 + lc] =
                        __floats2half2_rn(acc[mt][nt][2], acc[mt][nt][3]);
                }
            }
            __syncthreads();
            const int lc = tid >> 1;                   // 0..63
            const int mh = tid & 1;                    // which 16-pair half
            const int h  = (ntb - 4)*2 + (lc >> 5);
            const int c  = lc & 31;
            unsigned w[16];
            #pragma unroll
            for (int j = 0; j < 16; j++) {
                const int m2 = mh*16 + j;
                __half2 t2; t2.x = tileV[(2*m2)*64 + lc]; t2.y = tileV[(2*m2+1)*64 + lc];
                w[j] = *(unsigned*)&t2;
            }
            const size_t ob = ((size_t)(h*CH + c))*MW + (m0 >> 1) + mh*16;
            *(uint4*)&g_Vt[ob]    = make_uint4(w[0], w[1], w[2], w[3]);
            *(uint4*)&g_Vt[ob+4]  = make_uint4(w[4], w[5], w[6], w[7]);
            *(uint4*)&g_Vt[ob+8]  = make_uint4(w[8], w[9], w[10], w[11]);
            *(uint4*)&g_Vt[ob+12] = make_uint4(w[12], w[13], w[14], w[15]);
        } else {
            #pragma unroll
            for (int mt = 0; mt < 2; mt++) {
                const int r0 = m0 + wm*32 + mt*16 + g;
                #pragma unroll
                for (int nt = 0; nt < 4; nt++) {
                    const int col = cbase + wn*32 + nt*8 + 2*tg;
                    const int h = col >> 5, c0 = col & 31;
                    float v0 = acc[mt][nt][0], v1 = acc[mt][nt][1];
                    float v2 = acc[mt][nt][2], v3 = acc[mt][nt][3];
                    if (kind == 0 || kind == 1) {
                        if (kind == 0) { v0*=QK_SCALE; v1*=QK_SCALE; v2*=QK_SCALE; v3*=QK_SCALE; }
                        unsigned* dh = (kind == 0) ? g_Qph : g_Kph;
                        unsigned* dl = (kind == 0) ? g_Qpl : g_Kpl;
                        const size_t w0i = ((size_t)h*M_TOT + r0)*16 + (c0>>1);
                        const size_t w1i = ((size_t)h*M_TOT + r0 + 8)*16 + (c0>>1);
                        unsigned hw, lw;
                        splitbf2(v0, v1, hw, lw); dh[w0i] = hw; dl[w0i] = lw;
                        splitbf2(v2, v3, hw, lw); dh[w1i] = hw; dl[w1i] = lw;
                    } else {
                        *(float2*)&g_G[(size_t)r0*CIN + col] =
                            make_float2(1.f/(1.f+__expf(-v0)), 1.f/(1.f+__expf(-v1)));
                        *(float2*)&g_G[(size_t)(r0+8)*CIN + col] =
                            make_float2(1.f/(1.f+__expf(-v2)), 1.f/(1.f+__expf(-v3)));
                    }
                }
            }
        }
    } else if (wn == 0 && tg < 2) {
        #pragma unroll
        for (int mt = 0; mt < 2; mt++) {
            const int r0 = m0 + wm*32 + mt*16 + g;
            const int c0 = 2*tg;
            g_TRI[(size_t)c0*M_TOT     + r0]   = acc[mt][0][0];
            g_TRI[(size_t)(c0+1)*M_TOT + r0]   = acc[mt][0][1];
            g_TRI[(size_t)c0*M_TOT     + r0+8] = acc[mt][0][2];
            g_TRI[(size_t)(c0+1)*M_TOT + r0+8] = acc[mt][0][3];
        }
    }
}

// =====================================================================
// flash attention, 128 queries/block (8 warps), cp.async double-buffered
// K/V stages, S = split-bf16, PV = fp16, ldmatrix operand loads.
// stage s (3712 words): Kh [64][20] | Kl [64][20] | Vt [32][36]
// =====================================================================
#define STG_W 3712
__global__ void __launch_bounds__(256, 2)
attn_mma_kernel(const float* __restrict__ mask)
{
    extern __shared__ unsigned sha[];
    float* sMbAll = (float*)(sha + 2*STG_W);   // [384]

    const int tid  = threadIdx.x;
    const int warp = tid >> 5, lane = tid & 31;
    const int g = lane >> 2, tg = lane & 3;
    const int q0 = blockIdx.x * 128;
    const int i  = blockIdx.y;
    const int h  = blockIdx.z;
    const size_t rowbase = (size_t)i * NN;
    const size_t hbase   = (size_t)h * M_TOT;

    const int arow = ((lane>>3)&1)*8 + (lane&7);
    const int awof = (lane>>4)*4;
    const int krow = ((lane>>4)&1)*8 + (lane&7);
    const int kwof = ((lane>>3)&1)*4;

    for (int idx = tid; idx < NN; idx += 256)
        sMbAll[idx] = 1e9f * (mask[rowbase + idx] - 1.f);

    // ---- stage Q (two passes through stage0 K buffers) ----
    unsigned qh[2][4], ql[2][4];
    {
        unsigned* sQh = sha;
        unsigned* sQl = sha + 1280;
        const unsigned aQh = sm_u32(sQh), aQl = sm_u32(sQl);
        #pragma unroll
        for (int half = 0; half < 2; half++) {
            const int r = tid >> 2, w4 = (tid & 3) << 2;
            const size_t gw = (hbase + rowbase + q0 + half*64 + r)*16 + w4;
            *(uint4*)&sQh[r*20 + w4] = *(const uint4*)&g_Qph[gw];
            *(uint4*)&sQl[r*20 + w4] = *(const uint4*)&g_Qpl[gw];
            __syncthreads();
            if ((warp >> 2) == half) {
                const int wl = warp & 3;
                #pragma unroll
                for (int ck = 0; ck < 2; ck++) {
                    const unsigned offq = ((wl*16 + arow)*20 + ck*8 + awof) << 2;
                    ldsm4(qh[ck], aQh + offq);
                    ldsm4(ql[ck], aQl + offq);
                }
            }
            __syncthreads();
        }
    }

    const int qrow = q0 + (warp & 3)*16 + (warp >> 2)*64 + g;
    const float* triP0 = g_TRI + hbase + (size_t)qrow*NN;
    const float* triP1 = triP0 + (size_t)8*NN;

    float l0 = 0.f, l1 = 0.f;
    float oacc[4][4];
    #pragma unroll
    for (int a = 0; a < 4; a++)
        #pragma unroll
        for (int b = 0; b < 4; b++) oacc[a][b] = 0.f;

    const int fr  = tid >> 2,  fw  = (tid & 3) << 2;
    const int fvr = tid >> 3,  fvw = (tid & 7) << 2;

    {
        unsigned* st = sha;
        const size_t gw = (hbase + rowbase + 0 + fr)*16 + fw;
        cp16(sm_u32(st + fr*20 + fw),        &g_Kph[gw]);
        cp16(sm_u32(st + 1280 + fr*20 + fw), &g_Kpl[gw]);
        const size_t mw0 = rowbase >> 1;
        cp16(sm_u32(st + 2560 + fvr*36 + fvw), &g_Vt[((size_t)(h*CH + fvr))*MW + mw0 + fvw]);
        cp_commit();
    }

    for (int t = 0; t < 6; t++) {
        const int cur = t & 1;
        if (t < 5) {
            unsigned* st = sha + (1-cur)*STG_W;
            const int kbn = (t+1)*64;
            const size_t gw = (hbase + rowbase + kbn + fr)*16 + fw;
            cp16(sm_u32(st + fr*20 + fw),        &g_Kph[gw]);
            cp16(sm_u32(st + 1280 + fr*20 + fw), &g_Kpl[gw]);
            const size_t mw0 = (rowbase + kbn) >> 1;
            cp16(sm_u32(st + 2560 + fvr*36 + fvw), &g_Vt[((size_t)(h*CH + fvr))*MW + mw0 + fvw]);
            cp_commit();
            cp_wait1();
        } else {
            cp_wait0();
        }
        __syncthreads();

        const unsigned aKh = sm_u32(sha + cur*STG_W);
        const unsigned aKl = aKh + 1280*4;
        const unsigned aVt = aKh + 2560*4;
        const int kb = t*64;

        float s[8][4];
        #pragma unroll
        for (int a = 0; a < 8; a++)
            #pragma unroll
            for (int b = 0; b < 4; b++) s[a][b] = 0.f;

        #pragma unroll
        for (int ck = 0; ck < 2; ck++) {
            #pragma unroll
            for (int p = 0; p < 4; p++) {
                const unsigned off = ((p*16 + krow)*20 + ck*8 + kwof) << 2;
                unsigned bh[4], bl[4];
                ldsm4(bh, aKh + off);
                ldsm4(bl, aKl + off);
                mma16(s[2*p],   qh[ck], bh);
                mma16(s[2*p],   qh[ck], bl);
                mma16(s[2*p],   ql[ck], bh);
                mma16(s[2*p+1], qh[ck], bh+2);
                mma16(s[2*p+1], qh[ck], bl+2);
                mma16(s[2*p+1], ql[ck], bh+2);
            }
        }

        #pragma unroll
        for (int nt = 0; nt < 8; nt++) {
            const int col = nt*8 + 2*tg;
            const float2 t0 = *(const float2*)&triP0[kb + col];
            const float2 t1 = *(const float2*)&triP1[kb + col];
            const float2 mb = *(const float2*)&sMbAll[kb + col];
            s[nt][0] = __expf(s[nt][0] + t0.x + mb.x);
            s[nt][1] = __expf(s[nt][1] + t0.y + mb.y);
            s[nt][2] = __expf(s[nt][2] + t1.x + mb.x);
            s[nt][3] = __expf(s[nt][3] + t1.y + mb.y);
            l0 += s[nt][0] + s[nt][1];
            l1 += s[nt][2] + s[nt][3];
        }

        #pragma unroll
        for (int j = 0; j < 4; j++) {
            unsigned a[4];
            a[0] = pack2h(s[2*j  ][0], s[2*j  ][1]);
            a[1] = pack2h(s[2*j  ][2], s[2*j  ][3]);
            a[2] = pack2h(s[2*j+1][0], s[2*j+1][1]);
            a[3] = pack2h(s[2*j+1][2], s[2*j+1][3]);
            #pragma unroll
            for (int p = 0; p < 2; p++) {
                const unsigned off = ((p*16 + krow)*36 + j*8 + kwof) << 2;
                unsigned b[4];
                ldsm4(b, aVt + off);
                mma16h(oacc[2*p],   a, b);
                mma16h(oacc[2*p+1], a, b+2);
            }
        }
        __syncthreads();
    }

    l0 += __shfl_xor_sync(0xffffffffu, l0, 1);
    l0 += __shfl_xor_sync(0xffffffffu, l0, 2);
    l1 += __shfl_xor_sync(0xffffffffu, l1, 1);
    l1 += __shfl_xor_sync(0xffffffffu, l1, 2);

    const float inv0 = 1.f/l0, inv1 = 1.f/l1;
    const size_t ob0 = (rowbase + qrow)*CIN + h*CH;
    const size_t ob1 = (rowbase + qrow + 8)*CIN + h*CH;
    #pragma unroll
    for (int nt = 0; nt < 4; nt++) {
        const int col = nt*8 + 2*tg;
        *(float2*)&g_O[ob0 + col] = make_float2(oacc[nt][0]*inv0, oacc[nt][1]*inv0);
        *(float2*)&g_O[ob1 + col] = make_float2(oacc[nt][2]*inv1, oacc[nt][3]*inv1);
    }
}

// =====================================================================
// GEMM 3: out = (O*G) @ wo, fp16 m16n8k16, ldmatrix loads.
// =====================================================================
__global__ void __launch_bounds__(128, 6)
outproj_mma_kernel(float* __restrict__ out)
{
    extern __shared__ unsigned sho[];
    unsigned* sA = sho;             // [64][20] words
    unsigned* sB = sA + 64*20;      // [64][20]

    const int tid  = threadIdx.x;
    const int warp = tid >> 5, lane = tid & 31;
    const int g = lane >> 2, tg = lane & 3;
    const int wm = warp >> 1, wn = warp & 1;
    const int n0 = blockIdx.x * 64;
    const int m0 = blockIdx.y * 64;

    const unsigned aA = sm_u32(sA), aB = sm_u32(sB);
    const int arow = ((lane>>3)&1)*8 + (lane&7);
    const int awof = (lane>>4)*4;
    const int krow = ((lane>>4)&1)*8 + (lane&7);
    const int kwof = ((lane>>3)&1)*4;

    float acc[2][4][4];
    #pragma unroll
    for (int a = 0; a < 2; a++)
        #pragma unroll
        for (int b = 0; b < 4; b++)
            #pragma unroll
            for (int c = 0; c < 4; c++) acc[a][b][c] = 0.f;

    for (int kc = 0; kc < 128; kc += 32) {
        __syncthreads();
        for (int idx = tid; idx < 512; idx += 128) {
            const int ra = idx >> 3, ca = (idx & 7) << 2;
            const size_t ga = (size_t)(m0+ra)*CIN + kc + ca;
            const float4 o4 = *(const float4*)&g_O[ga];
            const float4 g4 = *(const float4*)&g_G[ga];
            sA[ra*20 + (ca>>1)    ] = pack2h(o4.x*g4.x, o4.y*g4.y);
            sA[ra*20 + (ca>>1) + 1] = pack2h(o4.z*g4.z, o4.w*g4.w);
        }
        for (int idx = tid; idx < 256; idx += 128) {
            const int r = idx >> 2, w4 = (idx & 3) << 2;
            *(uint4*)&sB[r*20 + w4] = *(const uint4*)&g_WOt[(size_t)(n0+r)*64 + (kc>>1) + w4];
        }
        __syncthreads();
        #pragma unroll
        for (int ck = 0; ck < 2; ck++) {
            const int w0 = ck*8;
            unsigned ah[2][4];
            #pragma unroll
            for (int mt = 0; mt < 2; mt++)
                ldsm4(ah[mt], aA + (((wm*32 + mt*16 + arow)*20 + w0 + awof) << 2));
            #pragma unroll
            for (int p = 0; p < 2; p++) {
                unsigned b[4];
                ldsm4(b, aB + (((wn*32 + p*16 + krow)*20 + w0 + kwof) << 2));
                #pragma unroll
                for (int mt = 0; mt < 2; mt++) {
                    mma16h(acc[mt][2*p],   ah[mt], b);
                    mma16h(acc[mt][2*p+1], ah[mt], b+2);
                }
            }
        }
    }

    #pragma unroll
    for (int mt = 0; mt < 2; mt++) {
        const int r0 = m0 + wm*32 + mt*16 + g;
        #pragma unroll
        for (int nt = 0; nt < 4; nt++) {
            const int col = n0 + wn*32 + nt*8 + 2*tg;
            *(float2*)&out[(size_t)r0*CIN + col]     = make_float2(acc[mt][nt][0], acc[mt][nt][1]);
            *(float2*)&out[(size_t)(r0+8)*CIN + col] = make_float2(acc[mt][nt][2], acc[mt][nt][3]);
        }
    }
}

// =====================================================================
// launch
// =====================================================================
extern "C" void kernel_launch(void* const* d_in, const int* in_sizes, int n_in,
                              void* d_out, int out_size)
{
    (void)in_sizes; (void)n_in; (void)out_size;
    const float* z    = (const float*)d_in[0];
    const float* mask = (const float*)d_in[1];
    const float* lnw  = (const float*)d_in[2];
    const float* lnb  = (const float*)d_in[3];
    const float* wtri = (const float*)d_in[4];
    const float* wq   = (const float*)d_in[5];
    const float* wk   = (const float*)d_in[6];
    const float* wv   = (const float*)d_in[7];
    const float* wg   = (const float*)d_in[8];
    const float* wo   = (const float*)d_in[9];

    const size_t proj_sh = (size_t)(2*PSTG_W) * 4;                // 40960
    const size_t attn_sh = (size_t)(2*STG_W) * 4 + NN*4;          // 31232
    const size_t out_sh  = (size_t)(2*64*20) * 4;                 // 10240

    wsplit_kernel<<<(WCOLS*64 + CIN*64 + 255)/256, 256>>>(wq, wk, wv, wg, wtri, wo);
    ln_split_kernel<<<M_TOT/8, 256>>>(z, lnw, lnb);
    proj_mma_kernel<<<dim3(9, M_TOT/64), 128, proj_sh>>>();
    attn_mma_kernel<<<dim3(NN/128, NN, NH), 256, attn_sh>>>(mask);
    outproj_mma_kernel<<<dim3(2, M_TOT/64), 128, out_sh>>>((float*)d_out);
}

// round 10
// speedup vs baseline: 3.3883x; 1.0051x over previous
#include <cuda_runtime.h>
#include <cuda_bf16.h>
#include <cuda_fp16.h>
#include <math.h>

// ---------------- problem constants ----------------
#define NN   384
#define CIN  128
#define NH   4
#define CH   32
#define M_TOT (NN*NN)                   // 147456
#define MW   (M_TOT/2)
#define QK_SCALE 0.17677669529663687f   // 1/sqrt(32)
#define WCOLS 576                        // 512 proj cols + 4 tri + pad
#define MPT  36                          // m-tiles per proj block (2304/36 = 64)

// ---------------- scratch (device globals; no allocs) ----------------
__device__ unsigned g_Ah[(size_t)M_TOT*64];      // LN(z) bf16x2 hi plane
__device__ unsigned g_Al[(size_t)M_TOT*64];      // lo plane
__device__ unsigned g_Wth[(size_t)WCOLS*64];     // weights^T packed bf16x2 hi
__device__ unsigned g_Wtl[(size_t)WCOLS*64];
__device__ unsigned g_WOt[(size_t)CIN*64];       // wo^T packed half2
__device__ unsigned g_Qph[(size_t)NH*M_TOT*16];  // Q head-major bf16x2 hi/lo
__device__ unsigned g_Qpl[(size_t)NH*M_TOT*16];
__device__ unsigned g_Kph[(size_t)NH*M_TOT*16];
__device__ unsigned g_Kpl[(size_t)NH*M_TOT*16];
__device__ unsigned g_Vt [(size_t)NH*CH*MW];     // V^T packed half2 [h][c][m/2]
__device__ float g_G  [(size_t)M_TOT*CIN];       // sigmoid gate
__device__ float g_TRI[(size_t)NH*M_TOT];
__device__ float g_O  [(size_t)M_TOT*CIN];       // attn out, m-major

// ---------------- helpers ----------------
__device__ __forceinline__ unsigned pack2h(float a, float b) {
    __half2 t = __floats2half2_rn(a, b);
    return *(unsigned*)&t;
}
__device__ __forceinline__ unsigned packbf(float a, float b) {
    __nv_bfloat162 t = __floats2bfloat162_rn(a, b);
    return *(unsigned*)&t;
}
__device__ __forceinline__ void splitbf2(float a, float b, unsigned& hw, unsigned& lw) {
    __nv_bfloat16 ha = __float2bfloat16_rn(a);
    __nv_bfloat16 hb = __float2bfloat16_rn(b);
    float ra = a - __bfloat162float(ha);
    float rb = b - __bfloat162float(hb);
    __nv_bfloat162 h; h.x = ha; h.y = hb;
    hw = *(unsigned*)&h;
    lw = packbf(ra, rb);
}
__device__ __forceinline__ unsigned sm_u32(const void* p) {
    return (unsigned)__cvta_generic_to_shared(p);
}
__device__ __forceinline__ void ldsm4(unsigned* r, unsigned addr) {
    asm volatile("ldmatrix.sync.aligned.m8n8.x4.shared.b16 {%0,%1,%2,%3}, [%4];"
        : "=r"(r[0]), "=r"(r[1]), "=r"(r[2]), "=r"(r[3]) : "r"(addr));
}
__device__ __forceinline__ void cp16(unsigned saddr, const void* gptr) {
    asm volatile("cp.async.cg.shared.global [%0], [%1], 16;" :: "r"(saddr), "l"(gptr));
}
__device__ __forceinline__ void cp_commit() { asm volatile("cp.async.commit_group;"); }
__device__ __forceinline__ void cp_wait0()  { asm volatile("cp.async.wait_group 0;"); }
__device__ __forceinline__ void cp_wait1()  { asm volatile("cp.async.wait_group 1;"); }
// bf16 m16n8k16
__device__ __forceinline__ void mma16(float* d, const unsigned* a, const unsigned* b) {
    asm volatile(
        "mma.sync.aligned.m16n8k16.row.col.f32.bf16.bf16.f32 "
        "{%0,%1,%2,%3},{%4,%5,%6,%7},{%8,%9},{%0,%1,%2,%3};\n"
        : "+f"(d[0]), "+f"(d[1]), "+f"(d[2]), "+f"(d[3])
        : "r"(a[0]), "r"(a[1]), "r"(a[2]), "r"(a[3]), "r"(b[0]), "r"(b[1]));
}
// fp16 m16n8k16
__device__ __forceinline__ void mma16h(float* d, const unsigned* a, const unsigned* b) {
    asm volatile(
        "mma.sync.aligned.m16n8k16.row.col.f32.f16.f16.f32 "
        "{%0,%1,%2,%3},{%4,%5,%6,%7},{%8,%9},{%0,%1,%2,%3};\n"
        : "+f"(d[0]), "+f"(d[1]), "+f"(d[2]), "+f"(d[3])
        : "r"(a[0]), "r"(a[1]), "r"(a[2]), "r"(a[3]), "r"(b[0]), "r"(b[1]));
}

// =====================================================================
// prep 1: LayerNorm + bf16-split pack (1 warp per row)
// =====================================================================
__global__ void __launch_bounds__(256)
ln_split_kernel(const float* __restrict__ z,
                const float* __restrict__ lnw, const float* __restrict__ lnb)
{
    const int row  = blockIdx.x*8 + (threadIdx.x >> 5);
    const int lane = threadIdx.x & 31;
    const float4 v = *(const float4*)(z + (size_t)row*CIN + lane*4);
    float s1 = v.x+v.y+v.z+v.w;
    float s2 = v.x*v.x + v.y*v.y + v.z*v.z + v.w*v.w;
    #pragma unroll
    for (int o = 16; o; o >>= 1) {
        s1 += __shfl_xor_sync(0xffffffffu, s1, o);
        s2 += __shfl_xor_sync(0xffffffffu, s2, o);
    }
    const float mu  = s1 * (1.f/128.f);
    const float var = s2 * (1.f/128.f) - mu*mu;
    const float inv = rsqrtf(var + 1e-5f);
    const float4 w = *(const float4*)(lnw + lane*4);
    const float4 b = *(const float4*)(lnb + lane*4);
    const float y0 = (v.x-mu)*inv*w.x + b.x;
    const float y1 = (v.y-mu)*inv*w.y + b.y;
    const float y2 = (v.z-mu)*inv*w.z + b.z;
    const float y3 = (v.w-mu)*inv*w.w + b.w;
    unsigned h0,l0,h1,l1;
    splitbf2(y0,y1,h0,l0);
    splitbf2(y2,y3,h1,l1);
    const size_t base = (size_t)row*64 + lane*2;
    g_Ah[base] = h0; g_Ah[base+1] = h1;
    g_Al[base] = l0; g_Al[base+1] = l1;
}

// =====================================================================
// prep 2: weights -> transposed packed bf16 planes; wo -> packed half2
// =====================================================================
__global__ void __launch_bounds__(256)
wsplit_kernel(const float* __restrict__ wq, const float* __restrict__ wk,
              const float* __restrict__ wv, const float* __restrict__ wg,
              const float* __restrict__ wtri, const float* __restrict__ wo)
{
    const int idx = blockIdx.x*256 + threadIdx.x;
    if (idx < WCOLS*64) {
        const int n = idx >> 6, kw = idx & 63;
        const int k0 = kw*2;
        float v0, v1;
        if      (n < 128) { v0 = wq[k0*128 + n];          v1 = wq[(k0+1)*128 + n]; }
        else if (n < 256) { v0 = wk[k0*128 + n-128];      v1 = wk[(k0+1)*128 + n-128]; }
        else if (n < 384) { v0 = wv[k0*128 + n-256];      v1 = wv[(k0+1)*128 + n-256]; }
        else if (n < 512) { v0 = wg[k0*128 + n-384];      v1 = wg[(k0+1)*128 + n-384]; }
        else if (n < 516) { v0 = wtri[k0*4 + n-512];      v1 = wtri[(k0+1)*4 + n-512]; }
        else              { v0 = 0.f; v1 = 0.f; }
        unsigned hw, lw; splitbf2(v0, v1, hw, lw);
        g_Wth[idx] = hw; g_Wtl[idx] = lw;
    } else if (idx < WCOLS*64 + CIN*64) {
        const int j = idx - WCOLS*64;
        const int n = j >> 6, kw = j & 63;
        g_WOt[j] = pack2h(wo[(2*kw)*128 + n], wo[(2*kw+1)*128 + n]);
    }
}

// =====================================================================
// GEMM 1 (persistent, weight-stationary): each block owns one n-column
// (B hi/lo resident, full K) and streams MPT m-tiles of A through a
// 2-stage cp.async pipeline.
// smem layout (words): Bh[64][68] | Bl[64][68] | stage0(Ah[64][20]|Al) | stage1
// =====================================================================
#define PROJ_B_W   (64*68)             // 4352 per plane
#define PROJ_STGW  (2*64*20)           // 2560 per A stage
#define PROJ_SH_W  (2*PROJ_B_W + 2*PROJ_STGW)   // 13824 words = 55296 B
__global__ void __launch_bounds__(128, 4)
proj_mma_kernel()
{
    extern __shared__ unsigned shp[];
    unsigned* sBh = shp;
    unsigned* sBl = shp + PROJ_B_W;
    unsigned* sA  = shp + 2*PROJ_B_W;   // two stages of 2560 words

    const int tid  = threadIdx.x;
    const int warp = tid >> 5, lane = tid & 31;
    const int g = lane >> 2, tg = lane & 3;
    const int wm = warp >> 1, wn = warp & 1;
    const int ntb = blockIdx.x;            // 0..8
    const int n0  = ntb * 64;
    const int kind = ntb >> 1;             // 0=Q 1=K 2=V 3=G (ntb==8 -> tri)
    const bool isV = (ntb == 4 || ntb == 5);

    const int arow = ((lane>>3)&1)*8 + (lane&7);
    const int awof = (lane>>4)*4;
    const int krow = ((lane>>4)&1)*8 + (lane&7);
    const int kwof = ((lane>>3)&1)*4;

    const int fr0 = tid >> 1, fw0 = (tid & 1) << 3;
    const int NCHUNK = 4*MPT;

    // ---- prologue: B (both planes) + A chunk0 as group0; A chunk1 as group1
    for (int idx = tid; idx < 1024; idx += 128) {
        const int r = idx >> 4, w4 = (idx & 15) << 2;
        cp16(sm_u32(sBh + r*68 + w4), &g_Wth[(size_t)(n0+r)*64 + w4]);
        cp16(sm_u32(sBl + r*68 + w4), &g_Wtl[(size_t)(n0+r)*64 + w4]);
    }
    {
        const int mtg = blockIdx.y*MPT;          // chunk 0: m-tile 0, kc 0
        unsigned* st = sA;
        #pragma unroll
        for (int half = 0; half < 2; half++) {
            const int fw = fw0 + half*4;
            const size_t ga = (size_t)(mtg*64 + fr0)*64 + 0 + fw;
            cp16(sm_u32(st +        fr0*20 + fw), &g_Ah[ga]);
            cp16(sm_u32(st + 1280 + fr0*20 + fw), &g_Al[ga]);
        }
        cp_commit();
    }
    {
        const int mtg = blockIdx.y*MPT;          // chunk 1: m-tile 0, kc 1
        unsigned* st = sA + PROJ_STGW;
        #pragma unroll
        for (int half = 0; half < 2; half++) {
            const int fw = fw0 + half*4;
            const size_t ga = (size_t)(mtg*64 + fr0)*64 + 16 + fw;
            cp16(sm_u32(st +        fr0*20 + fw), &g_Ah[ga]);
            cp16(sm_u32(st + 1280 + fr0*20 + fw), &g_Al[ga]);
        }
        cp_commit();
    }

    const unsigned aBh = sm_u32(sBh), aBl = sm_u32(sBl);

    for (int mt_i = 0; mt_i < MPT; mt_i++) {
        const int m0 = (blockIdx.y*MPT + mt_i)*64;

        float acc[2][4][4];
        #pragma unroll
        for (int a = 0; a < 2; a++)
            #pragma unroll
            for (int b = 0; b < 4; b++)
                #pragma unroll
                for (int c = 0; c < 4; c++) acc[a][b][c] = 0.f;

        #pragma unroll
        for (int kc = 0; kc < 4; kc++) {
            const int c = mt_i*4 + kc;
            if (c == NCHUNK-1) cp_wait0(); else cp_wait1();
            __syncthreads();

            const unsigned aAh = sm_u32(sA + (c&1)*PROJ_STGW);
            const unsigned aAl = aAh + 1280*4;
            const int kw0 = kc*16;

            #pragma unroll
            for (int sub = 0; sub < 2; sub++) {
                const int w0 = sub*8;
                unsigned ah[2][4], al[2][4];
                #pragma unroll
                for (int mt = 0; mt < 2; mt++) {
                    const unsigned offa = ((wm*32 + mt*16 + arow)*20 + w0 + awof) << 2;
                    ldsm4(ah[mt], aAh + offa);
                    ldsm4(al[mt], aAl + offa);
                }
                #pragma unroll
                for (int p = 0; p < 2; p++) {
                    const unsigned offb = ((wn*32 + p*16 + krow)*68 + kw0 + w0 + kwof) << 2;
                    unsigned bh[4], bl[4];
                    ldsm4(bh, aBh + offb);
                    ldsm4(bl, aBl + offb);
                    #pragma unroll
                    for (int mt = 0; mt < 2; mt++) {
                        mma16(acc[mt][2*p],   ah[mt], bh);
                        mma16(acc[mt][2*p],   ah[mt], bl);
                        mma16(acc[mt][2*p],   al[mt], bh);
                        mma16(acc[mt][2*p+1], ah[mt], bh+2);
                        mma16(acc[mt][2*p+1], ah[mt], bl+2);
                        mma16(acc[mt][2*p+1], al[mt], bh+2);
                    }
                }
            }
            __syncthreads();

            // prefetch chunk c+2 into stage c&1 (V blocks postpone the kc==3 one)
            const int cn = c + 2;
            if (cn < NCHUNK && !(isV && kc == 3)) {
                unsigned* st = sA + (c&1)*PROJ_STGW;
                const int mtg = blockIdx.y*MPT + (cn >> 2);
                const int kw  = (cn & 3)*16;
                #pragma unroll
                for (int half = 0; half < 2; half++) {
                    const int fw = fw0 + half*4;
                    const size_t ga = (size_t)(mtg*64 + fr0)*64 + kw + fw;
                    cp16(sm_u32(st +        fr0*20 + fw), &g_Ah[ga]);
                    cp16(sm_u32(st + 1280 + fr0*20 + fw), &g_Al[ga]);
                }
                cp_commit();
            }
        }

        // ---- per-m-tile epilogue ----
        if (ntb < 8) {
            const int cbase = (ntb & 1)*64;
            if (isV) {
                // fused V transpose via the just-consumed stage 1 buffer
                __half* tileV = (__half*)(sA + PROJ_STGW);
                #pragma unroll
                for (int mt = 0; mt < 2; mt++) {
                    const int lm = wm*32 + mt*16 + g;
                    #pragma unroll
                    for (int nt = 0; nt < 4; nt++) {
                        const int lc = wn*32 + nt*8 + 2*tg;
                        *(__half2*)&tileV[lm*64 + lc] =
                            __floats2half2_rn(acc[mt][nt][0], acc[mt][nt][1]);
                        *(__half2*)&tileV[(lm+8)*64 + lc] =
                            __floats2half2_rn(acc[mt][nt][2], acc[mt][nt][3]);
                    }
                }
                __syncthreads();
                const int lc = tid >> 1;
                const int mh = tid & 1;
                const int h  = (ntb - 4)*2 + (lc >> 5);
                const int c  = lc & 31;
                unsigned w[16];
                #pragma unroll
                for (int j = 0; j < 16; j++) {
                    const int m2 = mh*16 + j;
                    __half2 t2; t2.x = tileV[(2*m2)*64 + lc]; t2.y = tileV[(2*m2+1)*64 + lc];
                    w[j] = *(unsigned*)&t2;
                }
                const size_t ob = ((size_t)(h*CH + c))*MW + (m0 >> 1) + mh*16;
                *(uint4*)&g_Vt[ob]    = make_uint4(w[0], w[1], w[2], w[3]);
                *(uint4*)&g_Vt[ob+4]  = make_uint4(w[4], w[5], w[6], w[7]);
                *(uint4*)&g_Vt[ob+8]  = make_uint4(w[8], w[9], w[10], w[11]);
                *(uint4*)&g_Vt[ob+12] = make_uint4(w[12], w[13], w[14], w[15]);
                __syncthreads();
                // postponed prefetch of chunk (mt_i*4+3)+2 into stage 1
                const int cn = mt_i*4 + 5;
                if (cn < NCHUNK) {
                    unsigned* st = sA + PROJ_STGW;
                    const int mtg = blockIdx.y*MPT + (cn >> 2);
                    const int kw  = (cn & 3)*16;
                    #pragma unroll
                    for (int half = 0; half < 2; half++) {
                        const int fw = fw0 + half*4;
                        const size_t ga = (size_t)(mtg*64 + fr0)*64 + kw + fw;
                        cp16(sm_u32(st +        fr0*20 + fw), &g_Ah[ga]);
                        cp16(sm_u32(st + 1280 + fr0*20 + fw), &g_Al[ga]);
                    }
                    cp_commit();
                }
            } else {
                #pragma unroll
                for (int mt = 0; mt < 2; mt++) {
                    const int r0 = m0 + wm*32 + mt*16 + g;
                    #pragma unroll
                    for (int nt = 0; nt < 4; nt++) {
                        const int col = cbase + wn*32 + nt*8 + 2*tg;
                        const int h = col >> 5, c0 = col & 31;
                        float v0 = acc[mt][nt][0], v1 = acc[mt][nt][1];
                        float v2 = acc[mt][nt][2], v3 = acc[mt][nt][3];
                        if (kind == 0 || kind == 1) {
                            if (kind == 0) { v0*=QK_SCALE; v1*=QK_SCALE; v2*=QK_SCALE; v3*=QK_SCALE; }
                            unsigned* dh = (kind == 0) ? g_Qph : g_Kph;
                            unsigned* dl = (kind == 0) ? g_Qpl : g_Kpl;
                            const size_t w0i = ((size_t)h*M_TOT + r0)*16 + (c0>>1);
                            const size_t w1i = ((size_t)h*M_TOT + r0 + 8)*16 + (c0>>1);
                            unsigned hw, lw;
                            splitbf2(v0, v1, hw, lw); dh[w0i] = hw; dl[w0i] = lw;
                            splitbf2(v2, v3, hw, lw); dh[w1i] = hw; dl[w1i] = lw;
                        } else {
                            *(float2*)&g_G[(size_t)r0*CIN + col] =
                                make_float2(1.f/(1.f+__expf(-v0)), 1.f/(1.f+__expf(-v1)));
                            *(float2*)&g_G[(size_t)(r0+8)*CIN + col] =
                                make_float2(1.f/(1.f+__expf(-v2)), 1.f/(1.f+__expf(-v3)));
                        }
                    }
                }
            }
        } else if (wn == 0 && tg < 2) {
            #pragma unroll
            for (int mt = 0; mt < 2; mt++) {
                const int r0 = m0 + wm*32 + mt*16 + g;
                const int c0 = 2*tg;
                g_TRI[(size_t)c0*M_TOT     + r0]   = acc[mt][0][0];
                g_TRI[(size_t)(c0+1)*M_TOT + r0]   = acc[mt][0][1];
                g_TRI[(size_t)c0*M_TOT     + r0+8] = acc[mt][0][2];
                g_TRI[(size_t)(c0+1)*M_TOT + r0+8] = acc[mt][0][3];
            }
        }
    }
}

// =====================================================================
// flash attention, 128 queries/block (8 warps), cp.async double-buffered
// K/V stages, S = split-bf16, PV = fp16, ldmatrix operand loads.
// stage s (3712 words): Kh [64][20] | Kl [64][20] | Vt [32][36]
// =====================================================================
#define STG_W 3712
__global__ void __launch_bounds__(256, 2)
attn_mma_kernel(const float* __restrict__ mask)
{
    extern __shared__ unsigned sha[];
    float* sMbAll = (float*)(sha + 2*STG_W);   // [384]

    const int tid  = threadIdx.x;
    const int warp = tid >> 5, lane = tid & 31;
    const int g = lane >> 2, tg = lane & 3;
    const int q0 = blockIdx.x * 128;
    const int i  = blockIdx.y;
    const int h  = blockIdx.z;
    const size_t rowbase = (size_t)i * NN;
    const size_t hbase   = (size_t)h * M_TOT;

    const int arow = ((lane>>3)&1)*8 + (lane&7);
    const int awof = (lane>>4)*4;
    const int krow = ((lane>>4)&1)*8 + (lane&7);
    const int kwof = ((lane>>3)&1)*4;

    for (int idx = tid; idx < NN; idx += 256)
        sMbAll[idx] = 1e9f * (mask[rowbase + idx] - 1.f);

    // ---- stage Q (two passes through stage0 K buffers) ----
    unsigned qh[2][4], ql[2][4];
    {
        unsigned* sQh = sha;
        unsigned* sQl = sha + 1280;
        const unsigned aQh = sm_u32(sQh), aQl = sm_u32(sQl);
        #pragma unroll
        for (int half = 0; half < 2; half++) {
            const int r = tid >> 2, w4 = (tid & 3) << 2;
            const size_t gw = (hbase + rowbase + q0 + half*64 + r)*16 + w4;
            *(uint4*)&sQh[r*20 + w4] = *(const uint4*)&g_Qph[gw];
            *(uint4*)&sQl[r*20 + w4] = *(const uint4*)&g_Qpl[gw];
            __syncthreads();
            if ((warp >> 2) == half) {
                const int wl = warp & 3;
                #pragma unroll
                for (int ck = 0; ck < 2; ck++) {
                    const unsigned offq = ((wl*16 + arow)*20 + ck*8 + awof) << 2;
                    ldsm4(qh[ck], aQh + offq);
                    ldsm4(ql[ck], aQl + offq);
                }
            }
            __syncthreads();
        }
    }

    const int qrow = q0 + (warp & 3)*16 + (warp >> 2)*64 + g;
    const float* triP0 = g_TRI + hbase + (size_t)qrow*NN;
    const float* triP1 = triP0 + (size_t)8*NN;

    float l0 = 0.f, l1 = 0.f;
    float oacc[4][4];
    #pragma unroll
    for (int a = 0; a < 4; a++)
        #pragma unroll
        for (int b = 0; b < 4; b++) oacc[a][b] = 0.f;

    const int fr  = tid >> 2,  fw  = (tid & 3) << 2;
    const int fvr = tid >> 3,  fvw = (tid & 7) << 2;

    {
        unsigned* st = sha;
        const size_t gw = (hbase + rowbase + 0 + fr)*16 + fw;
        cp16(sm_u32(st + fr*20 + fw),        &g_Kph[gw]);
        cp16(sm_u32(st + 1280 + fr*20 + fw), &g_Kpl[gw]);
        const size_t mw0 = rowbase >> 1;
        cp16(sm_u32(st + 2560 + fvr*36 + fvw), &g_Vt[((size_t)(h*CH + fvr))*MW + mw0 + fvw]);
        cp_commit();
    }

    for (int t = 0; t < 6; t++) {
        const int cur = t & 1;
        if (t < 5) {
            unsigned* st = sha + (1-cur)*STG_W;
            const int kbn = (t+1)*64;
            const size_t gw = (hbase + rowbase + kbn + fr)*16 + fw;
            cp16(sm_u32(st + fr*20 + fw),        &g_Kph[gw]);
            cp16(sm_u32(st + 1280 + fr*20 + fw), &g_Kpl[gw]);
            const size_t mw0 = (rowbase + kbn) >> 1;
            cp16(sm_u32(st + 2560 + fvr*36 + fvw), &g_Vt[((size_t)(h*CH + fvr))*MW + mw0 + fvw]);
            cp_commit();
            cp_wait1();
        } else {
            cp_wait0();
        }
        __syncthreads();

        const unsigned aKh = sm_u32(sha + cur*STG_W);
        const unsigned aKl = aKh + 1280*4;
        const unsigned aVt = aKh + 2560*4;
        const int kb = t*64;

        float s[8][4];
        #pragma unroll
        for (int a = 0; a < 8; a++)
            #pragma unroll
            for (int b = 0; b < 4; b++) s[a][b] = 0.f;

        #pragma unroll
        for (int ck = 0; ck < 2; ck++) {
            #pragma unroll
            for (int p = 0; p < 4; p++) {
                const unsigned off = ((p*16 + krow)*20 + ck*8 + kwof) << 2;
                unsigned bh[4], bl[4];
                ldsm4(bh, aKh + off);
                ldsm4(bl, aKl + off);
                mma16(s[2*p],   qh[ck], bh);
                mma16(s[2*p],   qh[ck], bl);
                mma16(s[2*p],   ql[ck], bh);
                mma16(s[2*p+1], qh[ck], bh+2);
                mma16(s[2*p+1], qh[ck], bl+2);
                mma16(s[2*p+1], ql[ck], bh+2);
            }
        }

        #pragma unroll
        for (int nt = 0; nt < 8; nt++) {
            const int col = nt*8 + 2*tg;
            const float2 t0 = *(const float2*)&triP0[kb + col];
            const float2 t1 = *(const float2*)&triP1[kb + col];
            const float2 mb = *(const float2*)&sMbAll[kb + col];
            s[nt][0] = __expf(s[nt][0] + t0.x + mb.x);
            s[nt][1] = __expf(s[nt][1] + t0.y + mb.y);
            s[nt][2] = __expf(s[nt][2] + t1.x + mb.x);
            s[nt][3] = __expf(s[nt][3] + t1.y + mb.y);
            l0 += s[nt][0] + s[nt][1];
            l1 += s[nt][2] + s[nt][3];
        }

        #pragma unroll
        for (int j = 0; j < 4; j++) {
            unsigned a[4];
            a[0] = pack2h(s[2*j  ][0], s[2*j  ][1]);
            a[1] = pack2h(s[2*j  ][2], s[2*j  ][3]);
            a[2] = pack2h(s[2*j+1][0], s[2*j+1][1]);
            a[3] = pack2h(s[2*j+1][2], s[2*j+1][3]);
            #pragma unroll
            for (int p = 0; p < 2; p++) {
                const unsigned off = ((p*16 + krow)*36 + j*8 + kwof) << 2;
                unsigned b[4];
                ldsm4(b, aVt + off);
                mma16h(oacc[2*p],   a, b);
                mma16h(oacc[2*p+1], a, b+2);
            }
        }
        __syncthreads();
    }

    l0 += __shfl_xor_sync(0xffffffffu, l0, 1);
    l0 += __shfl_xor_sync(0xffffffffu, l0, 2);
    l1 += __shfl_xor_sync(0xffffffffu, l1, 1);
    l1 += __shfl_xor_sync(0xffffffffu, l1, 2);

    const float inv0 = 1.f/l0, inv1 = 1.f/l1;
    const size_t ob0 = (rowbase + qrow)*CIN + h*CH;
    const size_t ob1 = (rowbase + qrow + 8)*CIN + h*CH;
    #pragma unroll
    for (int nt = 0; nt < 4; nt++) {
        const int col = nt*8 + 2*tg;
        *(float2*)&g_O[ob0 + col] = make_float2(oacc[nt][0]*inv0, oacc[nt][1]*inv0);
        *(float2*)&g_O[ob1 + col] = make_float2(oacc[nt][2]*inv1, oacc[nt][3]*inv1);
    }
}

// =====================================================================
// GEMM 3: out = (O*G) @ wo, fp16 m16n8k16, ldmatrix loads.
// =====================================================================
__global__ void __launch_bounds__(128, 6)
outproj_mma_kernel(float* __restrict__ out)
{
    extern __shared__ unsigned sho[];
    unsigned* sA = sho;             // [64][20] words
    unsigned* sB = sA + 64*20;      // [64][20]

    const int tid  = threadIdx.x;
    const int warp = tid >> 5, lane = tid & 31;
    const int g = lane >> 2, tg = lane & 3;
    const int wm = warp >> 1, wn = warp & 1;
    const int n0 = blockIdx.x * 64;
    const int m0 = blockIdx.y * 64;

    const unsigned aA = sm_u32(sA), aB = sm_u32(sB);
    const int arow = ((lane>>3)&1)*8 + (lane&7);
    const int awof = (lane>>4)*4;
    const int krow = ((lane>>4)&1)*8 + (lane&7);
    const int kwof = ((lane>>3)&1)*4;

    float acc[2][4][4];
    #pragma unroll
    for (int a = 0; a < 2; a++)
        #pragma unroll
        for (int b = 0; b < 4; b++)
            #pragma unroll
            for (int c = 0; c < 4; c++) acc[a][b][c] = 0.f;

    for (int kc = 0; kc < 128; kc += 32) {
        __syncthreads();
        for (int idx = tid; idx < 512; idx += 128) {
            const int ra = idx >> 3, ca = (idx & 7) << 2;
            const size_t ga = (size_t)(m0+ra)*CIN + kc + ca;
            const float4 o4 = *(const float4*)&g_O[ga];
            const float4 g4 = *(const float4*)&g_G[ga];
            sA[ra*20 + (ca>>1)    ] = pack2h(o4.x*g4.x, o4.y*g4.y);
            sA[ra*20 + (ca>>1) + 1] = pack2h(o4.z*g4.z, o4.w*g4.w);
        }
        for (int idx = tid; idx < 256; idx += 128) {
            const int r = idx >> 2, w4 = (idx & 3) << 2;
            *(uint4*)&sB[r*20 + w4] = *(const uint4*)&g_WOt[(size_t)(n0+r)*64 + (kc>>1) + w4];
        }
        __syncthreads();
        #pragma unroll
        for (int ck = 0; ck < 2; ck++) {
            const int w0 = ck*8;
            unsigned ah[2][4];
            #pragma unroll
            for (int mt = 0; mt < 2; mt++)
                ldsm4(ah[mt], aA + (((wm*32 + mt*16 + arow)*20 + w0 + awof) << 2));
            #pragma unroll
            for (int p = 0; p < 2; p++) {
                unsigned b[4];
                ldsm4(b, aB + (((wn*32 + p*16 + krow)*20 + w0 + kwof) << 2));
                #pragma unroll
                for (int mt = 0; mt < 2; mt++) {
                    mma16h(acc[mt][2*p],   ah[mt], b);
                    mma16h(acc[mt][2*p+1], ah[mt], b+2);
                }
            }
        }
    }

    #pragma unroll
    for (int mt = 0; mt < 2; mt++) {
        const int r0 = m0 + wm*32 + mt*16 + g;
        #pragma unroll
        for (int nt = 0; nt < 4; nt++) {
            const int col = n0 + wn*32 + nt*8 + 2*tg;
            *(float2*)&out[(size_t)r0*CIN + col]     = make_float2(acc[mt][nt][0], acc[mt][nt][1]);
            *(float2*)&out[(size_t)(r0+8)*CIN + col] = make_float2(acc[mt][nt][2], acc[mt][nt][3]);
        }
    }
}

// =====================================================================
// launch
// =====================================================================
extern "C" void kernel_launch(void* const* d_in, const int* in_sizes, int n_in,
                              void* d_out, int out_size)
{
    (void)in_sizes; (void)n_in; (void)out_size;
    const float* z    = (const float*)d_in[0];
    const float* mask = (const float*)d_in[1];
    const float* lnw  = (const float*)d_in[2];
    const float* lnb  = (const float*)d_in[3];
    const float* wtri = (const float*)d_in[4];
    const float* wq   = (const float*)d_in[5];
    const float* wk   = (const float*)d_in[6];
    const float* wv   = (const float*)d_in[7];
    const float* wg   = (const float*)d_in[8];
    const float* wo   = (const float*)d_in[9];

    const size_t proj_sh = (size_t)PROJ_SH_W * 4;                 // 55296
    const size_t attn_sh = (size_t)(2*STG_W) * 4 + NN*4;          // 31232
    const size_t out_sh  = (size_t)(2*64*20) * 4;                 // 10240

    static int s_attr_set = 0;
    if (!s_attr_set) {
        cudaFuncSetAttribute(proj_mma_kernel,
                             cudaFuncAttributeMaxDynamicSharedMemorySize, (int)proj_sh);
        s_attr_set = 1;
    }

    wsplit_kernel<<<(WCOLS*64 + CIN*64 + 255)/256, 256>>>(wq, wk, wv, wg, wtri, wo);
    ln_split_kernel<<<M_TOT/8, 256>>>(z, lnw, lnb);
    proj_mma_kernel<<<dim3(9, 2304/MPT), 128, proj_sh>>>();
    attn_mma_kernel<<<dim3(NN/128, NN, NH), 256, attn_sh>>>(mask);
    outproj_mma_kernel<<<dim3(2, M_TOT/64), 128, out_sh>>>((float*)d_out);
}

// round 14
// speedup vs baseline: 3.4129x; 1.0073x over previous
#include <cuda_runtime.h>
#include <cuda_bf16.h>
#include <cuda_fp16.h>
#include <cstdint>
#include <math.h>

// ---------------- problem constants ----------------
#define NN   384
#define CIN  128
#define NH   4
#define CH   32
#define M_TOT (NN*NN)                   // 147456
#define MW   (M_TOT/2)
#define QK_SCALE 0.17677669529663687f   // 1/sqrt(32)
#define LOG2E    1.4426950408889634f
#define WCOLS 576                        // 512 proj cols + 4 tri + pad
#define MPT  36                          // m-tiles per proj block (2304/36 = 64)

// ---------------- scratch (device globals; no allocs) ----------------
__device__ unsigned g_Ah[(size_t)M_TOT*64];      // LN(z) bf16x2 hi plane
__device__ unsigned g_Al[(size_t)M_TOT*64];      // lo plane
__device__ unsigned g_Wth[(size_t)WCOLS*64];     // weights^T packed bf16x2 hi
__device__ unsigned g_Wtl[(size_t)WCOLS*64];
__device__ unsigned g_WOt[(size_t)CIN*64];       // wo^T packed half2
__device__ unsigned g_Qph[(size_t)NH*M_TOT*16];  // Q head-major bf16x2 hi/lo (pre-scaled by log2e)
__device__ unsigned g_Qpl[(size_t)NH*M_TOT*16];
__device__ unsigned g_Kph[(size_t)NH*M_TOT*16];
__device__ unsigned g_Kpl[(size_t)NH*M_TOT*16];
__device__ unsigned g_Vt [(size_t)NH*CH*MW];     // V^T packed half2 [h][c][m/2]
__device__ float g_G  [(size_t)M_TOT*CIN];       // sigmoid gate
__device__ float g_TRI[(size_t)NH*M_TOT];        // tri bias (pre-scaled by log2e)
__device__ float g_O  [(size_t)M_TOT*CIN];       // attn out, m-major

// ---------------- helpers ----------------
__device__ __forceinline__ unsigned pack2h(float a, float b) {
    __half2 t = __floats2half2_rn(a, b);
    return *(unsigned*)&t;
}
__device__ __forceinline__ unsigned packbf(float a, float b) {
    __nv_bfloat162 t = __floats2bfloat162_rn(a, b);
    return *(unsigned*)&t;
}
__device__ __forceinline__ void splitbf2(float a, float b, unsigned& hw, unsigned& lw) {
    __nv_bfloat16 ha = __float2bfloat16_rn(a);
    __nv_bfloat16 hb = __float2bfloat16_rn(b);
    float ra = a - __bfloat162float(ha);
    float rb = b - __bfloat162float(hb);
    __nv_bfloat162 h; h.x = ha; h.y = hb;
    hw = *(unsigned*)&h;
    lw = packbf(ra, rb);
}
__device__ __forceinline__ unsigned sm_u32(const void* p) {
    return (unsigned)__cvta_generic_to_shared(p);
}
__device__ __forceinline__ void ldsm4(unsigned* r, unsigned addr) {
    asm volatile("ldmatrix.sync.aligned.m8n8.x4.shared.b16 {%0,%1,%2,%3}, [%4];"
        : "=r"(r[0]), "=r"(r[1]), "=r"(r[2]), "=r"(r[3]) : "r"(addr));
}
__device__ __forceinline__ void cp16(unsigned saddr, const void* gptr) {
    asm volatile("cp.async.cg.shared.global [%0], [%1], 16;" :: "r"(saddr), "l"(gptr));
}
__device__ __forceinline__ void cp_commit() { asm volatile("cp.async.commit_group;"); }
__device__ __forceinline__ void cp_wait0()  { asm volatile("cp.async.wait_group 0;"); }
__device__ __forceinline__ void cp_wait1()  { asm volatile("cp.async.wait_group 1;"); }
__device__ __forceinline__ float ex2f(float x) {
    float y; asm("ex2.approx.f32 %0, %1;" : "=f"(y) : "f"(x)); return y;
}
// bf16 m16n8k16
__device__ __forceinline__ void mma16(float* d, const unsigned* a, const unsigned* b) {
    asm volatile(
        "mma.sync.aligned.m16n8k16.row.col.f32.bf16.bf16.f32 "
        "{%0,%1,%2,%3},{%4,%5,%6,%7},{%8,%9},{%0,%1,%2,%3};\n"
        : "+f"(d[0]), "+f"(d[1]), "+f"(d[2]), "+f"(d[3])
        : "r"(a[0]), "r"(a[1]), "r"(a[2]), "r"(a[3]), "r"(b[0]), "r"(b[1]));
}
// fp16 m16n8k16
__device__ __forceinline__ void mma16h(float* d, const unsigned* a, const unsigned* b) {
    asm volatile(
        "mma.sync.aligned.m16n8k16.row.col.f32.f16.f16.f32 "
        "{%0,%1,%2,%3},{%4,%5,%6,%7},{%8,%9},{%0,%1,%2,%3};\n"
        : "+f"(d[0]), "+f"(d[1]), "+f"(d[2]), "+f"(d[3])
        : "r"(a[0]), "r"(a[1]), "r"(a[2]), "r"(a[3]), "r"(b[0]), "r"(b[1]));
}

// =====================================================================
// prep 1: LayerNorm + bf16-split pack (1 warp per row)
// =====================================================================
__global__ void __launch_bounds__(256)
ln_split_kernel(const float* __restrict__ z,
                const float* __restrict__ lnw, const float* __restrict__ lnb)
{
    const int row  = blockIdx.x*8 + (threadIdx.x >> 5);
    const int lane = threadIdx.x & 31;
    const float4 v = *(const float4*)(z + (size_t)row*CIN + lane*4);
    float s1 = v.x+v.y+v.z+v.w;
    float s2 = v.x*v.x + v.y*v.y + v.z*v.z + v.w*v.w;
    #pragma unroll
    for (int o = 16; o; o >>= 1) {
        s1 += __shfl_xor_sync(0xffffffffu, s1, o);
        s2 += __shfl_xor_sync(0xffffffffu, s2, o);
    }
    const float mu  = s1 * (1.f/128.f);
    const float var = s2 * (1.f/128.f) - mu*mu;
    const float inv = rsqrtf(var + 1e-5f);
    const float4 w = *(const float4*)(lnw + lane*4);
    const float4 b = *(const float4*)(lnb + lane*4);
    const float y0 = (v.x-mu)*inv*w.x + b.x;
    const float y1 = (v.y-mu)*inv*w.y + b.y;
    const float y2 = (v.z-mu)*inv*w.z + b.z;
    const float y3 = (v.w-mu)*inv*w.w + b.w;
    unsigned h0,l0,h1,l1;
    splitbf2(y0,y1,h0,l0);
    splitbf2(y2,y3,h1,l1);
    const size_t base = (size_t)row*64 + lane*2;
    g_Ah[base] = h0; g_Ah[base+1] = h1;
    g_Al[base] = l0; g_Al[base+1] = l1;
}

// =====================================================================
// prep 2: weights -> transposed packed bf16 planes; wo -> packed half2
// =====================================================================
__global__ void __launch_bounds__(256)
wsplit_kernel(const float* __restrict__ wq, const float* __restrict__ wk,
              const float* __restrict__ wv, const float* __restrict__ wg,
              const float* __restrict__ wtri, const float* __restrict__ wo)
{
    const int idx = blockIdx.x*256 + threadIdx.x;
    if (idx < WCOLS*64) {
        const int n = idx >> 6, kw = idx & 63;
        const int k0 = kw*2;
        float v0, v1;
        if      (n < 128) { v0 = wq[k0*128 + n];          v1 = wq[(k0+1)*128 + n]; }
        else if (n < 256) { v0 = wk[k0*128 + n-128];      v1 = wk[(k0+1)*128 + n-128]; }
        else if (n < 384) { v0 = wv[k0*128 + n-256];      v1 = wv[(k0+1)*128 + n-256]; }
        else if (n < 512) { v0 = wg[k0*128 + n-384];      v1 = wg[(k0+1)*128 + n-384]; }
        else if (n < 516) { v0 = wtri[k0*4 + n-512];      v1 = wtri[(k0+1)*4 + n-512]; }
        else              { v0 = 0.f; v1 = 0.f; }
        unsigned hw, lw; splitbf2(v0, v1, hw, lw);
        g_Wth[idx] = hw; g_Wtl[idx] = lw;
    } else if (idx < WCOLS*64 + CIN*64) {
        const int j = idx - WCOLS*64;
        const int n = j >> 6, kw = j & 63;
        g_WOt[j] = pack2h(wo[(2*kw)*128 + n], wo[(2*kw+1)*128 + n]);
    }
}

// =====================================================================
// GEMM 1 (persistent, weight-stationary): each block owns one n-column
// (B hi/lo resident, full K) and streams MPT m-tiles of A through a
// 2-stage cp.async pipeline.
// =====================================================================
#define PROJ_B_W   (64*68)
#define PROJ_STGW  (2*64*20)
#define PROJ_SH_W  (2*PROJ_B_W + 2*PROJ_STGW)
__global__ void __launch_bounds__(128, 4)
proj_mma_kernel()
{
    extern __shared__ unsigned shp[];
    unsigned* sBh = shp;
    unsigned* sBl = shp + PROJ_B_W;
    unsigned* sA  = shp + 2*PROJ_B_W;

    const int tid  = threadIdx.x;
    const int warp = tid >> 5, lane = tid & 31;
    const int g = lane >> 2, tg = lane & 3;
    const int wm = warp >> 1, wn = warp & 1;
    const int ntb = blockIdx.x;
    const int n0  = ntb * 64;
    const int kind = ntb >> 1;
    const bool isV = (ntb == 4 || ntb == 5);

    const int arow = ((lane>>3)&1)*8 + (lane&7);
    const int awof = (lane>>4)*4;
    const int krow = ((lane>>4)&1)*8 + (lane&7);
    const int kwof = ((lane>>3)&1)*4;

    const int fr0 = tid >> 1, fw0 = (tid & 1) << 3;
    const int NCHUNK = 4*MPT;

    for (int idx = tid; idx < 1024; idx += 128) {
        const int r = idx >> 4, w4 = (idx & 15) << 2;
        cp16(sm_u32(sBh + r*68 + w4), &g_Wth[(size_t)(n0+r)*64 + w4]);
        cp16(sm_u32(sBl + r*68 + w4), &g_Wtl[(size_t)(n0+r)*64 + w4]);
    }
    {
        const int mtg = blockIdx.y*MPT;
        unsigned* st = sA;
        #pragma unroll
        for (int half = 0; half < 2; half++) {
            const int fw = fw0 + half*4;
            const size_t ga = (size_t)(mtg*64 + fr0)*64 + 0 + fw;
            cp16(sm_u32(st +        fr0*20 + fw), &g_Ah[ga]);
            cp16(sm_u32(st + 1280 + fr0*20 + fw), &g_Al[ga]);
        }
        cp_commit();
    }
    {
        const int mtg = blockIdx.y*MPT;
        unsigned* st = sA + PROJ_STGW;
        #pragma unroll
        for (int half = 0; half < 2; half++) {
            const int fw = fw0 + half*4;
            const size_t ga = (size_t)(mtg*64 + fr0)*64 + 16 + fw;
            cp16(sm_u32(st +        fr0*20 + fw), &g_Ah[ga]);
            cp16(sm_u32(st + 1280 + fr0*20 + fw), &g_Al[ga]);
        }
        cp_commit();
    }

    const unsigned aBh = sm_u32(sBh), aBl = sm_u32(sBl);

    for (int mt_i = 0; mt_i < MPT; mt_i++) {
        const int m0 = (blockIdx.y*MPT + mt_i)*64;

        float acc[2][4][4];
        #pragma unroll
        for (int a = 0; a < 2; a++)
            #pragma unroll
            for (int b = 0; b < 4; b++)
                #pragma unroll
                for (int c = 0; c < 4; c++) acc[a][b][c] = 0.f;

        #pragma unroll
        for (int kc = 0; kc < 4; kc++) {
            const int c = mt_i*4 + kc;
            if (c == NCHUNK-1) cp_wait0(); else cp_wait1();
            __syncthreads();

            const unsigned aAh = sm_u32(sA + (c&1)*PROJ_STGW);
            const unsigned aAl = aAh + 1280*4;
            const int kw0 = kc*16;

            #pragma unroll
            for (int sub = 0; sub < 2; sub++) {
                const int w0 = sub*8;
                unsigned ah[2][4], al[2][4];
                #pragma unroll
                for (int mt = 0; mt < 2; mt++) {
                    const unsigned offa = ((wm*32 + mt*16 + arow)*20 + w0 + awof) << 2;
                    ldsm4(ah[mt], aAh + offa);
                    ldsm4(al[mt], aAl + offa);
                }
                #pragma unroll
                for (int p = 0; p < 2; p++) {
                    const unsigned offb = ((wn*32 + p*16 + krow)*68 + kw0 + w0 + kwof) << 2;
                    unsigned bh[4], bl[4];
                    ldsm4(bh, aBh + offb);
                    ldsm4(bl, aBl + offb);
                    #pragma unroll
                    for (int mt = 0; mt < 2; mt++) {
                        mma16(acc[mt][2*p],   ah[mt], bh);
                        mma16(acc[mt][2*p],   ah[mt], bl);
                        mma16(acc[mt][2*p],   al[mt], bh);
                        mma16(acc[mt][2*p+1], ah[mt], bh+2);
                        mma16(acc[mt][2*p+1], ah[mt], bl+2);
                        mma16(acc[mt][2*p+1], al[mt], bh+2);
                    }
                }
            }
            __syncthreads();

            const int cn = c + 2;
            if (cn < NCHUNK && !(isV && kc == 3)) {
                unsigned* st = sA + (c&1)*PROJ_STGW;
                const int mtg = blockIdx.y*MPT + (cn >> 2);
                const int kw  = (cn & 3)*16;
                #pragma unroll
                for (int half = 0; half < 2; half++) {
                    const int fw = fw0 + half*4;
                    const size_t ga = (size_t)(mtg*64 + fr0)*64 + kw + fw;
                    cp16(sm_u32(st +        fr0*20 + fw), &g_Ah[ga]);
                    cp16(sm_u32(st + 1280 + fr0*20 + fw), &g_Al[ga]);
                }
                cp_commit();
            }
        }

        // ---- per-m-tile epilogue ----
        if (ntb < 8) {
            const int cbase = (ntb & 1)*64;
            if (isV) {
                __half* tileV = (__half*)(sA + PROJ_STGW);
                #pragma unroll
                for (int mt = 0; mt < 2; mt++) {
                    const int lm = wm*32 + mt*16 + g;
                    #pragma unroll
                    for (int nt = 0; nt < 4; nt++) {
                        const int lc = wn*32 + nt*8 + 2*tg;
                        *(__half2*)&tileV[lm*64 + lc] =
                            __floats2half2_rn(acc[mt][nt][0], acc[mt][nt][1]);
                        *(__half2*)&tileV[(lm+8)*64 + lc] =
                            __floats2half2_rn(acc[mt][nt][2], acc[mt][nt][3]);
                    }
                }
                __syncthreads();
                const int lc = tid >> 1;
                const int mh = tid & 1;
                const int h  = (ntb - 4)*2 + (lc >> 5);
                const int c  = lc & 31;
                unsigned w[16];
                #pragma unroll
                for (int j = 0; j < 16; j++) {
                    const int m2 = mh*16 + j;
                    __half2 t2; t2.x = tileV[(2*m2)*64 + lc]; t2.y = tileV[(2*m2+1)*64 + lc];
                    w[j] = *(unsigned*)&t2;
                }
                const size_t ob = ((size_t)(h*CH + c))*MW + (m0 >> 1) + mh*16;
                *(uint4*)&g_Vt[ob]    = make_uint4(w[0], w[1], w[2], w[3]);
                *(uint4*)&g_Vt[ob+4]  = make_uint4(w[4], w[5], w[6], w[7]);
                *(uint4*)&g_Vt[ob+8]  = make_uint4(w[8], w[9], w[10], w[11]);
                *(uint4*)&g_Vt[ob+12] = make_uint4(w[12], w[13], w[14], w[15]);
                __syncthreads();
                const int cn = mt_i*4 + 5;
                if (cn < NCHUNK) {
                    unsigned* st = sA + PROJ_STGW;
                    const int mtg = blockIdx.y*MPT + (cn >> 2);
                    const int kw  = (cn & 3)*16;
                    #pragma unroll
                    for (int half = 0; half < 2; half++) {
                        const int fw = fw0 + half*4;
                        const size_t ga = (size_t)(mtg*64 + fr0)*64 + kw + fw;
                        cp16(sm_u32(st +        fr0*20 + fw), &g_Ah[ga]);
                        cp16(sm_u32(st + 1280 + fr0*20 + fw), &g_Al[ga]);
                    }
                    cp_commit();
                }
            } else {
                #pragma unroll
                for (int mt = 0; mt < 2; mt++) {
                    const int r0 = m0 + wm*32 + mt*16 + g;
                    #pragma unroll
                    for (int nt = 0; nt < 4; nt++) {
                        const int col = cbase + wn*32 + nt*8 + 2*tg;
                        const int h = col >> 5, c0 = col & 31;
                        float v0 = acc[mt][nt][0], v1 = acc[mt][nt][1];
                        float v2 = acc[mt][nt][2], v3 = acc[mt][nt][3];
                        if (kind == 0 || kind == 1) {
                            if (kind == 0) {
                                const float sc = QK_SCALE * LOG2E;   // fold log2e for ex2 softmax
                                v0*=sc; v1*=sc; v2*=sc; v3*=sc;
                            }
                            unsigned* dh = (kind == 0) ? g_Qph : g_Kph;
                            unsigned* dl = (kind == 0) ? g_Qpl : g_Kpl;
                            const size_t w0i = ((size_t)h*M_TOT + r0)*16 + (c0>>1);
                            const size_t w1i = ((size_t)h*M_TOT + r0 + 8)*16 + (c0>>1);
                            unsigned hw, lw;
                            splitbf2(v0, v1, hw, lw); dh[w0i] = hw; dl[w0i] = lw;
                            splitbf2(v2, v3, hw, lw); dh[w1i] = hw; dl[w1i] = lw;
                        } else {
                            *(float2*)&g_G[(size_t)r0*CIN + col] =
                                make_float2(1.f/(1.f+__expf(-v0)), 1.f/(1.f+__expf(-v1)));
                            *(float2*)&g_G[(size_t)(r0+8)*CIN + col] =
                                make_float2(1.f/(1.f+__expf(-v2)), 1.f/(1.f+__expf(-v3)));
                        }
                    }
                }
            }
        } else if (wn == 0 && tg < 2) {
            #pragma unroll
            for (int mt = 0; mt < 2; mt++) {
                const int r0 = m0 + wm*32 + mt*16 + g;
                const int c0 = 2*tg;
                g_TRI[(size_t)c0*M_TOT     + r0]   = acc[mt][0][0] * LOG2E;
                g_TRI[(size_t)(c0+1)*M_TOT + r0]   = acc[mt][0][1] * LOG2E;
                g_TRI[(size_t)c0*M_TOT     + r0+8] = acc[mt][0][2] * LOG2E;
                g_TRI[(size_t)(c0+1)*M_TOT + r0+8] = acc[mt][0][3] * LOG2E;
            }
        }
    }
}

// =====================================================================
// flash attention, 128 q/block (8 warps), cp.async double-buffered stages
// stage (11904 words): Kh[64][20] | Kl[64][20] | Vt[32][36] | Tri[128][64]f32
// S = split-bf16, PV = fp16, softmax via ex2 (log2e pre-folded).
// =====================================================================
#define STG_W 11904
__global__ void __launch_bounds__(256, 2)
attn_mma_kernel(const float* __restrict__ mask)
{
    extern __shared__ unsigned sha[];
    float* sMbAll = (float*)(sha + 2*STG_W);   // [384]

    const int tid  = threadIdx.x;
    const int warp = tid >> 5, lane = tid & 31;
    const int g = lane >> 2, tg = lane & 3;
    const int q0 = blockIdx.x * 128;
    const int i  = blockIdx.y;
    const int h  = blockIdx.z;
    const size_t rowbase = (size_t)i * NN;
    const size_t hbase   = (size_t)h * M_TOT;

    const int arow = ((lane>>3)&1)*8 + (lane&7);
    const int awof = (lane>>4)*4;
    const int krow = ((lane>>4)&1)*8 + (lane&7);
    const int kwof = ((lane>>3)&1)*4;

    const float MBSCALE = 1e9f * LOG2E;
    for (int idx = tid; idx < NN; idx += 256)
        sMbAll[idx] = MBSCALE * (mask[rowbase + idx] - 1.f);

    // ---- stage Q (two passes through stage0 K buffers) ----
    unsigned qh[2][4], ql[2][4];
    {
        unsigned* sQh = sha;
        unsigned* sQl = sha + 1280;
        const unsigned aQh = sm_u32(sQh), aQl = sm_u32(sQl);
        #pragma unroll
        for (int half = 0; half < 2; half++) {
            const int r = tid >> 2, w4 = (tid & 3) << 2;
            const size_t gw = (hbase + rowbase + q0 + half*64 + r)*16 + w4;
            *(uint4*)&sQh[r*20 + w4] = *(const uint4*)&g_Qph[gw];
            *(uint4*)&sQl[r*20 + w4] = *(const uint4*)&g_Qpl[gw];
            __syncthreads();
            if ((warp >> 2) == half) {
                const int wl = warp & 3;
                #pragma unroll
                for (int ck = 0; ck < 2; ck++) {
                    const unsigned offq = ((wl*16 + arow)*20 + ck*8 + awof) << 2;
                    ldsm4(qh[ck], aQh + offq);
                    ldsm4(ql[ck], aQl + offq);
                }
            }
            __syncthreads();
        }
    }

    const int qrow = q0 + (warp & 3)*16 + (warp >> 2)*64 + g;
    const int lrow0 = (warp & 3)*16 + (warp >> 2)*64 + g;      // local q row in tri tile

    float l0 = 0.f, l1 = 0.f;
    float oacc[4][4];
    #pragma unroll
    for (int a = 0; a < 4; a++)
        #pragma unroll
        for (int b = 0; b < 4; b++) oacc[a][b] = 0.f;

    const int fr  = tid >> 2,  fw  = (tid & 3) << 2;
    const int fvr = tid >> 3,  fvw = (tid & 7) << 2;

    // ---- stage-fill helper pattern (prologue) ----
    {
        unsigned* st = sha;
        const size_t gw = (hbase + rowbase + 0 + fr)*16 + fw;
        cp16(sm_u32(st + fr*20 + fw),        &g_Kph[gw]);
        cp16(sm_u32(st + 1280 + fr*20 + fw), &g_Kpl[gw]);
        const size_t mw0 = rowbase >> 1;
        cp16(sm_u32(st + 2560 + fvr*36 + fvw), &g_Vt[((size_t)(h*CH + fvr))*MW + mw0 + fvw]);
        float* sTri = (float*)(st + 3712);
        for (int idx = tid; idx < 2048; idx += 256) {
            const int r = idx >> 4, cw = (idx & 15) << 2;
            cp16(sm_u32(sTri + r*64 + cw), &g_TRI[hbase + (size_t)(q0 + r)*NN + 0 + cw]);
        }
        cp_commit();
    }

    for (int t = 0; t < 6; t++) {
        const int cur = t & 1;
        if (t < 5) {
            unsigned* st = sha + (1-cur)*STG_W;
            const int kbn = (t+1)*64;
            const size_t gw = (hbase + rowbase + kbn + fr)*16 + fw;
            cp16(sm_u32(st + fr*20 + fw),        &g_Kph[gw]);
            cp16(sm_u32(st + 1280 + fr*20 + fw), &g_Kpl[gw]);
            const size_t mw0 = (rowbase + kbn) >> 1;
            cp16(sm_u32(st + 2560 + fvr*36 + fvw), &g_Vt[((size_t)(h*CH + fvr))*MW + mw0 + fvw]);
            float* sTriN = (float*)(st + 3712);
            for (int idx = tid; idx < 2048; idx += 256) {
                const int r = idx >> 4, cw = (idx & 15) << 2;
                cp16(sm_u32(sTriN + r*64 + cw), &g_TRI[hbase + (size_t)(q0 + r)*NN + kbn + cw]);
            }
            cp_commit();
            cp_wait1();
        } else {
            cp_wait0();
        }
        __syncthreads();

        const unsigned aKh = sm_u32(sha + cur*STG_W);
        const unsigned aKl = aKh + 1280*4;
        const unsigned aVt = aKh + 2560*4;
        const float* sTri = (const float*)(sha + cur*STG_W + 3712);

        float s[8][4];
        #pragma unroll
        for (int a = 0; a < 8; a++)
            #pragma unroll
            for (int b = 0; b < 4; b++) s[a][b] = 0.f;

        #pragma unroll
        for (int ck = 0; ck < 2; ck++) {
            #pragma unroll
            for (int p = 0; p < 4; p++) {
                const unsigned off = ((p*16 + krow)*20 + ck*8 + kwof) << 2;
                unsigned bh[4], bl[4];
                ldsm4(bh, aKh + off);
                ldsm4(bl, aKl + off);
                mma16(s[2*p],   qh[ck], bh);
                mma16(s[2*p],   qh[ck], bl);
                mma16(s[2*p],   ql[ck], bh);
                mma16(s[2*p+1], qh[ck], bh+2);
                mma16(s[2*p+1], qh[ck], bl+2);
                mma16(s[2*p+1], ql[ck], bh+2);
            }
        }

        // ---- bias + ex2 (no max subtraction; scores bounded) ----
        #pragma unroll
        for (int nt = 0; nt < 8; nt++) {
            const int col = nt*8 + 2*tg;
            const float2 t0 = *(const float2*)&sTri[lrow0*64 + col];
            const float2 t1 = *(const float2*)&sTri[(lrow0+8)*64 + col];
            const float2 mb = *(const float2*)&sMbAll[t*64 + col];
            s[nt][0] = ex2f(s[nt][0] + t0.x + mb.x);
            s[nt][1] = ex2f(s[nt][1] + t0.y + mb.y);
            s[nt][2] = ex2f(s[nt][2] + t1.x + mb.x);
            s[nt][3] = ex2f(s[nt][3] + t1.y + mb.y);
            l0 += s[nt][0] + s[nt][1];
            l1 += s[nt][2] + s[nt][3];
        }

        // ---- O += P V ----
        #pragma unroll
        for (int j = 0; j < 4; j++) {
            unsigned a[4];
            a[0] = pack2h(s[2*j  ][0], s[2*j  ][1]);
            a[1] = pack2h(s[2*j  ][2], s[2*j  ][3]);
            a[2] = pack2h(s[2*j+1][0], s[2*j+1][1]);
            a[3] = pack2h(s[2*j+1][2], s[2*j+1][3]);
            #pragma unroll
            for (int p = 0; p < 2; p++) {
                const unsigned off = ((p*16 + krow)*36 + j*8 + kwof) << 2;
                unsigned b[4];
                ldsm4(b, aVt + off);
                mma16h(oacc[2*p],   a, b);
                mma16h(oacc[2*p+1], a, b+2);
            }
        }
        __syncthreads();
    }

    l0 += __shfl_xor_sync(0xffffffffu, l0, 1);
    l0 += __shfl_xor_sync(0xffffffffu, l0, 2);
    l1 += __shfl_xor_sync(0xffffffffu, l1, 1);
    l1 += __shfl_xor_sync(0xffffffffu, l1, 2);

    const float inv0 = 1.f/l0, inv1 = 1.f/l1;
    const size_t ob0 = (rowbase + qrow)*CIN + h*CH;
    const size_t ob1 = (rowbase + qrow + 8)*CIN + h*CH;
    #pragma unroll
    for (int nt = 0; nt < 4; nt++) {
        const int col = nt*8 + 2*tg;
        *(float2*)&g_O[ob0 + col] = make_float2(oacc[nt][0]*inv0, oacc[nt][1]*inv0);
        *(float2*)&g_O[ob1 + col] = make_float2(oacc[nt][2]*inv1, oacc[nt][3]*inv1);
    }
}

// =====================================================================
// GEMM 3: out = (O*G) @ wo, fp16 m16n8k16, ldmatrix loads.
// =====================================================================
__global__ void __launch_bounds__(128, 6)
outproj_mma_kernel(float* __restrict__ out)
{
    extern __shared__ unsigned sho[];
    unsigned* sA = sho;
    unsigned* sB = sA + 64*20;

    const int tid  = threadIdx.x;
    const int warp = tid >> 5, lane = tid & 31;
    const int g = lane >> 2, tg = lane & 3;
    const int wm = warp >> 1, wn = warp & 1;
    const int n0 = blockIdx.x * 64;
    const int m0 = blockIdx.y * 64;

    const unsigned aA = sm_u32(sA), aB = sm_u32(sB);
    const int arow = ((lane>>3)&1)*8 + (lane&7);
    const int awof = (lane>>4)*4;
    const int krow = ((lane>>4)&1)*8 + (lane&7);
    const int kwof = ((lane>>3)&1)*4;

    float acc[2][4][4];
    #pragma unroll
    for (int a = 0; a < 2; a++)
        #pragma unroll
        for (int b = 0; b < 4; b++)
            #pragma unroll
            for (int c = 0; c < 4; c++) acc[a][b][c] = 0.f;

    for (int kc = 0; kc < 128; kc += 32) {
        __syncthreads();
        for (int idx = tid; idx < 512; idx += 128) {
            const int ra = idx >> 3, ca = (idx & 7) << 2;
            const size_t ga = (size_t)(m0+ra)*CIN + kc + ca;
            const float4 o4 = *(const float4*)&g_O[ga];
            const float4 g4 = *(const float4*)&g_G[ga];
            sA[ra*20 + (ca>>1)    ] = pack2h(o4.x*g4.x, o4.y*g4.y);
            sA[ra*20 + (ca>>1) + 1] = pack2h(o4.z*g4.z, o4.w*g4.w);
        }
        for (int idx = tid; idx < 256; idx += 128) {
            const int r = idx >> 2, w4 = (idx & 3) << 2;
            *(uint4*)&sB[r*20 + w4] = *(const uint4*)&g_WOt[(size_t)(n0+r)*64 + (kc>>1) + w4];
        }
        __syncthreads();
        #pragma unroll
        for (int ck = 0; ck < 2; ck++) {
            const int w0 = ck*8;
            unsigned ah[2][4];
            #pragma unroll
            for (int mt = 0; mt < 2; mt++)
                ldsm4(ah[mt], aA + (((wm*32 + mt*16 + arow)*20 + w0 + awof) << 2));
            #pragma unroll
            for (int p = 0; p < 2; p++) {
                unsigned b[4];
                ldsm4(b, aB + (((wn*32 + p*16 + krow)*20 + w0 + kwof) << 2));
                #pragma unroll
                for (int mt = 0; mt < 2; mt++) {
                    mma16h(acc[mt][2*p],   ah[mt], b);
                    mma16h(acc[mt][2*p+1], ah[mt], b+2);
                }
            }
        }
    }

    #pragma unroll
    for (int mt = 0; mt < 2; mt++) {
        const int r0 = m0 + wm*32 + mt*16 + g;
        #pragma unroll
        for (int nt = 0; nt < 4; nt++) {
            const int col = n0 + wn*32 + nt*8 + 2*tg;
            *(float2*)&out[(size_t)r0*CIN + col]     = make_float2(acc[mt][nt][0], acc[mt][nt][1]);
            *(float2*)&out[(size_t)(r0+8)*CIN + col] = make_float2(acc[mt][nt][2], acc[mt][nt][3]);
        }
    }
}

// =====================================================================
// launch
// =====================================================================
extern "C" void kernel_launch(void* const* d_in, const int* in_sizes, int n_in,
                              void* d_out, int out_size)
{
    (void)in_sizes; (void)n_in; (void)out_size;
    const float* z    = (const float*)d_in[0];
    const float* mask = (const float*)d_in[1];
    const float* lnw  = (const float*)d_in[2];
    const float* lnb  = (const float*)d_in[3];
    const float* wtri = (const float*)d_in[4];
    const float* wq   = (const float*)d_in[5];
    const float* wk   = (const float*)d_in[6];
    const float* wv   = (const float*)d_in[7];
    const float* wg   = (const float*)d_in[8];
    const float* wo   = (const float*)d_in[9];

    const size_t proj_sh = (size_t)PROJ_SH_W * 4;                 // 55296
    const size_t attn_sh = (size_t)(2*STG_W) * 4 + NN*4;          // 96768
    const size_t out_sh  = (size_t)(2*64*20) * 4;                 // 10240

    static int s_attr_set = 0;
    if (!s_attr_set) {
        cudaFuncSetAttribute(proj_mma_kernel,
                             cudaFuncAttributeMaxDynamicSharedMemorySize, (int)proj_sh);
        cudaFuncSetAttribute(attn_mma_kernel,
                             cudaFuncAttributeMaxDynamicSharedMemorySize, (int)attn_sh);
        s_attr_set = 1;
    }

    wsplit_kernel<<<(WCOLS*64 + CIN*64 + 255)/256, 256>>>(wq, wk, wv, wg, wtri, wo);
    ln_split_kernel<<<M_TOT/8, 256>>>(z, lnw, lnb);
    proj_mma_kernel<<<dim3(9, 2304/MPT), 128, proj_sh>>>();
    attn_mma_kernel<<<dim3(NN/128, NN, NH), 256, attn_sh>>>(mask);
    outproj_mma_kernel<<<dim3(2, M_TOT/64), 128, out_sh>>>((float*)d_out);
}

// round 15
// speedup vs baseline: 3.4928x; 1.0234x over previous
#include <cuda_runtime.h>
#include <cuda_bf16.h>
#include <cuda_fp16.h>
#include <cstdint>
#include <math.h>

// ---------------- problem constants ----------------
#define NN   384
#define CIN  128
#define NH   4
#define CH   32
#define M_TOT (NN*NN)                   // 147456
#define MW   (M_TOT/2)
#define QK_SCALE 0.17677669529663687f   // 1/sqrt(32)
#define LOG2E    1.4426950408889634f
#define WCOLS 576                        // 512 proj cols + 4 tri + pad
#define MPT  36                          // m-tiles per proj block (2304/36 = 64)

// ---------------- scratch (device globals; no allocs) ----------------
__device__ unsigned g_Ah[(size_t)M_TOT*64];      // LN(z) bf16x2 hi plane
__device__ unsigned g_Al[(size_t)M_TOT*64];      // lo plane
__device__ unsigned g_Wth[(size_t)WCOLS*64];     // weights^T packed bf16x2 hi
__device__ unsigned g_Wtl[(size_t)WCOLS*64];
__device__ unsigned g_WOt[(size_t)CIN*64];       // wo^T packed half2
__device__ unsigned g_Qph[(size_t)NH*M_TOT*16];  // Q head-major bf16x2 hi/lo (pre-scaled log2e)
__device__ unsigned g_Qpl[(size_t)NH*M_TOT*16];
__device__ unsigned g_Kph[(size_t)NH*M_TOT*16];
__device__ unsigned g_Kpl[(size_t)NH*M_TOT*16];
__device__ unsigned g_Vt [(size_t)NH*CH*MW];     // V^T packed half2 [h][c][m/2]
__device__ float g_G  [(size_t)M_TOT*CIN];       // sigmoid gate
__device__ float g_TRI[(size_t)NH*M_TOT];        // tri bias (pre-scaled log2e)
__device__ unsigned g_Oh[(size_t)M_TOT*64];      // gated attn out, packed half2 [m][64w]

// ---------------- helpers ----------------
__device__ __forceinline__ unsigned pack2h(float a, float b) {
    __half2 t = __floats2half2_rn(a, b);
    return *(unsigned*)&t;
}
__device__ __forceinline__ unsigned packbf(float a, float b) {
    __nv_bfloat162 t = __floats2bfloat162_rn(a, b);
    return *(unsigned*)&t;
}
__device__ __forceinline__ void splitbf2(float a, float b, unsigned& hw, unsigned& lw) {
    __nv_bfloat16 ha = __float2bfloat16_rn(a);
    __nv_bfloat16 hb = __float2bfloat16_rn(b);
    float ra = a - __bfloat162float(ha);
    float rb = b - __bfloat162float(hb);
    __nv_bfloat162 h; h.x = ha; h.y = hb;
    hw = *(unsigned*)&h;
    lw = packbf(ra, rb);
}
__device__ __forceinline__ unsigned sm_u32(const void* p) {
    return (unsigned)__cvta_generic_to_shared(p);
}
__device__ __forceinline__ void ldsm4(unsigned* r, unsigned addr) {
    asm volatile("ldmatrix.sync.aligned.m8n8.x4.shared.b16 {%0,%1,%2,%3}, [%4];"
        : "=r"(r[0]), "=r"(r[1]), "=r"(r[2]), "=r"(r[3]) : "r"(addr));
}
__device__ __forceinline__ void cp16(unsigned saddr, const void* gptr) {
    asm volatile("cp.async.cg.shared.global [%0], [%1], 16;" :: "r"(saddr), "l"(gptr));
}
__device__ __forceinline__ void cp_commit() { asm volatile("cp.async.commit_group;"); }
__device__ __forceinline__ void cp_wait0()  { asm volatile("cp.async.wait_group 0;"); }
__device__ __forceinline__ void cp_wait1()  { asm volatile("cp.async.wait_group 1;"); }
__device__ __forceinline__ float ex2f(float x) {
    float y; asm("ex2.approx.f32 %0, %1;" : "=f"(y) : "f"(x)); return y;
}
// bf16 m16n8k16
__device__ __forceinline__ void mma16(float* d, const unsigned* a, const unsigned* b) {
    asm volatile(
        "mma.sync.aligned.m16n8k16.row.col.f32.bf16.bf16.f32 "
        "{%0,%1,%2,%3},{%4,%5,%6,%7},{%8,%9},{%0,%1,%2,%3};\n"
        : "+f"(d[0]), "+f"(d[1]), "+f"(d[2]), "+f"(d[3])
        : "r"(a[0]), "r"(a[1]), "r"(a[2]), "r"(a[3]), "r"(b[0]), "r"(b[1]));
}
// fp16 m16n8k16
__device__ __forceinline__ void mma16h(float* d, const unsigned* a, const unsigned* b) {
    asm volatile(
        "mma.sync.aligned.m16n8k16.row.col.f32.f16.f16.f32 "
        "{%0,%1,%2,%3},{%4,%5,%6,%7},{%8,%9},{%0,%1,%2,%3};\n"
        : "+f"(d[0]), "+f"(d[1]), "+f"(d[2]), "+f"(d[3])
        : "r"(a[0]), "r"(a[1]), "r"(a[2]), "r"(a[3]), "r"(b[0]), "r"(b[1]));
}

// =====================================================================
// prep 1: LayerNorm + bf16-split pack (1 warp per row)
// =====================================================================
__global__ void __launch_bounds__(256)
ln_split_kernel(const float* __restrict__ z,
                const float* __restrict__ lnw, const float* __restrict__ lnb)
{
    const int row  = blockIdx.x*8 + (threadIdx.x >> 5);
    const int lane = threadIdx.x & 31;
    const float4 v = *(const float4*)(z + (size_t)row*CIN + lane*4);
    float s1 = v.x+v.y+v.z+v.w;
    float s2 = v.x*v.x + v.y*v.y + v.z*v.z + v.w*v.w;
    #pragma unroll
    for (int o = 16; o; o >>= 1) {
        s1 += __shfl_xor_sync(0xffffffffu, s1, o);
        s2 += __shfl_xor_sync(0xffffffffu, s2, o);
    }
    const float mu  = s1 * (1.f/128.f);
    const float var = s2 * (1.f/128.f) - mu*mu;
    const float inv = rsqrtf(var + 1e-5f);
    const float4 w = *(const float4*)(lnw + lane*4);
    const float4 b = *(const float4*)(lnb + lane*4);
    const float y0 = (v.x-mu)*inv*w.x + b.x;
    const float y1 = (v.y-mu)*inv*w.y + b.y;
    const float y2 = (v.z-mu)*inv*w.z + b.z;
    const float y3 = (v.w-mu)*inv*w.w + b.w;
    unsigned h0,l0,h1,l1;
    splitbf2(y0,y1,h0,l0);
    splitbf2(y2,y3,h1,l1);
    const size_t base = (size_t)row*64 + lane*2;
    g_Ah[base] = h0; g_Ah[base+1] = h1;
    g_Al[base] = l0; g_Al[base+1] = l1;
}

// =====================================================================
// prep 2: weights -> transposed packed bf16 planes; wo -> packed half2
// =====================================================================
__global__ void __launch_bounds__(256)
wsplit_kernel(const float* __restrict__ wq, const float* __restrict__ wk,
              const float* __restrict__ wv, const float* __restrict__ wg,
              const float* __restrict__ wtri, const float* __restrict__ wo)
{
    const int idx = blockIdx.x*256 + threadIdx.x;
    if (idx < WCOLS*64) {
        const int n = idx >> 6, kw = idx & 63;
        const int k0 = kw*2;
        float v0, v1;
        if      (n < 128) { v0 = wq[k0*128 + n];          v1 = wq[(k0+1)*128 + n]; }
        else if (n < 256) { v0 = wk[k0*128 + n-128];      v1 = wk[(k0+1)*128 + n-128]; }
        else if (n < 384) { v0 = wv[k0*128 + n-256];      v1 = wv[(k0+1)*128 + n-256]; }
        else if (n < 512) { v0 = wg[k0*128 + n-384];      v1 = wg[(k0+1)*128 + n-384]; }
        else if (n < 516) { v0 = wtri[k0*4 + n-512];      v1 = wtri[(k0+1)*4 + n-512]; }
        else              { v0 = 0.f; v1 = 0.f; }
        unsigned hw, lw; splitbf2(v0, v1, hw, lw);
        g_Wth[idx] = hw; g_Wtl[idx] = lw;
    } else if (idx < WCOLS*64 + CIN*64) {
        const int j = idx - WCOLS*64;
        const int n = j >> 6, kw = j & 63;
        g_WOt[j] = pack2h(wo[(2*kw)*128 + n], wo[(2*kw+1)*128 + n]);
    }
}

// =====================================================================
// GEMM 1 (persistent, weight-stationary)
// =====================================================================
#define PROJ_B_W   (64*68)
#define PROJ_STGW  (2*64*20)
#define PROJ_SH_W  (2*PROJ_B_W + 2*PROJ_STGW)
__global__ void __launch_bounds__(128, 4)
proj_mma_kernel()
{
    extern __shared__ unsigned shp[];
    unsigned* sBh = shp;
    unsigned* sBl = shp + PROJ_B_W;
    unsigned* sA  = shp + 2*PROJ_B_W;

    const int tid  = threadIdx.x;
    const int warp = tid >> 5, lane = tid & 31;
    const int g = lane >> 2, tg = lane & 3;
    const int wm = warp >> 1, wn = warp & 1;
    const int ntb = blockIdx.x;
    const int n0  = ntb * 64;
    const int kind = ntb >> 1;
    const bool isV = (ntb == 4 || ntb == 5);

    const int arow = ((lane>>3)&1)*8 + (lane&7);
    const int awof = (lane>>4)*4;
    const int krow = ((lane>>4)&1)*8 + (lane&7);
    const int kwof = ((lane>>3)&1)*4;

    const int fr0 = tid >> 1, fw0 = (tid & 1) << 3;
    const int NCHUNK = 4*MPT;

    for (int idx = tid; idx < 1024; idx += 128) {
        const int r = idx >> 4, w4 = (idx & 15) << 2;
        cp16(sm_u32(sBh + r*68 + w4), &g_Wth[(size_t)(n0+r)*64 + w4]);
        cp16(sm_u32(sBl + r*68 + w4), &g_Wtl[(size_t)(n0+r)*64 + w4]);
    }
    {
        const int mtg = blockIdx.y*MPT;
        unsigned* st = sA;
        #pragma unroll
        for (int half = 0; half < 2; half++) {
            const int fw = fw0 + half*4;
            const size_t ga = (size_t)(mtg*64 + fr0)*64 + 0 + fw;
            cp16(sm_u32(st +        fr0*20 + fw), &g_Ah[ga]);
            cp16(sm_u32(st + 1280 + fr0*20 + fw), &g_Al[ga]);
        }
        cp_commit();
    }
    {
        const int mtg = blockIdx.y*MPT;
        unsigned* st = sA + PROJ_STGW;
        #pragma unroll
        for (int half = 0; half < 2; half++) {
            const int fw = fw0 + half*4;
            const size_t ga = (size_t)(mtg*64 + fr0)*64 + 16 + fw;
            cp16(sm_u32(st +        fr0*20 + fw), &g_Ah[ga]);
            cp16(sm_u32(st + 1280 + fr0*20 + fw), &g_Al[ga]);
        }
        cp_commit();
    }

    const unsigned aBh = sm_u32(sBh), aBl = sm_u32(sBl);

    for (int mt_i = 0; mt_i < MPT; mt_i++) {
        const int m0 = (blockIdx.y*MPT + mt_i)*64;

        float acc[2][4][4];
        #pragma unroll
        for (int a = 0; a < 2; a++)
            #pragma unroll
            for (int b = 0; b < 4; b++)
                #pragma unroll
                for (int c = 0; c < 4; c++) acc[a][b][c] = 0.f;

        #pragma unroll
        for (int kc = 0; kc < 4; kc++) {
            const int c = mt_i*4 + kc;
            if (c == NCHUNK-1) cp_wait0(); else cp_wait1();
            __syncthreads();

            const unsigned aAh = sm_u32(sA + (c&1)*PROJ_STGW);
            const unsigned aAl = aAh + 1280*4;
            const int kw0 = kc*16;

            #pragma unroll
            for (int sub = 0; sub < 2; sub++) {
                const int w0 = sub*8;
                unsigned ah[2][4], al[2][4];
                #pragma unroll
                for (int mt = 0; mt < 2; mt++) {
                    const unsigned offa = ((wm*32 + mt*16 + arow)*20 + w0 + awof) << 2;
                    ldsm4(ah[mt], aAh + offa);
                    ldsm4(al[mt], aAl + offa);
                }
                #pragma unroll
                for (int p = 0; p < 2; p++) {
                    const unsigned offb = ((wn*32 + p*16 + krow)*68 + kw0 + w0 + kwof) << 2;
                    unsigned bh[4], bl[4];
                    ldsm4(bh, aBh + offb);
                    ldsm4(bl, aBl + offb);
                    #pragma unroll
                    for (int mt = 0; mt < 2; mt++) {
                        mma16(acc[mt][2*p],   ah[mt], bh);
                        mma16(acc[mt][2*p],   ah[mt], bl);
                        mma16(acc[mt][2*p],   al[mt], bh);
                        mma16(acc[mt][2*p+1], ah[mt], bh+2);
                        mma16(acc[mt][2*p+1], ah[mt], bl+2);
                        mma16(acc[mt][2*p+1], al[mt], bh+2);
                    }
                }
            }
            __syncthreads();

            const int cn = c + 2;
            if (cn < NCHUNK && !(isV && kc == 3)) {
                unsigned* st = sA + (c&1)*PROJ_STGW;
                const int mtg = blockIdx.y*MPT + (cn >> 2);
                const int kw  = (cn & 3)*16;
                #pragma unroll
                for (int half = 0; half < 2; half++) {
                    const int fw = fw0 + half*4;
                    const size_t ga = (size_t)(mtg*64 + fr0)*64 + kw + fw;
                    cp16(sm_u32(st +        fr0*20 + fw), &g_Ah[ga]);
                    cp16(sm_u32(st + 1280 + fr0*20 + fw), &g_Al[ga]);
                }
                cp_commit();
            }
        }

        // ---- per-m-tile epilogue ----
        if (ntb < 8) {
            const int cbase = (ntb & 1)*64;
            if (isV) {
                __half* tileV = (__half*)(sA + PROJ_STGW);
                #pragma unroll
                for (int mt = 0; mt < 2; mt++) {
                    const int lm = wm*32 + mt*16 + g;
                    #pragma unroll
                    for (int nt = 0; nt < 4; nt++) {
                        const int lc = wn*32 + nt*8 + 2*tg;
                        *(__half2*)&tileV[lm*64 + lc] =
                            __floats2half2_rn(acc[mt][nt][0], acc[mt][nt][1]);
                        *(__half2*)&tileV[(lm+8)*64 + lc] =
                            __floats2half2_rn(acc[mt][nt][2], acc[mt][nt][3]);
                    }
                }
                __syncthreads();
                const int lc = tid >> 1;
                const int mh = tid & 1;
                const int h  = (ntb - 4)*2 + (lc >> 5);
                const int c  = lc & 31;
                unsigned w[16];
                #pragma unroll
                for (int j = 0; j < 16; j++) {
                    const int m2 = mh*16 + j;
                    __half2 t2; t2.x = tileV[(2*m2)*64 + lc]; t2.y = tileV[(2*m2+1)*64 + lc];
                    w[j] = *(unsigned*)&t2;
                }
                const size_t ob = ((size_t)(h*CH + c))*MW + (m0 >> 1) + mh*16;
                *(uint4*)&g_Vt[ob]    = make_uint4(w[0], w[1], w[2], w[3]);
                *(uint4*)&g_Vt[ob+4]  = make_uint4(w[4], w[5], w[6], w[7]);
                *(uint4*)&g_Vt[ob+8]  = make_uint4(w[8], w[9], w[10], w[11]);
                *(uint4*)&g_Vt[ob+12] = make_uint4(w[12], w[13], w[14], w[15]);
                __syncthreads();
                const int cn = mt_i*4 + 5;
                if (cn < NCHUNK) {
                    unsigned* st = sA + PROJ_STGW;
                    const int mtg = blockIdx.y*MPT + (cn >> 2);
                    const int kw  = (cn & 3)*16;
                    #pragma unroll
                    for (int half = 0; half < 2; half++) {
                        const int fw = fw0 + half*4;
                        const size_t ga = (size_t)(mtg*64 + fr0)*64 + kw + fw;
                        cp16(sm_u32(st +        fr0*20 + fw), &g_Ah[ga]);
                        cp16(sm_u32(st + 1280 + fr0*20 + fw), &g_Al[ga]);
                    }
                    cp_commit();
                }
            } else {
                #pragma unroll
                for (int mt = 0; mt < 2; mt++) {
                    const int r0 = m0 + wm*32 + mt*16 + g;
                    #pragma unroll
                    for (int nt = 0; nt < 4; nt++) {
                        const int col = cbase + wn*32 + nt*8 + 2*tg;
                        const int h = col >> 5, c0 = col & 31;
                        float v0 = acc[mt][nt][0], v1 = acc[mt][nt][1];
                        float v2 = acc[mt][nt][2], v3 = acc[mt][nt][3];
                        if (kind == 0 || kind == 1) {
                            if (kind == 0) {
                                const float sc = QK_SCALE * LOG2E;
                                v0*=sc; v1*=sc; v2*=sc; v3*=sc;
                            }
                            unsigned* dh = (kind == 0) ? g_Qph : g_Kph;
                            unsigned* dl = (kind == 0) ? g_Qpl : g_Kpl;
                            const size_t w0i = ((size_t)h*M_TOT + r0)*16 + (c0>>1);
                            const size_t w1i = ((size_t)h*M_TOT + r0 + 8)*16 + (c0>>1);
                            unsigned hw, lw;
                            splitbf2(v0, v1, hw, lw); dh[w0i] = hw; dl[w0i] = lw;
                            splitbf2(v2, v3, hw, lw); dh[w1i] = hw; dl[w1i] = lw;
                        } else {
                            *(float2*)&g_G[(size_t)r0*CIN + col] =
                                make_float2(1.f/(1.f+__expf(-v0)), 1.f/(1.f+__expf(-v1)));
                            *(float2*)&g_G[(size_t)(r0+8)*CIN + col] =
                                make_float2(1.f/(1.f+__expf(-v2)), 1.f/(1.f+__expf(-v3)));
                        }
                    }
                }
            }
        } else if (wn == 0 && tg < 2) {
            #pragma unroll
            for (int mt = 0; mt < 2; mt++) {
                const int r0 = m0 + wm*32 + mt*16 + g;
                const int c0 = 2*tg;
                g_TRI[(size_t)c0*M_TOT     + r0]   = acc[mt][0][0] * LOG2E;
                g_TRI[(size_t)(c0+1)*M_TOT + r0]   = acc[mt][0][1] * LOG2E;
                g_TRI[(size_t)c0*M_TOT     + r0+8] = acc[mt][0][2] * LOG2E;
                g_TRI[(size_t)(c0+1)*M_TOT + r0+8] = acc[mt][0][3] * LOG2E;
            }
        }
    }
}

// =====================================================================
// flash attention, 128 q/block, cp.async double-buffered stages
// (Kh|Kl|Vt|Tri), S = split-bf16 with bias preloaded into accumulators,
// PV = fp16, softmax via ex2.  Epilogue gates + packs fp16 -> g_Oh.
// =====================================================================
#define STG_W 11904
__global__ void __launch_bounds__(256, 2)
attn_mma_kernel(const float* __restrict__ mask)
{
    extern __shared__ unsigned sha[];
    float* sMbAll = (float*)(sha + 2*STG_W);   // [384]

    const int tid  = threadIdx.x;
    const int warp = tid >> 5, lane = tid & 31;
    const int g = lane >> 2, tg = lane & 3;
    const int q0 = blockIdx.x * 128;
    const int i  = blockIdx.y;
    const int h  = blockIdx.z;
    const size_t rowbase = (size_t)i * NN;
    const size_t hbase   = (size_t)h * M_TOT;

    const int arow = ((lane>>3)&1)*8 + (lane&7);
    const int awof = (lane>>4)*4;
    const int krow = ((lane>>4)&1)*8 + (lane&7);
    const int kwof = ((lane>>3)&1)*4;

    const float MBSCALE = 1e9f * LOG2E;
    for (int idx = tid; idx < NN; idx += 256)
        sMbAll[idx] = MBSCALE * (mask[rowbase + idx] - 1.f);

    // ---- stage Q (two passes through stage0 K buffers) ----
    unsigned qh[2][4], ql[2][4];
    {
        unsigned* sQh = sha;
        unsigned* sQl = sha + 1280;
        const unsigned aQh = sm_u32(sQh), aQl = sm_u32(sQl);
        #pragma unroll
        for (int half = 0; half < 2; half++) {
            const int r = tid >> 2, w4 = (tid & 3) << 2;
            const size_t gw = (hbase + rowbase + q0 + half*64 + r)*16 + w4;
            *(uint4*)&sQh[r*20 + w4] = *(const uint4*)&g_Qph[gw];
            *(uint4*)&sQl[r*20 + w4] = *(const uint4*)&g_Qpl[gw];
            __syncthreads();
            if ((warp >> 2) == half) {
                const int wl = warp & 3;
                #pragma unroll
                for (int ck = 0; ck < 2; ck++) {
                    const unsigned offq = ((wl*16 + arow)*20 + ck*8 + awof) << 2;
                    ldsm4(qh[ck], aQh + offq);
                    ldsm4(ql[ck], aQl + offq);
                }
            }
            __syncthreads();
        }
    }

    const int qrow = q0 + (warp & 3)*16 + (warp >> 2)*64 + g;
    const int lrow0 = (warp & 3)*16 + (warp >> 2)*64 + g;

    float l0 = 0.f, l1 = 0.f;
    float oacc[4][4];
    #pragma unroll
    for (int a = 0; a < 4; a++)
        #pragma unroll
        for (int b = 0; b < 4; b++) oacc[a][b] = 0.f;

    const int fr  = tid >> 2,  fw  = (tid & 3) << 2;
    const int fvr = tid >> 3,  fvw = (tid & 7) << 2;

    {
        unsigned* st = sha;
        const size_t gw = (hbase + rowbase + 0 + fr)*16 + fw;
        cp16(sm_u32(st + fr*20 + fw),        &g_Kph[gw]);
        cp16(sm_u32(st + 1280 + fr*20 + fw), &g_Kpl[gw]);
        const size_t mw0 = rowbase >> 1;
        cp16(sm_u32(st + 2560 + fvr*36 + fvw), &g_Vt[((size_t)(h*CH + fvr))*MW + mw0 + fvw]);
        float* sTri = (float*)(st + 3712);
        for (int idx = tid; idx < 2048; idx += 256) {
            const int r = idx >> 4, cw = (idx & 15) << 2;
            cp16(sm_u32(sTri + r*64 + cw), &g_TRI[hbase + (size_t)(q0 + r)*NN + 0 + cw]);
        }
        cp_commit();
    }

    for (int t = 0; t < 6; t++) {
        const int cur = t & 1;
        if (t < 5) {
            unsigned* st = sha + (1-cur)*STG_W;
            const int kbn = (t+1)*64;
            const size_t gw = (hbase + rowbase + kbn + fr)*16 + fw;
            cp16(sm_u32(st + fr*20 + fw),        &g_Kph[gw]);
            cp16(sm_u32(st + 1280 + fr*20 + fw), &g_Kpl[gw]);
            const size_t mw0 = (rowbase + kbn) >> 1;
            cp16(sm_u32(st + 2560 + fvr*36 + fvw), &g_Vt[((size_t)(h*CH + fvr))*MW + mw0 + fvw]);
            float* sTriN = (float*)(st + 3712);
            for (int idx = tid; idx < 2048; idx += 256) {
                const int r = idx >> 4, cw = (idx & 15) << 2;
                cp16(sm_u32(sTriN + r*64 + cw), &g_TRI[hbase + (size_t)(q0 + r)*NN + kbn + cw]);
            }
            cp_commit();
            cp_wait1();
        } else {
            cp_wait0();
        }
        __syncthreads();

        const unsigned aKh = sm_u32(sha + cur*STG_W);
        const unsigned aKl = aKh + 1280*4;
        const unsigned aVt = aKh + 2560*4;
        const float* sTri = (const float*)(sha + cur*STG_W + 3712);

        // ---- preload bias (tri + mask) into S accumulators ----
        float s[8][4];
        #pragma unroll
        for (int nt = 0; nt < 8; nt++) {
            const int col = nt*8 + 2*tg;
            const float2 t0 = *(const float2*)&sTri[lrow0*64 + col];
            const float2 t1 = *(const float2*)&sTri[(lrow0+8)*64 + col];
            const float2 mb = *(const float2*)&sMbAll[t*64 + col];
            s[nt][0] = t0.x + mb.x;
            s[nt][1] = t0.y + mb.y;
            s[nt][2] = t1.x + mb.x;
            s[nt][3] = t1.y + mb.y;
        }

        // ---- S += Q K^T ----
        #pragma unroll
        for (int ck = 0; ck < 2; ck++) {
            #pragma unroll
            for (int p = 0; p < 4; p++) {
                const unsigned off = ((p*16 + krow)*20 + ck*8 + kwof) << 2;
                unsigned bh[4], bl[4];
                ldsm4(bh, aKh + off);
                ldsm4(bl, aKl + off);
                mma16(s[2*p],   qh[ck], bh);
                mma16(s[2*p],   qh[ck], bl);
                mma16(s[2*p],   ql[ck], bh);
                mma16(s[2*p+1], qh[ck], bh+2);
                mma16(s[2*p+1], qh[ck], bl+2);
                mma16(s[2*p+1], ql[ck], bh+2);
            }
        }

        // ---- ex2 softmax numerator ----
        #pragma unroll
        for (int nt = 0; nt < 8; nt++) {
            s[nt][0] = ex2f(s[nt][0]);
            s[nt][1] = ex2f(s[nt][1]);
            s[nt][2] = ex2f(s[nt][2]);
            s[nt][3] = ex2f(s[nt][3]);
            l0 += s[nt][0] + s[nt][1];
            l1 += s[nt][2] + s[nt][3];
        }

        // ---- O += P V ----
        #pragma unroll
        for (int j = 0; j < 4; j++) {
            unsigned a[4];
            a[0] = pack2h(s[2*j  ][0], s[2*j  ][1]);
            a[1] = pack2h(s[2*j  ][2], s[2*j  ][3]);
            a[2] = pack2h(s[2*j+1][0], s[2*j+1][1]);
            a[3] = pack2h(s[2*j+1][2], s[2*j+1][3]);
            #pragma unroll
            for (int p = 0; p < 2; p++) {
                const unsigned off = ((p*16 + krow)*36 + j*8 + kwof) << 2;
                unsigned b[4];
                ldsm4(b, aVt + off);
                mma16h(oacc[2*p],   a, b);
                mma16h(oacc[2*p+1], a, b+2);
            }
        }
        __syncthreads();
    }

    l0 += __shfl_xor_sync(0xffffffffu, l0, 1);
    l0 += __shfl_xor_sync(0xffffffffu, l0, 2);
    l1 += __shfl_xor_sync(0xffffffffu, l1, 1);
    l1 += __shfl_xor_sync(0xffffffffu, l1, 2);

    // ---- epilogue: normalize, gate, pack fp16 -> g_Oh ----
    const float inv0 = 1.f/l0, inv1 = 1.f/l1;
    const size_t gb0 = (rowbase + qrow)*CIN + h*CH;
    const size_t gb1 = gb0 + (size_t)8*CIN;
    const size_t ow0 = (rowbase + qrow)*64 + h*16;
    const size_t ow1 = ow0 + (size_t)8*64;
    #pragma unroll
    for (int nt = 0; nt < 4; nt++) {
        const int col = nt*8 + 2*tg;
        const float2 gv0 = *(const float2*)&g_G[gb0 + col];
        const float2 gv1 = *(const float2*)&g_G[gb1 + col];
        g_Oh[ow0 + (col>>1)] = pack2h(oacc[nt][0]*inv0*gv0.x, oacc[nt][1]*inv0*gv0.y);
        g_Oh[ow1 + (col>>1)] = pack2h(oacc[nt][2]*inv1*gv1.x, oacc[nt][3]*inv1*gv1.y);
    }
}

// =====================================================================
// GEMM 3: out = Oh @ wo (Oh already gated+packed fp16), m16n8k16.
// =====================================================================
__global__ void __launch_bounds__(128, 6)
outproj_mma_kernel(float* __restrict__ out)
{
    extern __shared__ unsigned sho[];
    unsigned* sA = sho;
    unsigned* sB = sA + 64*20;

    const int tid  = threadIdx.x;
    const int warp = tid >> 5, lane = tid & 31;
    const int g = lane >> 2, tg = lane & 3;
    const int wm = warp >> 1, wn = warp & 1;
    const int n0 = blockIdx.x * 64;
    const int m0 = blockIdx.y * 64;

    const unsigned aA = sm_u32(sA), aB = sm_u32(sB);
    const int arow = ((lane>>3)&1)*8 + (lane&7);
    const int awof = (lane>>4)*4;
    const int krow = ((lane>>4)&1)*8 + (lane&7);
    const int kwof = ((lane>>3)&1)*4;

    float acc[2][4][4];
    #pragma unroll
    for (int a = 0; a < 2; a++)
        #pragma unroll
        for (int b = 0; b < 4; b++)
            #pragma unroll
            for (int c = 0; c < 4; c++) acc[a][b][c] = 0.f;

    for (int kc = 0; kc < 128; kc += 32) {
        __syncthreads();
        for (int idx = tid; idx < 256; idx += 128) {
            const int r = idx >> 2, w4 = (idx & 3) << 2;
            *(uint4*)&sA[r*20 + w4] = *(const uint4*)&g_Oh[(size_t)(m0+r)*64 + (kc>>1) + w4];
            *(uint4*)&sB[r*20 + w4] = *(const uint4*)&g_WOt[(size_t)(n0+r)*64 + (kc>>1) + w4];
        }
        __syncthreads();
        #pragma unroll
        for (int ck = 0; ck < 2; ck++) {
            const int w0 = ck*8;
            unsigned ah[2][4];
            #pragma unroll
            for (int mt = 0; mt < 2; mt++)
                ldsm4(ah[mt], aA + (((wm*32 + mt*16 + arow)*20 + w0 + awof) << 2));
            #pragma unroll
            for (int p = 0; p < 2; p++) {
                unsigned b[4];
                ldsm4(b, aB + (((wn*32 + p*16 + krow)*20 + w0 + kwof) << 2));
                #pragma unroll
                for (int mt = 0; mt < 2; mt++) {
                    mma16h(acc[mt][2*p],   ah[mt], b);
                    mma16h(acc[mt][2*p+1], ah[mt], b+2);
                }
            }
        }
    }

    #pragma unroll
    for (int mt = 0; mt < 2; mt++) {
        const int r0 = m0 + wm*32 + mt*16 + g;
        #pragma unroll
        for (int nt = 0; nt < 4; nt++) {
            const int col = n0 + wn*32 + nt*8 + 2*tg;
            *(float2*)&out[(size_t)r0*CIN + col]     = make_float2(acc[mt][nt][0], acc[mt][nt][1]);
            *(float2*)&out[(size_t)(r0+8)*CIN + col] = make_float2(acc[mt][nt][2], acc[mt][nt][3]);
        }
    }
}

// =====================================================================
// launch
// =====================================================================
extern "C" void kernel_launch(void* const* d_in, const int* in_sizes, int n_in,
                              void* d_out, int out_size)
{
    (void)in_sizes; (void)n_in; (void)out_size;
    const float* z    = (const float*)d_in[0];
    const float* mask = (const float*)d_in[1];
    const float* lnw  = (const float*)d_in[2];
    const float* lnb  = (const float*)d_in[3];
    const float* wtri = (const float*)d_in[4];
    const float* wq   = (const float*)d_in[5];
    const float* wk   = (const float*)d_in[6];
    const float* wv   = (const float*)d_in[7];
    const float* wg   = (const float*)d_in[8];
    const float* wo   = (const float*)d_in[9];

    const size_t proj_sh = (size_t)PROJ_SH_W * 4;                 // 55296
    const size_t attn_sh = (size_t)(2*STG_W) * 4 + NN*4;          // 96768
    const size_t out_sh  = (size_t)(2*64*20) * 4;                 // 10240

    static int s_attr_set = 0;
    if (!s_attr_set) {
        cudaFuncSetAttribute(proj_mma_kernel,
                             cudaFuncAttributeMaxDynamicSharedMemorySize, (int)proj_sh);
        cudaFuncSetAttribute(attn_mma_kernel,
                             cudaFuncAttributeMaxDynamicSharedMemorySize, (int)attn_sh);
        s_attr_set = 1;
    }

    wsplit_kernel<<<(WCOLS*64 + CIN*64 + 255)/256, 256>>>(wq, wk, wv, wg, wtri, wo);
    ln_split_kernel<<<M_TOT/8, 256>>>(z, lnw, lnb);
    proj_mma_kernel<<<dim3(9, 2304/MPT), 128, proj_sh>>>();
    attn_mma_kernel<<<dim3(NN/128, NN, NH), 256, attn_sh>>>(mask);
    outproj_mma_kernel<<<dim3(2, M_TOT/64), 128, out_sh>>>((float*)d_out);
}